// round 1
// baseline (speedup 1.0000x reference)
#include <cuda_runtime.h>
#include <math.h>

#define S 1024
#define D 1024
#define H 16
#define HD 64
#define L 4
#define FF 4096
#define V 32000
#define EPSF 1e-5f

// ---------------- scratch (device globals; no allocations allowed) -------------
__device__ float g_h[S * D];          // residual stream
__device__ float g_hn[S * D];         // layernorm output
__device__ float g_q[S * D];
__device__ float g_k[S * D];
__device__ float g_v[S * D];
__device__ float g_att[S * D];        // attention output (pre-Wo)
__device__ float g_scores[H * S * S]; // 64 MB score/attn buffer
__device__ float g_ff[S * FF];        // FFN hidden

// ---------------- embedding + sinusoidal positional encoding -------------------
__global__ __launch_bounds__(256) void k_embed(const int* __restrict__ x,
                                               const float* __restrict__ emb,
                                               float* __restrict__ h) {
    int s = blockIdx.y;
    int d = blockIdx.x * 256 + threadIdx.x;
    int tok = x[s];
    float e = emb[(size_t)tok * D + d];
    int i2 = d & ~1;  // arange(0, D, 2) pair index * 2
    float freq = expf((float)i2 * (-9.210340371976184f / (float)D)); // -ln(10000)/D
    float ang = (float)s * freq;
    float pe = (d & 1) ? cosf(ang) : sinf(ang);
    h[(size_t)s * D + d] = e + pe;
}

// ---------------- layernorm (one block per row) ---------------------------------
__global__ __launch_bounds__(256) void k_ln(const float* __restrict__ in,
                                            float* __restrict__ out,
                                            const float* __restrict__ w,
                                            const float* __restrict__ b) {
    int row = blockIdx.x;
    const float* xr = in + (size_t)row * D;
    int t = threadIdx.x;
    __shared__ float sh1[256];
    __shared__ float sh2[256];
    float s1 = 0.f, s2 = 0.f;
    for (int d = t; d < D; d += 256) {
        float v = xr[d];
        s1 += v;
        s2 += v * v;
    }
    sh1[t] = s1; sh2[t] = s2;
    __syncthreads();
    for (int o = 128; o > 0; o >>= 1) {
        if (t < o) { sh1[t] += sh1[t + o]; sh2[t] += sh2[t + o]; }
        __syncthreads();
    }
    float mean = sh1[0] * (1.0f / D);
    float var = sh2[0] * (1.0f / D) - mean * mean;
    float rstd = rsqrtf(var + EPSF);
    float* orow = out + (size_t)row * D;
    for (int d = t; d < D; d += 256)
        orow[d] = (xr[d] - mean) * rstd * w[d] + b[d];
}

// ---------------- generic batched SGEMM -----------------------------------------
// C[b] = A[b] @ B[b] (+bias) (+res) (relu), all row-major with leading dims.
// Requires: M,N % 64 == 0, K % 16 == 0, lda/ldb/ldc and column offsets % 4 == 0.
__global__ __launch_bounds__(256) void k_sgemm(
    const float* __restrict__ A, const float* __restrict__ B,
    const float* __restrict__ bias, const float* __restrict__ res,
    float* __restrict__ C,
    int M, int N, int K, int lda, int ldb, int ldc,
    long long sA, long long sB, long long sC, int relu) {
    __shared__ float As[16][64];  // transposed: As[k][m]
    __shared__ float Bs[16][64];  // Bs[k][n]

    const float* Ab = A + (long long)blockIdx.z * sA;
    const float* Bb = B + (long long)blockIdx.z * sB;
    float* Cb = C + (long long)blockIdx.z * sC;
    const float* Rb = res ? (res + (long long)blockIdx.z * sC) : nullptr;

    int tid = threadIdx.x;
    int bm = blockIdx.y * 64, bn = blockIdx.x * 64;
    int ar = tid >> 2, ac = (tid & 3) * 4;     // A tile: 64 rows x 4 float4
    int br = tid >> 4, bc = (tid & 15) * 4;    // B tile: 16 rows x 16 float4
    int tx = tid & 15, ty = tid >> 4;

    float acc[4][4] = {};
    for (int k0 = 0; k0 < K; k0 += 16) {
        float4 av = *(const float4*)(Ab + (size_t)(bm + ar) * lda + k0 + ac);
        float4 bv = *(const float4*)(Bb + (size_t)(k0 + br) * ldb + bn + bc);
        As[ac + 0][ar] = av.x;
        As[ac + 1][ar] = av.y;
        As[ac + 2][ar] = av.z;
        As[ac + 3][ar] = av.w;
        *(float4*)&Bs[br][bc] = bv;
        __syncthreads();
#pragma unroll
        for (int kk = 0; kk < 16; kk++) {
            float a[4], bb[4];
#pragma unroll
            for (int i = 0; i < 4; i++) a[i] = As[kk][ty * 4 + i];
#pragma unroll
            for (int j = 0; j < 4; j++) bb[j] = Bs[kk][tx * 4 + j];
#pragma unroll
            for (int i = 0; i < 4; i++)
#pragma unroll
                for (int j = 0; j < 4; j++) acc[i][j] += a[i] * bb[j];
        }
        __syncthreads();
    }
#pragma unroll
    for (int i = 0; i < 4; i++) {
        int m = bm + ty * 4 + i;
#pragma unroll
        for (int j = 0; j < 4; j++) {
            int n = bn + tx * 4 + j;
            float v = acc[i][j];
            if (bias) v += bias[n];
            if (Rb) v += Rb[(size_t)m * ldc + n];
            if (relu) v = fmaxf(v, 0.f);
            Cb[(size_t)m * ldc + n] = v;
        }
    }
}

// ---------------- causal attention scores: q . k^T / sqrt(HD) -------------------
// grid: (kb, qb, head). Blocks with kb>qb are skipped (softmax never reads them).
__global__ __launch_bounds__(256) void k_scores(const float* __restrict__ q,
                                                const float* __restrict__ k,
                                                float* __restrict__ scores) {
    int kb = blockIdx.x, qb = blockIdx.y, hh = blockIdx.z;
    if (kb > qb) return;
    __shared__ float Qs[64][65];  // Qs[feat][query]
    __shared__ float Ks[64][65];  // Ks[feat][key]
    int tid = threadIdx.x;
    int tx = tid & 15, ty = tid >> 4;

    // load 64x64 tiles (transposed into smem)
#pragma unroll
    for (int i = 0; i < 4; i++) {
        int r = i * 16 + (tid >> 4);
        int c = (tid & 15) * 4;
        float4 qv = *(const float4*)(q + (size_t)(qb * 64 + r) * D + hh * HD + c);
        float4 kv = *(const float4*)(k + (size_t)(kb * 64 + r) * D + hh * HD + c);
        Qs[c + 0][r] = qv.x; Qs[c + 1][r] = qv.y; Qs[c + 2][r] = qv.z; Qs[c + 3][r] = qv.w;
        Ks[c + 0][r] = kv.x; Ks[c + 1][r] = kv.y; Ks[c + 2][r] = kv.z; Ks[c + 3][r] = kv.w;
    }
    __syncthreads();

    float acc[4][4] = {};
#pragma unroll
    for (int kk = 0; kk < 64; kk++) {
        float a[4], b[4];
#pragma unroll
        for (int i = 0; i < 4; i++) a[i] = Qs[kk][ty * 4 + i];
#pragma unroll
        for (int j = 0; j < 4; j++) b[j] = Ks[kk][tx * 4 + j];
#pragma unroll
        for (int i = 0; i < 4; i++)
#pragma unroll
            for (int j = 0; j < 4; j++) acc[i][j] += a[i] * b[j];
    }
    const float scale = 0.125f;  // 1/sqrt(64)
#pragma unroll
    for (int i = 0; i < 4; i++) {
        int qg = qb * 64 + ty * 4 + i;
#pragma unroll
        for (int j = 0; j < 4; j++) {
            int kg = kb * 64 + tx * 4 + j;
            scores[((size_t)hh * S + qg) * S + kg] = acc[i][j] * scale;
        }
    }
}

// ---------------- causal softmax in place; zero-fills k>q -----------------------
__global__ __launch_bounds__(256) void k_softmax(float* __restrict__ scores) {
    int row = blockIdx.x;          // h*S + q
    int q = row & (S - 1);
    float* sr = scores + (size_t)row * S;
    int n = q + 1;
    int t = threadIdx.x;
    __shared__ float sh[256];

    float m = -1e30f;
    for (int kk = t; kk < n; kk += 256) m = fmaxf(m, sr[kk]);
    sh[t] = m;
    __syncthreads();
    for (int o = 128; o > 0; o >>= 1) {
        if (t < o) sh[t] = fmaxf(sh[t], sh[t + o]);
        __syncthreads();
    }
    m = sh[0];
    __syncthreads();

    float s = 0.f;
    for (int kk = t; kk < n; kk += 256) {
        float e = expf(sr[kk] - m);
        sr[kk] = e;
        s += e;
    }
    sh[t] = s;
    __syncthreads();
    for (int o = 128; o > 0; o >>= 1) {
        if (t < o) sh[t] += sh[t + o];
        __syncthreads();
    }
    float inv = 1.0f / sh[0];
    for (int kk = t; kk < S; kk += 256)
        sr[kk] = (kk < n) ? sr[kk] * inv : 0.f;
}

// ---------------- launch orchestration ------------------------------------------
extern "C" void kernel_launch(void* const* d_in, const int* in_sizes, int n_in,
                              void* d_out, int out_size) {
    (void)in_sizes; (void)n_in; (void)out_size;
    const int*   x      = (const int*)d_in[0];
    const float* emb    = (const float*)d_in[1];
    const float* Wq     = (const float*)d_in[2];
    const float* Wk     = (const float*)d_in[3];
    const float* Wv     = (const float*)d_in[4];
    const float* Wo     = (const float*)d_in[5];
    const float* bo     = (const float*)d_in[6];
    const float* ln1_w  = (const float*)d_in[7];
    const float* ln1_b  = (const float*)d_in[8];
    const float* W1     = (const float*)d_in[9];
    const float* b1     = (const float*)d_in[10];
    const float* W2     = (const float*)d_in[11];
    const float* b2     = (const float*)d_in[12];
    const float* ln2_w  = (const float*)d_in[13];
    const float* ln2_b  = (const float*)d_in[14];
    const float* fn_w   = (const float*)d_in[15];
    const float* fn_b   = (const float*)d_in[16];
    const float* lmhead = (const float*)d_in[17];
    float* out = (float*)d_out;

    static float *ph = nullptr, *phn, *pq, *pk, *pv, *pa, *ps, *pf;
    if (!ph) {
        cudaGetSymbolAddress((void**)&ph,  g_h);
        cudaGetSymbolAddress((void**)&phn, g_hn);
        cudaGetSymbolAddress((void**)&pq,  g_q);
        cudaGetSymbolAddress((void**)&pk,  g_k);
        cudaGetSymbolAddress((void**)&pv,  g_v);
        cudaGetSymbolAddress((void**)&pa,  g_att);
        cudaGetSymbolAddress((void**)&ps,  g_scores);
        cudaGetSymbolAddress((void**)&pf,  g_ff);
    }

    // embedding + positional encoding
    k_embed<<<dim3(D / 256, S), 256>>>(x, emb, ph);

    dim3 gDD(D / 64, S / 64);        // [S,D] x [D,D]
    dim3 gFF1(FF / 64, S / 64);      // [S,D] x [D,FF]
    dim3 gFF2(D / 64, S / 64);       // [S,FF] x [FF,D]
    dim3 gAV(HD / 64, S / 64, H);    // per-head [S,S] x [S,64]
    dim3 gSc(S / 64, S / 64, H);
    dim3 gLM(V / 64, S / 64);

    for (int i = 0; i < L; i++) {
        size_t wo = (size_t)i * D * D;
        // --- attention block ---
        k_ln<<<S, 256>>>(ph, phn, ln1_w + (size_t)i * D, ln1_b + (size_t)i * D);
        k_sgemm<<<gDD, 256>>>(phn, Wq + wo, nullptr, nullptr, pq,
                              S, D, D, D, D, D, 0, 0, 0, 0);
        k_sgemm<<<gDD, 256>>>(phn, Wk + wo, nullptr, nullptr, pk,
                              S, D, D, D, D, D, 0, 0, 0, 0);
        k_sgemm<<<gDD, 256>>>(phn, Wv + wo, nullptr, nullptr, pv,
                              S, D, D, D, D, D, 0, 0, 0, 0);
        k_scores<<<gSc, 256>>>(pq, pk, ps);
        k_softmax<<<H * S, 256>>>(ps);
        // AV: batched over heads. A=attn[h] (lda=S, stride S*S); B=v[:,h*64:] (ldb=D, stride 64)
        k_sgemm<<<gAV, 256>>>(ps, pv, nullptr, nullptr, pa,
                              S, HD, S, S, D, D,
                              (long long)S * S, HD, HD, 0);
        // h = att @ Wo + bo + h (in-place residual)
        k_sgemm<<<gDD, 256>>>(pa, Wo + wo, bo + (size_t)i * D, ph, ph,
                              S, D, D, D, D, D, 0, 0, 0, 0);
        // --- FFN block ---
        k_ln<<<S, 256>>>(ph, phn, ln2_w + (size_t)i * D, ln2_b + (size_t)i * D);
        k_sgemm<<<gFF1, 256>>>(phn, W1 + (size_t)i * D * FF, b1 + (size_t)i * FF,
                               nullptr, pf, S, FF, D, D, FF, FF, 0, 0, 0, 1);
        k_sgemm<<<gFF2, 256>>>(pf, W2 + (size_t)i * FF * D, b2 + (size_t)i * D,
                               ph, ph, S, D, FF, FF, D, D, 0, 0, 0, 0);
    }

    // final layernorm + LM head
    k_ln<<<S, 256>>>(ph, phn, fn_w, fn_b);
    k_sgemm<<<gLM, 256>>>(phn, lmhead, nullptr, nullptr, out,
                          S, V, D, D, V, V, 0, 0, 0, 0);
}

// round 3
// speedup vs baseline: 2.0646x; 2.0646x over previous
#include <cuda_runtime.h>
#include <cuda_bf16.h>
#include <math.h>
#include <stdint.h>

#define S 1024
#define D 1024
#define H 16
#define HD 64
#define L 4
#define FF 4096
#define V 32000
#define EPSF 1e-5f

// ---------------------------------------------------------------------------
// device scratch (no allocations allowed)
// ---------------------------------------------------------------------------
__device__ __align__(16) float g_h[S * D];
__device__ __align__(16) float g_hn[S * D];
__device__ __align__(16) float g_qkv[S * 3 * D];
__device__ __align__(16) float g_att[S * D];
__device__ __align__(16) float g_ff[S * FF];
__device__ __align__(16) float g_scores[H * S * S];

__device__ __align__(16) __nv_bfloat16 g_act_h[S * FF];
__device__ __align__(16) __nv_bfloat16 g_act_l[S * FF];

__device__ __align__(16) __nv_bfloat16 g_qkvT_h[(size_t)L * 3 * D * D];
__device__ __align__(16) __nv_bfloat16 g_qkvT_l[(size_t)L * 3 * D * D];
__device__ __align__(16) __nv_bfloat16 g_woT_h[(size_t)L * D * D];
__device__ __align__(16) __nv_bfloat16 g_woT_l[(size_t)L * D * D];
__device__ __align__(16) __nv_bfloat16 g_w1T_h[(size_t)L * FF * D];
__device__ __align__(16) __nv_bfloat16 g_w1T_l[(size_t)L * FF * D];
__device__ __align__(16) __nv_bfloat16 g_w2T_h[(size_t)L * D * FF];
__device__ __align__(16) __nv_bfloat16 g_w2T_l[(size_t)L * D * FF];
__device__ __align__(16) __nv_bfloat16 g_lmT_h[(size_t)V * D];
__device__ __align__(16) __nv_bfloat16 g_lmT_l[(size_t)V * D];

// ---------------------------------------------------------------------------
// PTX helpers (base sm_103-safe: mma.sync / ldmatrix / cp.async only)
// ---------------------------------------------------------------------------
__device__ __forceinline__ uint32_t smem_u32(const void* p) {
    uint32_t a;
    asm("{ .reg .u64 t; cvta.to.shared.u64 t, %1; cvt.u32.u64 %0, t; }" : "=r"(a) : "l"(p));
    return a;
}
#define CP16(dst, src) \
    asm volatile("cp.async.cg.shared.global [%0], [%1], 16;" :: "r"(dst), "l"(src))
#define CP_COMMIT() asm volatile("cp.async.commit_group;" ::: "memory")
#define CP_WAIT(n)  asm volatile("cp.async.wait_group %0;" :: "n"(n) : "memory")

__device__ __forceinline__ void ldsm4(uint32_t* r, uint32_t addr) {
    asm volatile("ldmatrix.sync.aligned.m8n8.x4.shared.b16 {%0,%1,%2,%3}, [%4];"
                 : "=r"(r[0]), "=r"(r[1]), "=r"(r[2]), "=r"(r[3]) : "r"(addr));
}
__device__ __forceinline__ void mma_bf16(float* d, const uint32_t* a, const uint32_t* b) {
    asm volatile(
        "mma.sync.aligned.m16n8k16.row.col.f32.bf16.bf16.f32 "
        "{%0,%1,%2,%3}, {%4,%5,%6,%7}, {%8,%9}, {%0,%1,%2,%3};"
        : "+f"(d[0]), "+f"(d[1]), "+f"(d[2]), "+f"(d[3])
        : "r"(a[0]), "r"(a[1]), "r"(a[2]), "r"(a[3]), "r"(b[0]), "r"(b[1]));
}

// ---------------------------------------------------------------------------
// HMMA bf16 3-pass GEMM: C[M,N] = A[M,K] @ B^T   (A [M,K], B [N,K], hi/lo pairs)
// grid (N/128, M/128), 256 threads, 64 KB dynamic smem, K % 32 == 0.
// ---------------------------------------------------------------------------
#define MG_SMEM (2 * 32768)

__device__ __forceinline__ void tile_load(uint32_t sdst,
                                          const __nv_bfloat16* gh,
                                          const __nv_bfloat16* gl,
                                          int ld, int k0, int tid) {
#pragma unroll
    for (int i = 0; i < 4; i++) {
        int cid = i * 256 + tid;        // 0..1023 : 128 rows * 8 chunks
        int row = cid >> 3, sub = cid & 7;
        const __nv_bfloat16* src =
            ((sub & 4) ? gl : gh) + (size_t)row * ld + k0 + (sub & 3) * 8;
        uint32_t dst = sdst + row * 128 + ((sub ^ (row & 7)) << 4);
        CP16(dst, src);
    }
}

__global__ __launch_bounds__(256, 1)
void k_mma_gemm(const __nv_bfloat16* __restrict__ Ah, const __nv_bfloat16* __restrict__ Al,
                const __nv_bfloat16* __restrict__ Bh, const __nv_bfloat16* __restrict__ Bl,
                const float* __restrict__ bias, const float* __restrict__ res,
                float* __restrict__ C, int K, int ldc, int relu) {
    extern __shared__ char smem[];
    const int tid = threadIdx.x;
    const int wid = tid >> 5, lane = tid & 31;
    const int bm = blockIdx.y * 128, bn = blockIdx.x * 128;
    const int wm = (wid >> 2) * 64, wn = (wid & 3) * 32;
    uint32_t sbase = smem_u32(smem);

    const __nv_bfloat16* ah_g = Ah + (size_t)bm * K;
    const __nv_bfloat16* al_g = Al + (size_t)bm * K;
    const __nv_bfloat16* bh_g = Bh + (size_t)bn * K;
    const __nv_bfloat16* bl_g = Bl + (size_t)bn * K;

    float acc[4][4][4] = {};

    const int nt = K >> 5;
    // prologue: stage tile 0
    tile_load(sbase,         ah_g, al_g, K, 0, tid);
    tile_load(sbase + 16384, bh_g, bl_g, K, 0, tid);
    CP_COMMIT();

    for (int t = 0; t < nt; t++) {
        int b = t & 1;
        if (t + 1 < nt) {
            uint32_t nb = sbase + ((t + 1) & 1) * 32768;
            tile_load(nb,         ah_g, al_g, K, (t + 1) << 5, tid);
            tile_load(nb + 16384, bh_g, bl_g, K, (t + 1) << 5, tid);
            CP_COMMIT();
            CP_WAIT(1);
        } else {
            CP_WAIT(0);
        }
        __syncthreads();

        uint32_t sA = sbase + b * 32768;
        uint32_t sB = sA + 16384;
#pragma unroll
        for (int ks = 0; ks < 2; ks++) {
            uint32_t ahf[4][4], alf[4][4], bhf[2][4], blf[2][4];
#pragma unroll
            for (int f = 0; f < 4; f++) {
                int row = wm + f * 16 + (lane & 15);
                int jc = (lane >> 4) + ks * 2;
                ldsm4(ahf[f], sA + row * 128 + ((jc ^ (row & 7)) << 4));
                ldsm4(alf[f], sA + row * 128 + (((jc + 4) ^ (row & 7)) << 4));
            }
#pragma unroll
            for (int np = 0; np < 2; np++) {
                int row = wn + np * 16 + ((lane >> 4) << 3) + (lane & 7);
                int jc = ((lane >> 3) & 1) + ks * 2;
                ldsm4(bhf[np], sB + row * 128 + ((jc ^ (row & 7)) << 4));
                ldsm4(blf[np], sB + row * 128 + (((jc + 4) ^ (row & 7)) << 4));
            }
#pragma unroll
            for (int m = 0; m < 4; m++)
#pragma unroll
                for (int nf = 0; nf < 4; nf++) {
                    uint32_t* bhp = &bhf[nf >> 1][(nf & 1) * 2];
                    uint32_t* blp = &blf[nf >> 1][(nf & 1) * 2];
                    mma_bf16(acc[m][nf], ahf[m], bhp);
                    mma_bf16(acc[m][nf], ahf[m], blp);
                    mma_bf16(acc[m][nf], alf[m], bhp);
                }
        }
        __syncthreads();
    }

    // epilogue
#pragma unroll
    for (int m = 0; m < 4; m++) {
        int r0 = bm + wm + m * 16 + (lane >> 2);
#pragma unroll
        for (int nf = 0; nf < 4; nf++) {
            int col = bn + wn + nf * 8 + ((lane & 3) << 1);
            float v0 = acc[m][nf][0], v1 = acc[m][nf][1];
            float v2 = acc[m][nf][2], v3 = acc[m][nf][3];
            if (bias) {
                float b0 = bias[col], b1 = bias[col + 1];
                v0 += b0; v1 += b1; v2 += b0; v3 += b1;
            }
            if (res) {
                const float* rr0 = res + (size_t)r0 * ldc + col;
                const float* rr1 = res + (size_t)(r0 + 8) * ldc + col;
                v0 += rr0[0]; v1 += rr0[1]; v2 += rr1[0]; v3 += rr1[1];
            }
            if (relu) {
                v0 = fmaxf(v0, 0.f); v1 = fmaxf(v1, 0.f);
                v2 = fmaxf(v2, 0.f); v3 = fmaxf(v3, 0.f);
            }
            *(float2*)(C + (size_t)r0 * ldc + col) = make_float2(v0, v1);
            *(float2*)(C + (size_t)(r0 + 8) * ldc + col) = make_float2(v2, v3);
        }
    }
}

// ---------------------------------------------------------------------------
// fp32 -> bf16 hi/lo split (flat)
// ---------------------------------------------------------------------------
__global__ __launch_bounds__(256) void k_split(const float* __restrict__ x,
                                               __nv_bfloat16* __restrict__ hi,
                                               __nv_bfloat16* __restrict__ lo, int n) {
    int i = blockIdx.x * 256 + threadIdx.x;
    if (i < n) {
        float v = x[i];
        __nv_bfloat16 h = __float2bfloat16(v);
        float r = v - __bfloat162float(h);
        hi[i] = h;
        lo[i] = __float2bfloat16(r);
    }
}

// W [K,N] row-major -> out [N,K] bf16 hi/lo (transpose + split)
__global__ __launch_bounds__(256) void k_splitT(const float* __restrict__ W,
                                                __nv_bfloat16* __restrict__ th,
                                                __nv_bfloat16* __restrict__ tl,
                                                int N, int ldt) {
    __shared__ float t[32][33];
    int k0 = blockIdx.y * 32, n0 = blockIdx.x * 32;
    int tx = threadIdx.x & 31, ty = threadIdx.x >> 5;
#pragma unroll
    for (int i = 0; i < 4; i++) {
        int r = ty + i * 8;
        t[r][tx] = W[(size_t)(k0 + r) * N + n0 + tx];
    }
    __syncthreads();
#pragma unroll
    for (int i = 0; i < 4; i++) {
        int r = ty + i * 8;
        float v = t[tx][r];
        __nv_bfloat16 h = __float2bfloat16(v);
        float rr = v - __bfloat162float(h);
        size_t o = (size_t)(n0 + r) * ldt + k0 + tx;
        th[o] = h;
        tl[o] = __float2bfloat16(rr);
    }
}

// ---------------------------------------------------------------------------
// embedding + sinusoidal positional encoding
// ---------------------------------------------------------------------------
__global__ __launch_bounds__(256) void k_embed(const int* __restrict__ x,
                                               const float* __restrict__ emb,
                                               float* __restrict__ h) {
    int s = blockIdx.y;
    int d = blockIdx.x * 256 + threadIdx.x;
    int tok = x[s];
    float e = emb[(size_t)tok * D + d];
    int i2 = d & ~1;
    float freq = expf((float)i2 * (-9.210340371976184f / (float)D));
    float ang = (float)s * freq;
    float pe = (d & 1) ? cosf(ang) : sinf(ang);
    h[(size_t)s * D + d] = e + pe;
}

// ---------------------------------------------------------------------------
// layernorm
// ---------------------------------------------------------------------------
__global__ __launch_bounds__(256) void k_ln(const float* __restrict__ in,
                                            float* __restrict__ out,
                                            const float* __restrict__ w,
                                            const float* __restrict__ b) {
    int row = blockIdx.x;
    const float* xr = in + (size_t)row * D;
    int t = threadIdx.x;
    __shared__ float sh1[256];
    __shared__ float sh2[256];
    float s1 = 0.f, s2 = 0.f;
    for (int d = t; d < D; d += 256) {
        float v = xr[d];
        s1 += v; s2 += v * v;
    }
    sh1[t] = s1; sh2[t] = s2;
    __syncthreads();
    for (int o = 128; o > 0; o >>= 1) {
        if (t < o) { sh1[t] += sh1[t + o]; sh2[t] += sh2[t + o]; }
        __syncthreads();
    }
    float mean = sh1[0] * (1.0f / D);
    float var = sh2[0] * (1.0f / D) - mean * mean;
    float rstd = rsqrtf(var + EPSF);
    float* orow = out + (size_t)row * D;
    for (int d = t; d < D; d += 256)
        orow[d] = (xr[d] - mean) * rstd * w[d] + b[d];
}

// ---------------------------------------------------------------------------
// fp32 batched SGEMM (AV)
// ---------------------------------------------------------------------------
__global__ __launch_bounds__(256) void k_sgemm(
    const float* __restrict__ A, const float* __restrict__ B,
    float* __restrict__ C,
    int M, int N, int K, int lda, int ldb, int ldc,
    long long sA, long long sB, long long sC) {
    __shared__ float As[16][64];
    __shared__ float Bs[16][64];

    const float* Ab = A + (long long)blockIdx.z * sA;
    const float* Bb = B + (long long)blockIdx.z * sB;
    float* Cb = C + (long long)blockIdx.z * sC;

    int tid = threadIdx.x;
    int bm = blockIdx.y * 64, bn = blockIdx.x * 64;
    int ar = tid >> 2, ac = (tid & 3) * 4;
    int br = tid >> 4, bc = (tid & 15) * 4;
    int tx = tid & 15, ty = tid >> 4;

    float acc[4][4] = {};
    for (int k0 = 0; k0 < K; k0 += 16) {
        float4 av = *(const float4*)(Ab + (size_t)(bm + ar) * lda + k0 + ac);
        float4 bv = *(const float4*)(Bb + (size_t)(k0 + br) * ldb + bn + bc);
        As[ac + 0][ar] = av.x; As[ac + 1][ar] = av.y;
        As[ac + 2][ar] = av.z; As[ac + 3][ar] = av.w;
        *(float4*)&Bs[br][bc] = bv;
        __syncthreads();
#pragma unroll
        for (int kk = 0; kk < 16; kk++) {
            float a[4], bb[4];
#pragma unroll
            for (int i = 0; i < 4; i++) a[i] = As[kk][ty * 4 + i];
#pragma unroll
            for (int j = 0; j < 4; j++) bb[j] = Bs[kk][tx * 4 + j];
#pragma unroll
            for (int i = 0; i < 4; i++)
#pragma unroll
                for (int j = 0; j < 4; j++) acc[i][j] += a[i] * bb[j];
        }
        __syncthreads();
    }
#pragma unroll
    for (int i = 0; i < 4; i++) {
        int m = bm + ty * 4 + i;
#pragma unroll
        for (int j = 0; j < 4; j++) {
            int n = bn + tx * 4 + j;
            Cb[(size_t)m * ldc + n] = acc[i][j];
        }
    }
}

// ---------------------------------------------------------------------------
// attention scores (fp32) over fused qkv buffer
// ---------------------------------------------------------------------------
__global__ __launch_bounds__(256) void k_scores(const float* __restrict__ qkv,
                                                float* __restrict__ scores) {
    int kb = blockIdx.x, qb = blockIdx.y, hh = blockIdx.z;
    if (kb > qb) return;
    __shared__ float Qs[64][65];
    __shared__ float Ks[64][65];
    int tid = threadIdx.x;
    int tx = tid & 15, ty = tid >> 4;

#pragma unroll
    for (int i = 0; i < 4; i++) {
        int r = i * 16 + (tid >> 4);
        int c = (tid & 15) * 4;
        float4 qv = *(const float4*)(qkv + (size_t)(qb * 64 + r) * (3 * D) + hh * HD + c);
        float4 kv = *(const float4*)(qkv + (size_t)(kb * 64 + r) * (3 * D) + D + hh * HD + c);
        Qs[c + 0][r] = qv.x; Qs[c + 1][r] = qv.y; Qs[c + 2][r] = qv.z; Qs[c + 3][r] = qv.w;
        Ks[c + 0][r] = kv.x; Ks[c + 1][r] = kv.y; Ks[c + 2][r] = kv.z; Ks[c + 3][r] = kv.w;
    }
    __syncthreads();

    float acc[4][4] = {};
#pragma unroll
    for (int kk = 0; kk < 64; kk++) {
        float a[4], b[4];
#pragma unroll
        for (int i = 0; i < 4; i++) a[i] = Qs[kk][ty * 4 + i];
#pragma unroll
        for (int j = 0; j < 4; j++) b[j] = Ks[kk][tx * 4 + j];
#pragma unroll
        for (int i = 0; i < 4; i++)
#pragma unroll
            for (int j = 0; j < 4; j++) acc[i][j] += a[i] * b[j];
    }
    const float scale = 0.125f;
#pragma unroll
    for (int i = 0; i < 4; i++) {
        int qg = qb * 64 + ty * 4 + i;
#pragma unroll
        for (int j = 0; j < 4; j++) {
            int kg = kb * 64 + tx * 4 + j;
            scores[((size_t)hh * S + qg) * S + kg] = acc[i][j] * scale;
        }
    }
}

// ---------------------------------------------------------------------------
// causal softmax, zero-fills k>q
// ---------------------------------------------------------------------------
__global__ __launch_bounds__(256) void k_softmax(float* __restrict__ scores) {
    int row = blockIdx.x;
    int q = row & (S - 1);
    float* sr = scores + (size_t)row * S;
    int n = q + 1;
    int t = threadIdx.x;
    __shared__ float sh[256];

    float m = -1e30f;
    for (int kk = t; kk < n; kk += 256) m = fmaxf(m, sr[kk]);
    sh[t] = m;
    __syncthreads();
    for (int o = 128; o > 0; o >>= 1) {
        if (t < o) sh[t] = fmaxf(sh[t], sh[t + o]);
        __syncthreads();
    }
    m = sh[0];
    __syncthreads();

    float s = 0.f;
    for (int kk = t; kk < n; kk += 256) {
        float e = expf(sr[kk] - m);
        sr[kk] = e;
        s += e;
    }
    sh[t] = s;
    __syncthreads();
    for (int o = 128; o > 0; o >>= 1) {
        if (t < o) sh[t] += sh[t + o];
        __syncthreads();
    }
    float inv = 1.0f / sh[0];
    for (int kk = t; kk < S; kk += 256)
        sr[kk] = (kk < n) ? sr[kk] * inv : 0.f;
}

// ---------------------------------------------------------------------------
// launch orchestration
// ---------------------------------------------------------------------------
extern "C" void kernel_launch(void* const* d_in, const int* in_sizes, int n_in,
                              void* d_out, int out_size) {
    (void)in_sizes; (void)n_in; (void)out_size;
    const int*   x      = (const int*)d_in[0];
    const float* emb    = (const float*)d_in[1];
    const float* Wq     = (const float*)d_in[2];
    const float* Wk     = (const float*)d_in[3];
    const float* Wv     = (const float*)d_in[4];
    const float* Wo     = (const float*)d_in[5];
    const float* bo     = (const float*)d_in[6];
    const float* ln1_w  = (const float*)d_in[7];
    const float* ln1_b  = (const float*)d_in[8];
    const float* W1     = (const float*)d_in[9];
    const float* b1     = (const float*)d_in[10];
    const float* W2     = (const float*)d_in[11];
    const float* b2     = (const float*)d_in[12];
    const float* ln2_w  = (const float*)d_in[13];
    const float* ln2_b  = (const float*)d_in[14];
    const float* fn_w   = (const float*)d_in[15];
    const float* fn_b   = (const float*)d_in[16];
    const float* lmhead = (const float*)d_in[17];
    float* out = (float*)d_out;

    static float *ph = nullptr, *phn, *pqkv, *pa, *pf, *ps;
    static __nv_bfloat16 *ah, *al, *qkvTh, *qkvTl, *woTh, *woTl,
                         *w1Th, *w1Tl, *w2Th, *w2Tl, *lmTh, *lmTl;
    if (!ph) {
        cudaGetSymbolAddress((void**)&ph,    g_h);
        cudaGetSymbolAddress((void**)&phn,   g_hn);
        cudaGetSymbolAddress((void**)&pqkv,  g_qkv);
        cudaGetSymbolAddress((void**)&pa,    g_att);
        cudaGetSymbolAddress((void**)&pf,    g_ff);
        cudaGetSymbolAddress((void**)&ps,    g_scores);
        cudaGetSymbolAddress((void**)&ah,    g_act_h);
        cudaGetSymbolAddress((void**)&al,    g_act_l);
        cudaGetSymbolAddress((void**)&qkvTh, g_qkvT_h);
        cudaGetSymbolAddress((void**)&qkvTl, g_qkvT_l);
        cudaGetSymbolAddress((void**)&woTh,  g_woT_h);
        cudaGetSymbolAddress((void**)&woTl,  g_woT_l);
        cudaGetSymbolAddress((void**)&w1Th,  g_w1T_h);
        cudaGetSymbolAddress((void**)&w1Tl,  g_w1T_l);
        cudaGetSymbolAddress((void**)&w2Th,  g_w2T_h);
        cudaGetSymbolAddress((void**)&w2Tl,  g_w2T_l);
        cudaGetSymbolAddress((void**)&lmTh,  g_lmT_h);
        cudaGetSymbolAddress((void**)&lmTl,  g_lmT_l);
        cudaFuncSetAttribute(k_mma_gemm, cudaFuncAttributeMaxDynamicSharedMemorySize, MG_SMEM);
    }

    // embedding
    k_embed<<<dim3(D / 256, S), 256>>>(x, emb, ph);

    // weight transpose + split (per launch; weights are inputs)
    dim3 gTDD(D / 32, D / 32);
    for (int l = 0; l < L; l++) {
        size_t wo = (size_t)l * D * D;
        size_t qo = (size_t)l * 3 * D * D;
        k_splitT<<<gTDD, 256>>>(Wq + wo, qkvTh + qo,             qkvTl + qo,             D, D);
        k_splitT<<<gTDD, 256>>>(Wk + wo, qkvTh + qo + D * D,     qkvTl + qo + D * D,     D, D);
        k_splitT<<<gTDD, 256>>>(Wv + wo, qkvTh + qo + 2 * D * D, qkvTl + qo + 2 * D * D, D, D);
        k_splitT<<<gTDD, 256>>>(Wo + wo, woTh + wo, woTl + wo, D, D);
        k_splitT<<<dim3(FF / 32, D / 32), 256>>>(W1 + (size_t)l * D * FF,
                                                 w1Th + (size_t)l * FF * D,
                                                 w1Tl + (size_t)l * FF * D, FF, D);
        k_splitT<<<dim3(D / 32, FF / 32), 256>>>(W2 + (size_t)l * FF * D,
                                                 w2Th + (size_t)l * D * FF,
                                                 w2Tl + (size_t)l * D * FF, D, FF);
    }
    k_splitT<<<dim3(V / 32, D / 32), 256>>>(lmhead, lmTh, lmTl, V, D);

    dim3 gSc(S / 64, S / 64, H);
    dim3 gAV(1, S / 64, H);

    for (int l = 0; l < L; l++) {
        size_t wo = (size_t)l * D * D;
        size_t qo = (size_t)l * 3 * D * D;
        // --- attention ---
        k_ln<<<S, 256>>>(ph, phn, ln1_w + (size_t)l * D, ln1_b + (size_t)l * D);
        k_split<<<(S * D + 255) / 256, 256>>>(phn, ah, al, S * D);
        k_mma_gemm<<<dim3(3 * D / 128, S / 128), 256, MG_SMEM>>>(
            ah, al, qkvTh + qo, qkvTl + qo, nullptr, nullptr, pqkv, D, 3 * D, 0);
        k_scores<<<gSc, 256>>>(pqkv, ps);
        k_softmax<<<H * S, 256>>>(ps);
        k_sgemm<<<gAV, 256>>>(ps, pqkv + 2 * D, pa,
                              S, HD, S, S, 3 * D, D,
                              (long long)S * S, HD, HD);
        k_split<<<(S * D + 255) / 256, 256>>>(pa, ah, al, S * D);
        k_mma_gemm<<<dim3(D / 128, S / 128), 256, MG_SMEM>>>(
            ah, al, woTh + wo, woTl + wo, bo + (size_t)l * D, ph, ph, D, D, 0);
        // --- FFN ---
        k_ln<<<S, 256>>>(ph, phn, ln2_w + (size_t)l * D, ln2_b + (size_t)l * D);
        k_split<<<(S * D + 255) / 256, 256>>>(phn, ah, al, S * D);
        k_mma_gemm<<<dim3(FF / 128, S / 128), 256, MG_SMEM>>>(
            ah, al, w1Th + (size_t)l * FF * D, w1Tl + (size_t)l * FF * D,
            b1 + (size_t)l * FF, nullptr, pf, D, FF, 1);
        k_split<<<(S * FF + 255) / 256, 256>>>(pf, ah, al, S * FF);
        k_mma_gemm<<<dim3(D / 128, S / 128), 256, MG_SMEM>>>(
            ah, al, w2Th + (size_t)l * D * FF, w2Tl + (size_t)l * D * FF,
            b2 + (size_t)l * D, ph, ph, FF, D, 0);
    }

    // final LN + LM head
    k_ln<<<S, 256>>>(ph, phn, fn_w, fn_b);
    k_split<<<(S * D + 255) / 256, 256>>>(phn, ah, al, S * D);
    k_mma_gemm<<<dim3(V / 128, S / 128), 256, MG_SMEM>>>(
        ah, al, lmTh, lmTl, nullptr, nullptr, out, D, V, 0);
}

// round 4
// speedup vs baseline: 2.6188x; 1.2684x over previous
#include <cuda_runtime.h>
#include <cuda_bf16.h>
#include <math.h>
#include <stdint.h>

#define S 1024
#define D 1024
#define H 16
#define HD 64
#define L 4
#define FF 4096
#define V 32000
#define EPSF 1e-5f

// ---------------------------------------------------------------------------
// device scratch
// ---------------------------------------------------------------------------
__device__ __align__(16) float g_h[S * D];

__device__ __align__(16) __nv_bfloat16 g_act_h[S * FF];
__device__ __align__(16) __nv_bfloat16 g_act_l[S * FF];
__device__ __align__(16) __nv_bfloat16 g_ff_h[S * FF];
__device__ __align__(16) __nv_bfloat16 g_ff_l[S * FF];
__device__ __align__(16) __nv_bfloat16 g_qh[S * D];
__device__ __align__(16) __nv_bfloat16 g_ql[S * D];
__device__ __align__(16) __nv_bfloat16 g_kh[S * D];
__device__ __align__(16) __nv_bfloat16 g_kl[S * D];
__device__ __align__(16) __nv_bfloat16 g_vth[D * S];
__device__ __align__(16) __nv_bfloat16 g_vtl[D * S];

__device__ __align__(16) __nv_bfloat16 g_qkvT_h[(size_t)L * 3 * D * D];
__device__ __align__(16) __nv_bfloat16 g_qkvT_l[(size_t)L * 3 * D * D];
__device__ __align__(16) __nv_bfloat16 g_woT_h[(size_t)L * D * D];
__device__ __align__(16) __nv_bfloat16 g_woT_l[(size_t)L * D * D];
__device__ __align__(16) __nv_bfloat16 g_w1T_h[(size_t)L * FF * D];
__device__ __align__(16) __nv_bfloat16 g_w1T_l[(size_t)L * FF * D];
__device__ __align__(16) __nv_bfloat16 g_w2T_h[(size_t)L * D * FF];
__device__ __align__(16) __nv_bfloat16 g_w2T_l[(size_t)L * D * FF];
__device__ __align__(16) __nv_bfloat16 g_lmT_h[(size_t)V * D];
__device__ __align__(16) __nv_bfloat16 g_lmT_l[(size_t)V * D];

// ---------------------------------------------------------------------------
// PTX helpers (base sm_103-safe)
// ---------------------------------------------------------------------------
__device__ __forceinline__ uint32_t smem_u32(const void* p) {
    uint32_t a;
    asm("{ .reg .u64 t; cvta.to.shared.u64 t, %1; cvt.u32.u64 %0, t; }" : "=r"(a) : "l"(p));
    return a;
}
#define CP16(dst, src) \
    asm volatile("cp.async.cg.shared.global [%0], [%1], 16;" :: "r"(dst), "l"(src))
#define CP_COMMIT() asm volatile("cp.async.commit_group;" ::: "memory")
#define CP_WAIT(n)  asm volatile("cp.async.wait_group %0;" :: "n"(n) : "memory")

__device__ __forceinline__ void ldsm4(uint32_t* r, uint32_t addr) {
    asm volatile("ldmatrix.sync.aligned.m8n8.x4.shared.b16 {%0,%1,%2,%3}, [%4];"
                 : "=r"(r[0]), "=r"(r[1]), "=r"(r[2]), "=r"(r[3]) : "r"(addr));
}
__device__ __forceinline__ void mma_bf16(float* d, const uint32_t* a, const uint32_t* b) {
    asm volatile(
        "mma.sync.aligned.m16n8k16.row.col.f32.bf16.bf16.f32 "
        "{%0,%1,%2,%3}, {%4,%5,%6,%7}, {%8,%9}, {%0,%1,%2,%3};"
        : "+f"(d[0]), "+f"(d[1]), "+f"(d[2]), "+f"(d[3])
        : "r"(a[0]), "r"(a[1]), "r"(a[2]), "r"(a[3]), "r"(b[0]), "r"(b[1]));
}
__device__ __forceinline__ uint32_t pack2bf(float a, float b) {
    unsigned short ra = __bfloat16_as_ushort(__float2bfloat16(a));
    unsigned short rb = __bfloat16_as_ushort(__float2bfloat16(b));
    return (uint32_t)ra | ((uint32_t)rb << 16);
}

// ---------------------------------------------------------------------------
// shared GEMM core: 128x128 tile, K-tile 32, 256 thr, 3-pass bf16 hi/lo
// ---------------------------------------------------------------------------
#define MG_SMEM (2 * 32768)

__device__ __forceinline__ void tile_load(uint32_t sdst,
                                          const __nv_bfloat16* gh,
                                          const __nv_bfloat16* gl,
                                          int ld, int k0, int tid) {
#pragma unroll
    for (int i = 0; i < 4; i++) {
        int cid = i * 256 + tid;
        int row = cid >> 3, sub = cid & 7;
        const __nv_bfloat16* src =
            ((sub & 4) ? gl : gh) + (size_t)row * ld + k0 + (sub & 3) * 8;
        uint32_t dst = sdst + row * 128 + ((sub ^ (row & 7)) << 4);
        CP16(dst, src);
    }
}

__device__ __forceinline__ void gemm_core(float (&acc)[4][4][4],
                                          const __nv_bfloat16* Ah, const __nv_bfloat16* Al,
                                          const __nv_bfloat16* Bh, const __nv_bfloat16* Bl,
                                          int K, int bm, int bn, char* smem) {
    const int tid = threadIdx.x;
    const int wid = tid >> 5, lane = tid & 31;
    const int wm = (wid >> 2) * 64, wn = (wid & 3) * 32;
    uint32_t sbase = smem_u32(smem);

    const __nv_bfloat16* ah_g = Ah + (size_t)bm * K;
    const __nv_bfloat16* al_g = Al + (size_t)bm * K;
    const __nv_bfloat16* bh_g = Bh + (size_t)bn * K;
    const __nv_bfloat16* bl_g = Bl + (size_t)bn * K;

    const int nt = K >> 5;
    tile_load(sbase,         ah_g, al_g, K, 0, tid);
    tile_load(sbase + 16384, bh_g, bl_g, K, 0, tid);
    CP_COMMIT();

    for (int t = 0; t < nt; t++) {
        int b = t & 1;
        if (t + 1 < nt) {
            uint32_t nb = sbase + ((t + 1) & 1) * 32768;
            tile_load(nb,         ah_g, al_g, K, (t + 1) << 5, tid);
            tile_load(nb + 16384, bh_g, bl_g, K, (t + 1) << 5, tid);
            CP_COMMIT();
            CP_WAIT(1);
        } else {
            CP_WAIT(0);
        }
        __syncthreads();

        uint32_t sA = sbase + b * 32768;
        uint32_t sB = sA + 16384;
#pragma unroll
        for (int ks = 0; ks < 2; ks++) {
            uint32_t ahf[4][4], alf[4][4], bhf[2][4], blf[2][4];
#pragma unroll
            for (int f = 0; f < 4; f++) {
                int row = wm + f * 16 + (lane & 15);
                int jc = (lane >> 4) + ks * 2;
                ldsm4(ahf[f], sA + row * 128 + ((jc ^ (row & 7)) << 4));
                ldsm4(alf[f], sA + row * 128 + (((jc + 4) ^ (row & 7)) << 4));
            }
#pragma unroll
            for (int np = 0; np < 2; np++) {
                int row = wn + np * 16 + ((lane >> 4) << 3) + (lane & 7);
                int jc = ((lane >> 3) & 1) + ks * 2;
                ldsm4(bhf[np], sB + row * 128 + ((jc ^ (row & 7)) << 4));
                ldsm4(blf[np], sB + row * 128 + (((jc + 4) ^ (row & 7)) << 4));
            }
#pragma unroll
            for (int m = 0; m < 4; m++)
#pragma unroll
                for (int nf = 0; nf < 4; nf++) {
                    uint32_t* bhp = &bhf[nf >> 1][(nf & 1) * 2];
                    uint32_t* blp = &blf[nf >> 1][(nf & 1) * 2];
                    mma_bf16(acc[m][nf], ahf[m], bhp);
                    mma_bf16(acc[m][nf], ahf[m], blp);
                    mma_bf16(acc[m][nf], alf[m], bhp);
                }
        }
        __syncthreads();
    }
}

// fp32 output (+bias, +res, relu)
__global__ __launch_bounds__(256, 1)
void k_gemm_f32(const __nv_bfloat16* __restrict__ Ah, const __nv_bfloat16* __restrict__ Al,
                const __nv_bfloat16* __restrict__ Bh, const __nv_bfloat16* __restrict__ Bl,
                const float* __restrict__ bias, const float* __restrict__ res,
                float* __restrict__ C, int K, int ldc) {
    extern __shared__ char smem[];
    const int tid = threadIdx.x, wid = tid >> 5, lane = tid & 31;
    const int bm = blockIdx.y * 128, bn = blockIdx.x * 128;
    const int wm = (wid >> 2) * 64, wn = (wid & 3) * 32;
    float acc[4][4][4] = {};
    gemm_core(acc, Ah, Al, Bh, Bl, K, bm, bn, smem);
#pragma unroll
    for (int m = 0; m < 4; m++) {
        int r0 = bm + wm + m * 16 + (lane >> 2);
#pragma unroll
        for (int nf = 0; nf < 4; nf++) {
            int col = bn + wn + nf * 8 + ((lane & 3) << 1);
            float v0 = acc[m][nf][0], v1 = acc[m][nf][1];
            float v2 = acc[m][nf][2], v3 = acc[m][nf][3];
            if (bias) {
                float b0 = bias[col], b1 = bias[col + 1];
                v0 += b0; v1 += b1; v2 += b0; v3 += b1;
            }
            if (res) {
                const float* rr0 = res + (size_t)r0 * ldc + col;
                const float* rr1 = res + (size_t)(r0 + 8) * ldc + col;
                v0 += rr0[0]; v1 += rr0[1]; v2 += rr1[0]; v3 += rr1[1];
            }
            *(float2*)(C + (size_t)r0 * ldc + col) = make_float2(v0, v1);
            *(float2*)(C + (size_t)(r0 + 8) * ldc + col) = make_float2(v2, v3);
        }
    }
}

// bf16 hi/lo output (+bias, relu) — for FFN1
__global__ __launch_bounds__(256, 1)
void k_gemm_bf16(const __nv_bfloat16* __restrict__ Ah, const __nv_bfloat16* __restrict__ Al,
                 const __nv_bfloat16* __restrict__ Bh, const __nv_bfloat16* __restrict__ Bl,
                 const float* __restrict__ bias,
                 __nv_bfloat16* __restrict__ Ch, __nv_bfloat16* __restrict__ Cl,
                 int K, int ldc, int relu) {
    extern __shared__ char smem[];
    const int tid = threadIdx.x, wid = tid >> 5, lane = tid & 31;
    const int bm = blockIdx.y * 128, bn = blockIdx.x * 128;
    const int wm = (wid >> 2) * 64, wn = (wid & 3) * 32;
    float acc[4][4][4] = {};
    gemm_core(acc, Ah, Al, Bh, Bl, K, bm, bn, smem);
#pragma unroll
    for (int m = 0; m < 4; m++) {
        int r0 = bm + wm + m * 16 + (lane >> 2);
#pragma unroll
        for (int nf = 0; nf < 4; nf++) {
            int col = bn + wn + nf * 8 + ((lane & 3) << 1);
            float v[4] = {acc[m][nf][0], acc[m][nf][1], acc[m][nf][2], acc[m][nf][3]};
            if (bias) {
                float b0 = bias[col], b1 = bias[col + 1];
                v[0] += b0; v[1] += b1; v[2] += b0; v[3] += b1;
            }
            if (relu) {
#pragma unroll
                for (int e = 0; e < 4; e++) v[e] = fmaxf(v[e], 0.f);
            }
            float h0 = __bfloat162float(__float2bfloat16(v[0]));
            float h1 = __bfloat162float(__float2bfloat16(v[1]));
            float h2 = __bfloat162float(__float2bfloat16(v[2]));
            float h3 = __bfloat162float(__float2bfloat16(v[3]));
            *(uint32_t*)(Ch + (size_t)r0 * ldc + col) = pack2bf(v[0], v[1]);
            *(uint32_t*)(Ch + (size_t)(r0 + 8) * ldc + col) = pack2bf(v[2], v[3]);
            *(uint32_t*)(Cl + (size_t)r0 * ldc + col) = pack2bf(v[0] - h0, v[1] - h1);
            *(uint32_t*)(Cl + (size_t)(r0 + 8) * ldc + col) = pack2bf(v[2] - h2, v[3] - h3);
        }
    }
}

// QKV gemm: N=3072; cols [0,D)->q hi/lo, [D,2D)->k hi/lo, [2D,3D)->vT via smem
__global__ __launch_bounds__(256, 1)
void k_qkv_gemm(const __nv_bfloat16* __restrict__ Ah, const __nv_bfloat16* __restrict__ Al,
                const __nv_bfloat16* __restrict__ Bh, const __nv_bfloat16* __restrict__ Bl,
                __nv_bfloat16* __restrict__ qh, __nv_bfloat16* __restrict__ ql,
                __nv_bfloat16* __restrict__ kh, __nv_bfloat16* __restrict__ kl,
                __nv_bfloat16* __restrict__ vth, __nv_bfloat16* __restrict__ vtl) {
    extern __shared__ char smem[];
    const int tid = threadIdx.x, wid = tid >> 5, lane = tid & 31;
    const int bm = blockIdx.y * 128, bn = blockIdx.x * 128;
    const int wm = (wid >> 2) * 64, wn = (wid & 3) * 32;
    float acc[4][4][4] = {};
    gemm_core(acc, Ah, Al, Bh, Bl, D, bm, bn, smem);

    if (bn < 2 * D) {
        __nv_bfloat16* oh = (bn < D) ? qh : kh;
        __nv_bfloat16* ol = (bn < D) ? ql : kl;
        int cb = (bn < D) ? bn : bn - D;
#pragma unroll
        for (int m = 0; m < 4; m++) {
            int r0 = bm + wm + m * 16 + (lane >> 2);
#pragma unroll
            for (int nf = 0; nf < 4; nf++) {
                int col = cb + wn + nf * 8 + ((lane & 3) << 1);
                float v0 = acc[m][nf][0], v1 = acc[m][nf][1];
                float v2 = acc[m][nf][2], v3 = acc[m][nf][3];
                float h0 = __bfloat162float(__float2bfloat16(v0));
                float h1 = __bfloat162float(__float2bfloat16(v1));
                float h2 = __bfloat162float(__float2bfloat16(v2));
                float h3 = __bfloat162float(__float2bfloat16(v3));
                *(uint32_t*)(oh + (size_t)r0 * D + col) = pack2bf(v0, v1);
                *(uint32_t*)(oh + (size_t)(r0 + 8) * D + col) = pack2bf(v2, v3);
                *(uint32_t*)(ol + (size_t)r0 * D + col) = pack2bf(v0 - h0, v1 - h1);
                *(uint32_t*)(ol + (size_t)(r0 + 8) * D + col) = pack2bf(v2 - h2, v3 - h3);
            }
        }
    } else {
        // stage 128x128 bf16 into smem transposed, write vT [D, S] coalesced
        __nv_bfloat16* sv = (__nv_bfloat16*)smem;   // [col][row], row-stride 136 halves
#pragma unroll
        for (int part = 0; part < 2; part++) {
#pragma unroll
            for (int m = 0; m < 4; m++) {
#pragma unroll
                for (int nf = 0; nf < 4; nf++) {
#pragma unroll
                    for (int e = 0; e < 4; e++) {
                        int rl = wm + m * 16 + (lane >> 2) + ((e >> 1) ? 8 : 0);
                        int cl = wn + nf * 8 + ((lane & 3) << 1) + (e & 1);
                        float v = acc[m][nf][e];
                        float hv = __bfloat162float(__float2bfloat16(v));
                        sv[cl * 136 + rl] = __float2bfloat16(part ? (v - hv) : v);
                    }
                }
            }
            __syncthreads();
            int col = tid >> 1, half = tid & 1;
            const uint4* src = (const uint4*)(smem + col * 272 + half * 128);
            __nv_bfloat16* dst = (part ? vtl : vth) +
                                 (size_t)(bn - 2 * D + col) * S + bm + half * 64;
#pragma unroll
            for (int j = 0; j < 8; j++) ((uint4*)dst)[j] = src[j];
            __syncthreads();
        }
    }
}

// ---------------------------------------------------------------------------
// flash attention: CTA = (qblock 64, head), 128 thr (4 warps, m16 each)
// smem: Q hi/lo 16KB @0; stage s @16384+s*32768: Khi,Klo,VThi,VTlo (8KB each)
// ---------------------------------------------------------------------------
#define FA_SMEM (16384 + 2 * 32768)

__device__ __forceinline__ void fa_load(uint32_t sdst, const __nv_bfloat16* g,
                                        int ld, int tid) {
#pragma unroll
    for (int i = 0; i < 4; i++) {
        int cid = i * 128 + tid;
        int row = cid >> 3, c = cid & 7;
        CP16(sdst + row * 128 + ((c ^ (row & 7)) << 4), g + (size_t)row * ld + c * 8);
    }
}

__global__ __launch_bounds__(128)
void k_flash(const __nv_bfloat16* __restrict__ qh, const __nv_bfloat16* __restrict__ ql,
             const __nv_bfloat16* __restrict__ kh, const __nv_bfloat16* __restrict__ kl,
             const __nv_bfloat16* __restrict__ vth, const __nv_bfloat16* __restrict__ vtl,
             __nv_bfloat16* __restrict__ oh, __nv_bfloat16* __restrict__ ol) {
    extern __shared__ char smem[];
    uint32_t sb = smem_u32(smem);
    const int tid = threadIdx.x, w = tid >> 5, lane = tid & 31;
    const int qb = gridDim.x - 1 - blockIdx.x;
    const int hh = blockIdx.y;

    // Q tiles
    fa_load(sb,        qh + (size_t)(qb * 64) * D + hh * 64, D, tid);
    fa_load(sb + 8192, ql + (size_t)(qb * 64) * D + hh * 64, D, tid);
    // stage 0: K/VT for kb=0
    {
        uint32_t st = sb + 16384;
        fa_load(st,         kh + (size_t)0 * D + hh * 64, D, tid);
        fa_load(st + 8192,  kl + (size_t)0 * D + hh * 64, D, tid);
        fa_load(st + 16384, vth + (size_t)(hh * 64) * S, S, tid);
        fa_load(st + 24576, vtl + (size_t)(hh * 64) * S, S, tid);
    }
    CP_COMMIT();

    uint32_t qhf[4][4], qlf[4][4];
    float o_acc[8][4] = {};
    float m0 = -1e30f, m1 = -1e30f, l0 = 0.f, l1 = 0.f;

    for (int kb = 0; kb <= qb; kb++) {
        if (kb + 1 <= qb) {
            uint32_t st = sb + 16384 + ((kb + 1) & 1) * 32768;
            fa_load(st,         kh + (size_t)((kb + 1) * 64) * D + hh * 64, D, tid);
            fa_load(st + 8192,  kl + (size_t)((kb + 1) * 64) * D + hh * 64, D, tid);
            fa_load(st + 16384, vth + (size_t)(hh * 64) * S + (kb + 1) * 64, S, tid);
            fa_load(st + 24576, vtl + (size_t)(hh * 64) * S + (kb + 1) * 64, S, tid);
            CP_COMMIT();
            CP_WAIT(1);
        } else {
            CP_WAIT(0);
        }
        __syncthreads();

        if (kb == 0) {
#pragma unroll
            for (int f = 0; f < 4; f++) {
                int row = w * 16 + (lane & 15);
                int jc = (lane >> 4) + f * 2;
                ldsm4(qhf[f], sb + row * 128 + ((jc ^ (row & 7)) << 4));
                ldsm4(qlf[f], sb + 8192 + row * 128 + ((jc ^ (row & 7)) << 4));
            }
        }

        uint32_t st = sb + 16384 + (kb & 1) * 32768;
        // ---- S = Q K^T ----
        float s_acc[8][4] = {};
#pragma unroll
        for (int ks = 0; ks < 4; ks++) {
            uint32_t bh4[4][4], bl4[4][4];
#pragma unroll
            for (int np = 0; np < 4; np++) {
                int row = np * 16 + ((lane >> 4) << 3) + (lane & 7);
                int jc = ((lane >> 3) & 1) + ks * 2;
                ldsm4(bh4[np], st + row * 128 + ((jc ^ (row & 7)) << 4));
                ldsm4(bl4[np], st + 8192 + row * 128 + ((jc ^ (row & 7)) << 4));
            }
#pragma unroll
            for (int nf = 0; nf < 8; nf++) {
                uint32_t* bh = &bh4[nf >> 1][(nf & 1) * 2];
                uint32_t* bl = &bl4[nf >> 1][(nf & 1) * 2];
                mma_bf16(s_acc[nf], qhf[ks], bh);
                mma_bf16(s_acc[nf], qhf[ks], bl);
                mma_bf16(s_acc[nf], qlf[ks], bh);
            }
        }
        // scale + causal mask
        int r_lo = qb * 64 + w * 16 + (lane >> 2);
#pragma unroll
        for (int nf = 0; nf < 8; nf++)
#pragma unroll
            for (int e = 0; e < 4; e++) {
                float v = s_acc[nf][e] * 0.125f;
                if (kb == qb) {
                    int key = kb * 64 + nf * 8 + ((lane & 3) << 1) + (e & 1);
                    int qr = r_lo + ((e >> 1) ? 8 : 0);
                    if (key > qr) v = -1e30f;
                }
                s_acc[nf][e] = v;
            }
        // row max
        float mx0 = -1e30f, mx1 = -1e30f;
#pragma unroll
        for (int nf = 0; nf < 8; nf++) {
            mx0 = fmaxf(mx0, fmaxf(s_acc[nf][0], s_acc[nf][1]));
            mx1 = fmaxf(mx1, fmaxf(s_acc[nf][2], s_acc[nf][3]));
        }
        mx0 = fmaxf(mx0, __shfl_xor_sync(0xffffffffu, mx0, 1));
        mx0 = fmaxf(mx0, __shfl_xor_sync(0xffffffffu, mx0, 2));
        mx1 = fmaxf(mx1, __shfl_xor_sync(0xffffffffu, mx1, 1));
        mx1 = fmaxf(mx1, __shfl_xor_sync(0xffffffffu, mx1, 2));
        float mn0 = fmaxf(m0, mx0), mn1 = fmaxf(m1, mx1);
        float a0 = __expf(m0 - mn0), a1 = __expf(m1 - mn1);
        // P = exp(S - m), row sums
        float sum0 = 0.f, sum1 = 0.f;
#pragma unroll
        for (int nf = 0; nf < 8; nf++) {
            s_acc[nf][0] = __expf(s_acc[nf][0] - mn0);
            s_acc[nf][1] = __expf(s_acc[nf][1] - mn0);
            s_acc[nf][2] = __expf(s_acc[nf][2] - mn1);
            s_acc[nf][3] = __expf(s_acc[nf][3] - mn1);
            sum0 += s_acc[nf][0] + s_acc[nf][1];
            sum1 += s_acc[nf][2] + s_acc[nf][3];
        }
        sum0 += __shfl_xor_sync(0xffffffffu, sum0, 1);
        sum0 += __shfl_xor_sync(0xffffffffu, sum0, 2);
        sum1 += __shfl_xor_sync(0xffffffffu, sum1, 1);
        sum1 += __shfl_xor_sync(0xffffffffu, sum1, 2);
        l0 = l0 * a0 + sum0;
        l1 = l1 * a1 + sum1;
        m0 = mn0; m1 = mn1;
        // rescale O
#pragma unroll
        for (int nf = 0; nf < 8; nf++) {
            o_acc[nf][0] *= a0; o_acc[nf][1] *= a0;
            o_acc[nf][2] *= a1; o_acc[nf][3] *= a1;
        }
        // P -> bf16 hi/lo A-fragments
        uint32_t pph[4][4], ppl[4][4];
#pragma unroll
        for (int g = 0; g < 4; g++) {
            float c0 = s_acc[2 * g][0], c1 = s_acc[2 * g][1];
            float c2 = s_acc[2 * g][2], c3 = s_acc[2 * g][3];
            float d0 = s_acc[2 * g + 1][0], d1 = s_acc[2 * g + 1][1];
            float d2 = s_acc[2 * g + 1][2], d3 = s_acc[2 * g + 1][3];
            pph[g][0] = pack2bf(c0, c1); pph[g][1] = pack2bf(c2, c3);
            pph[g][2] = pack2bf(d0, d1); pph[g][3] = pack2bf(d2, d3);
            ppl[g][0] = pack2bf(c0 - __bfloat162float(__float2bfloat16(c0)),
                                c1 - __bfloat162float(__float2bfloat16(c1)));
            ppl[g][1] = pack2bf(c2 - __bfloat162float(__float2bfloat16(c2)),
                                c3 - __bfloat162float(__float2bfloat16(c3)));
            ppl[g][2] = pack2bf(d0 - __bfloat162float(__float2bfloat16(d0)),
                                d1 - __bfloat162float(__float2bfloat16(d1)));
            ppl[g][3] = pack2bf(d2 - __bfloat162float(__float2bfloat16(d2)),
                                d3 - __bfloat162float(__float2bfloat16(d3)));
        }
        // ---- O += P V ----
        uint32_t sv = st + 16384;
#pragma unroll
        for (int ks = 0; ks < 4; ks++) {
            uint32_t bh4[4][4], bl4[4][4];
#pragma unroll
            for (int np = 0; np < 4; np++) {
                int row = np * 16 + ((lane >> 4) << 3) + (lane & 7);
                int jc = ((lane >> 3) & 1) + ks * 2;
                ldsm4(bh4[np], sv + row * 128 + ((jc ^ (row & 7)) << 4));
                ldsm4(bl4[np], sv + 8192 + row * 128 + ((jc ^ (row & 7)) << 4));
            }
#pragma unroll
            for (int nf = 0; nf < 8; nf++) {
                uint32_t* bh = &bh4[nf >> 1][(nf & 1) * 2];
                uint32_t* bl = &bl4[nf >> 1][(nf & 1) * 2];
                mma_bf16(o_acc[nf], pph[ks], bh);
                mma_bf16(o_acc[nf], ppl[ks], bh);
                mma_bf16(o_acc[nf], pph[ks], bl);
            }
        }
        __syncthreads();
    }

    // epilogue: normalize + write hi/lo
    float inv0 = 1.f / l0, inv1 = 1.f / l1;
    int row0 = qb * 64 + w * 16 + (lane >> 2);
#pragma unroll
    for (int nf = 0; nf < 8; nf++) {
        int col = hh * 64 + nf * 8 + ((lane & 3) << 1);
        float v0 = o_acc[nf][0] * inv0, v1 = o_acc[nf][1] * inv0;
        float v2 = o_acc[nf][2] * inv1, v3 = o_acc[nf][3] * inv1;
        float h0 = __bfloat162float(__float2bfloat16(v0));
        float h1 = __bfloat162float(__float2bfloat16(v1));
        float h2 = __bfloat162float(__float2bfloat16(v2));
        float h3 = __bfloat162float(__float2bfloat16(v3));
        *(uint32_t*)(oh + (size_t)row0 * D + col) = pack2bf(v0, v1);
        *(uint32_t*)(oh + (size_t)(row0 + 8) * D + col) = pack2bf(v2, v3);
        *(uint32_t*)(ol + (size_t)row0 * D + col) = pack2bf(v0 - h0, v1 - h1);
        *(uint32_t*)(ol + (size_t)(row0 + 8) * D + col) = pack2bf(v2 - h2, v3 - h3);
    }
}

// ---------------------------------------------------------------------------
// weight transpose + split, 64x64 tiles
// ---------------------------------------------------------------------------
__global__ __launch_bounds__(256) void k_splitT(const float* __restrict__ W,
                                                __nv_bfloat16* __restrict__ th,
                                                __nv_bfloat16* __restrict__ tl,
                                                int N, int ldt) {
    __shared__ float s[64][65];
    int n0 = blockIdx.x * 64, k0 = blockIdx.y * 64;
    int t = threadIdx.x;
    int rr = t >> 4, c4 = t & 15;
#pragma unroll
    for (int i = 0; i < 4; i++) {
        int row = rr + i * 16;
        float4 v = *(const float4*)(W + (size_t)(k0 + row) * N + n0 + c4 * 4);
        s[row][c4 * 4 + 0] = v.x; s[row][c4 * 4 + 1] = v.y;
        s[row][c4 * 4 + 2] = v.z; s[row][c4 * 4 + 3] = v.w;
    }
    __syncthreads();
#pragma unroll
    for (int i = 0; i < 4; i++) {
        int r = rr + i * 16;
        float v0 = s[c4 * 4 + 0][r], v1 = s[c4 * 4 + 1][r];
        float v2 = s[c4 * 4 + 2][r], v3 = s[c4 * 4 + 3][r];
        float h0 = __bfloat162float(__float2bfloat16(v0));
        float h1 = __bfloat162float(__float2bfloat16(v1));
        float h2 = __bfloat162float(__float2bfloat16(v2));
        float h3 = __bfloat162float(__float2bfloat16(v3));
        size_t o = (size_t)(n0 + r) * ldt + k0 + c4 * 4;
        *(uint32_t*)(th + o) = pack2bf(v0, v1);
        *(uint32_t*)(th + o + 2) = pack2bf(v2, v3);
        *(uint32_t*)(tl + o) = pack2bf(v0 - h0, v1 - h1);
        *(uint32_t*)(tl + o + 2) = pack2bf(v2 - h2, v3 - h3);
    }
}

// ---------------------------------------------------------------------------
// embedding + positional encoding
// ---------------------------------------------------------------------------
__global__ __launch_bounds__(256) void k_embed(const int* __restrict__ x,
                                               const float* __restrict__ emb,
                                               float* __restrict__ h) {
    int s = blockIdx.y;
    int d = blockIdx.x * 256 + threadIdx.x;
    int tok = x[s];
    float e = emb[(size_t)tok * D + d];
    int i2 = d & ~1;
    float freq = expf((float)i2 * (-9.210340371976184f / (float)D));
    float ang = (float)s * freq;
    float pe = (d & 1) ? cosf(ang) : sinf(ang);
    h[(size_t)s * D + d] = e + pe;
}

// ---------------------------------------------------------------------------
// layernorm -> bf16 hi/lo
// ---------------------------------------------------------------------------
__global__ __launch_bounds__(256) void k_ln(const float* __restrict__ in,
                                            __nv_bfloat16* __restrict__ oh,
                                            __nv_bfloat16* __restrict__ ol,
                                            const float* __restrict__ w,
                                            const float* __restrict__ b) {
    int row = blockIdx.x;
    const float* xr = in + (size_t)row * D;
    int t = threadIdx.x;
    __shared__ float sh1[256];
    __shared__ float sh2[256];
    float s1 = 0.f, s2 = 0.f;
    for (int d = t; d < D; d += 256) {
        float v = xr[d];
        s1 += v; s2 += v * v;
    }
    sh1[t] = s1; sh2[t] = s2;
    __syncthreads();
    for (int o = 128; o > 0; o >>= 1) {
        if (t < o) { sh1[t] += sh1[t + o]; sh2[t] += sh2[t + o]; }
        __syncthreads();
    }
    float mean = sh1[0] * (1.0f / D);
    float var = sh2[0] * (1.0f / D) - mean * mean;
    float rstd = rsqrtf(var + EPSF);
    for (int d = t; d < D; d += 256) {
        float v = (xr[d] - mean) * rstd * w[d] + b[d];
        __nv_bfloat16 hv = __float2bfloat16(v);
        oh[(size_t)row * D + d] = hv;
        ol[(size_t)row * D + d] = __float2bfloat16(v - __bfloat162float(hv));
    }
}

// ---------------------------------------------------------------------------
// launch orchestration
// ---------------------------------------------------------------------------
extern "C" void kernel_launch(void* const* d_in, const int* in_sizes, int n_in,
                              void* d_out, int out_size) {
    (void)in_sizes; (void)n_in; (void)out_size;
    const int*   x      = (const int*)d_in[0];
    const float* emb    = (const float*)d_in[1];
    const float* Wq     = (const float*)d_in[2];
    const float* Wk     = (const float*)d_in[3];
    const float* Wv     = (const float*)d_in[4];
    const float* Wo     = (const float*)d_in[5];
    const float* bo     = (const float*)d_in[6];
    const float* ln1_w  = (const float*)d_in[7];
    const float* ln1_b  = (const float*)d_in[8];
    const float* W1     = (const float*)d_in[9];
    const float* b1     = (const float*)d_in[10];
    const float* W2     = (const float*)d_in[11];
    const float* b2     = (const float*)d_in[12];
    const float* ln2_w  = (const float*)d_in[13];
    const float* ln2_b  = (const float*)d_in[14];
    const float* fn_w   = (const float*)d_in[15];
    const float* fn_b   = (const float*)d_in[16];
    const float* lmhead = (const float*)d_in[17];
    float* out = (float*)d_out;

    static float* ph = nullptr;
    static __nv_bfloat16 *acth, *actl, *ffh, *ffl, *qh, *ql, *kh, *kl, *vth, *vtl,
                         *qkvTh, *qkvTl, *woTh, *woTl, *w1Th, *w1Tl, *w2Th, *w2Tl,
                         *lmTh, *lmTl;
    if (!ph) {
        cudaGetSymbolAddress((void**)&ph,    g_h);
        cudaGetSymbolAddress((void**)&acth,  g_act_h);
        cudaGetSymbolAddress((void**)&actl,  g_act_l);
        cudaGetSymbolAddress((void**)&ffh,   g_ff_h);
        cudaGetSymbolAddress((void**)&ffl,   g_ff_l);
        cudaGetSymbolAddress((void**)&qh,    g_qh);
        cudaGetSymbolAddress((void**)&ql,    g_ql);
        cudaGetSymbolAddress((void**)&kh,    g_kh);
        cudaGetSymbolAddress((void**)&kl,    g_kl);
        cudaGetSymbolAddress((void**)&vth,   g_vth);
        cudaGetSymbolAddress((void**)&vtl,   g_vtl);
        cudaGetSymbolAddress((void**)&qkvTh, g_qkvT_h);
        cudaGetSymbolAddress((void**)&qkvTl, g_qkvT_l);
        cudaGetSymbolAddress((void**)&woTh,  g_woT_h);
        cudaGetSymbolAddress((void**)&woTl,  g_woT_l);
        cudaGetSymbolAddress((void**)&w1Th,  g_w1T_h);
        cudaGetSymbolAddress((void**)&w1Tl,  g_w1T_l);
        cudaGetSymbolAddress((void**)&w2Th,  g_w2T_h);
        cudaGetSymbolAddress((void**)&w2Tl,  g_w2T_l);
        cudaGetSymbolAddress((void**)&lmTh,  g_lmT_h);
        cudaGetSymbolAddress((void**)&lmTl,  g_lmT_l);
        cudaFuncSetAttribute(k_gemm_f32,  cudaFuncAttributeMaxDynamicSharedMemorySize, MG_SMEM);
        cudaFuncSetAttribute(k_gemm_bf16, cudaFuncAttributeMaxDynamicSharedMemorySize, MG_SMEM);
        cudaFuncSetAttribute(k_qkv_gemm,  cudaFuncAttributeMaxDynamicSharedMemorySize, MG_SMEM);
        cudaFuncSetAttribute(k_flash,     cudaFuncAttributeMaxDynamicSharedMemorySize, FA_SMEM);
    }

    k_embed<<<dim3(D / 256, S), 256>>>(x, emb, ph);

    // weight transpose + split
    dim3 gTDD(D / 64, D / 64);
    for (int l = 0; l < L; l++) {
        size_t wo = (size_t)l * D * D;
        size_t qo = (size_t)l * 3 * D * D;
        k_splitT<<<gTDD, 256>>>(Wq + wo, qkvTh + qo,             qkvTl + qo,             D, D);
        k_splitT<<<gTDD, 256>>>(Wk + wo, qkvTh + qo + D * D,     qkvTl + qo + D * D,     D, D);
        k_splitT<<<gTDD, 256>>>(Wv + wo, qkvTh + qo + 2 * D * D, qkvTl + qo + 2 * D * D, D, D);
        k_splitT<<<gTDD, 256>>>(Wo + wo, woTh + wo, woTl + wo, D, D);
        k_splitT<<<dim3(FF / 64, D / 64), 256>>>(W1 + (size_t)l * D * FF,
                                                 w1Th + (size_t)l * FF * D,
                                                 w1Tl + (size_t)l * FF * D, FF, D);
        k_splitT<<<dim3(D / 64, FF / 64), 256>>>(W2 + (size_t)l * FF * D,
                                                 w2Th + (size_t)l * D * FF,
                                                 w2Tl + (size_t)l * D * FF, D, FF);
    }
    k_splitT<<<dim3(V / 64, D / 64), 256>>>(lmhead, lmTh, lmTl, V, D);

    for (int l = 0; l < L; l++) {
        size_t wo = (size_t)l * D * D;
        size_t qo = (size_t)l * 3 * D * D;
        // --- attention ---
        k_ln<<<S, 256>>>(ph, acth, actl, ln1_w + (size_t)l * D, ln1_b + (size_t)l * D);
        k_qkv_gemm<<<dim3(3 * D / 128, S / 128), 256, MG_SMEM>>>(
            acth, actl, qkvTh + qo, qkvTl + qo, qh, ql, kh, kl, vth, vtl);
        k_flash<<<dim3(S / 64, H), 128, FA_SMEM>>>(qh, ql, kh, kl, vth, vtl, acth, actl);
        k_gemm_f32<<<dim3(D / 128, S / 128), 256, MG_SMEM>>>(
            acth, actl, woTh + wo, woTl + wo, bo + (size_t)l * D, ph, ph, D, D);
        // --- FFN ---
        k_ln<<<S, 256>>>(ph, acth, actl, ln2_w + (size_t)l * D, ln2_b + (size_t)l * D);
        k_gemm_bf16<<<dim3(FF / 128, S / 128), 256, MG_SMEM>>>(
            acth, actl, w1Th + (size_t)l * FF * D, w1Tl + (size_t)l * FF * D,
            b1 + (size_t)l * FF, ffh, ffl, D, FF, 1);
        k_gemm_f32<<<dim3(D / 128, S / 128), 256, MG_SMEM>>>(
            ffh, ffl, w2Th + (size_t)l * D * FF, w2Tl + (size_t)l * D * FF,
            b2 + (size_t)l * D, ph, ph, FF, D);
    }

    // final LN + LM head
    k_ln<<<S, 256>>>(ph, acth, actl, fn_w, fn_b);
    k_gemm_f32<<<dim3(V / 128, S / 128), 256, MG_SMEM>>>(
        acth, actl, lmTh, lmTl, nullptr, nullptr, out, D, V);
}

// round 5
// speedup vs baseline: 2.7080x; 1.0340x over previous
#include <cuda_runtime.h>
#include <cuda_bf16.h>
#include <math.h>
#include <stdint.h>

#define S 1024
#define D 1024
#define H 16
#define HD 64
#define L 4
#define FF 4096
#define V 32000
#define EPSF 1e-5f

// ---------------------------------------------------------------------------
// device scratch
// ---------------------------------------------------------------------------
__device__ __align__(16) float g_h[S * D];

__device__ __align__(16) __nv_bfloat16 g_act_h[S * FF];
__device__ __align__(16) __nv_bfloat16 g_act_l[S * FF];
__device__ __align__(16) __nv_bfloat16 g_ff_h[S * FF];
__device__ __align__(16) __nv_bfloat16 g_ff_l[S * FF];
__device__ __align__(16) __nv_bfloat16 g_qh[S * D];
__device__ __align__(16) __nv_bfloat16 g_ql[S * D];
__device__ __align__(16) __nv_bfloat16 g_kh[S * D];
__device__ __align__(16) __nv_bfloat16 g_kl[S * D];
__device__ __align__(16) __nv_bfloat16 g_vth[D * S];
__device__ __align__(16) __nv_bfloat16 g_vtl[D * S];

__device__ __align__(16) __nv_bfloat16 g_qkvT_h[(size_t)L * 3 * D * D];
__device__ __align__(16) __nv_bfloat16 g_qkvT_l[(size_t)L * 3 * D * D];
__device__ __align__(16) __nv_bfloat16 g_woT_h[(size_t)L * D * D];
__device__ __align__(16) __nv_bfloat16 g_woT_l[(size_t)L * D * D];
__device__ __align__(16) __nv_bfloat16 g_w1T_h[(size_t)L * FF * D];
__device__ __align__(16) __nv_bfloat16 g_w1T_l[(size_t)L * FF * D];
__device__ __align__(16) __nv_bfloat16 g_w2T_h[(size_t)L * D * FF];
__device__ __align__(16) __nv_bfloat16 g_w2T_l[(size_t)L * D * FF];
__device__ __align__(16) __nv_bfloat16 g_lmT_h[(size_t)V * D];
__device__ __align__(16) __nv_bfloat16 g_lmT_l[(size_t)V * D];

// ---------------------------------------------------------------------------
// PTX helpers (base sm_103-safe)
// ---------------------------------------------------------------------------
__device__ __forceinline__ uint32_t smem_u32(const void* p) {
    uint32_t a;
    asm("{ .reg .u64 t; cvta.to.shared.u64 t, %1; cvt.u32.u64 %0, t; }" : "=r"(a) : "l"(p));
    return a;
}
#define CP16(dst, src) \
    asm volatile("cp.async.cg.shared.global [%0], [%1], 16;" :: "r"(dst), "l"(src))
#define CP_COMMIT() asm volatile("cp.async.commit_group;" ::: "memory")
#define CP_WAIT(n)  asm volatile("cp.async.wait_group %0;" :: "n"(n) : "memory")

__device__ __forceinline__ void ldsm4(uint32_t* r, uint32_t addr) {
    asm volatile("ldmatrix.sync.aligned.m8n8.x4.shared.b16 {%0,%1,%2,%3}, [%4];"
                 : "=r"(r[0]), "=r"(r[1]), "=r"(r[2]), "=r"(r[3]) : "r"(addr));
}
__device__ __forceinline__ void mma_bf16(float* d, const uint32_t* a, const uint32_t* b) {
    asm volatile(
        "mma.sync.aligned.m16n8k16.row.col.f32.bf16.bf16.f32 "
        "{%0,%1,%2,%3}, {%4,%5,%6,%7}, {%8,%9}, {%0,%1,%2,%3};"
        : "+f"(d[0]), "+f"(d[1]), "+f"(d[2]), "+f"(d[3])
        : "r"(a[0]), "r"(a[1]), "r"(a[2]), "r"(a[3]), "r"(b[0]), "r"(b[1]));
}
__device__ __forceinline__ uint32_t pack2bf(float a, float b) {
    unsigned short ra = __bfloat16_as_ushort(__float2bfloat16(a));
    unsigned short rb = __bfloat16_as_ushort(__float2bfloat16(b));
    return (uint32_t)ra | ((uint32_t)rb << 16);
}

// ---------------------------------------------------------------------------
// shared GEMM core: 128x128 tile, K-tile 32, 256 thr, 3-pass bf16 hi/lo
// ---------------------------------------------------------------------------
#define MG_SMEM (2 * 32768)

__device__ __forceinline__ void tile_load(uint32_t sdst,
                                          const __nv_bfloat16* gh,
                                          const __nv_bfloat16* gl,
                                          int ld, int k0, int tid) {
#pragma unroll
    for (int i = 0; i < 4; i++) {
        int cid = i * 256 + tid;
        int row = cid >> 3, sub = cid & 7;
        const __nv_bfloat16* src =
            ((sub & 4) ? gl : gh) + (size_t)row * ld + k0 + (sub & 3) * 8;
        uint32_t dst = sdst + row * 128 + ((sub ^ (row & 7)) << 4);
        CP16(dst, src);
    }
}

__device__ __forceinline__ void gemm_core(float (&acc)[4][4][4],
                                          const __nv_bfloat16* Ah, const __nv_bfloat16* Al,
                                          const __nv_bfloat16* Bh, const __nv_bfloat16* Bl,
                                          int K, int bm, int bn, char* smem) {
    const int tid = threadIdx.x;
    const int wid = tid >> 5, lane = tid & 31;
    const int wm = (wid >> 2) * 64, wn = (wid & 3) * 32;
    uint32_t sbase = smem_u32(smem);

    const __nv_bfloat16* ah_g = Ah + (size_t)bm * K;
    const __nv_bfloat16* al_g = Al + (size_t)bm * K;
    const __nv_bfloat16* bh_g = Bh + (size_t)bn * K;
    const __nv_bfloat16* bl_g = Bl + (size_t)bn * K;

    const int nt = K >> 5;
    tile_load(sbase,         ah_g, al_g, K, 0, tid);
    tile_load(sbase + 16384, bh_g, bl_g, K, 0, tid);
    CP_COMMIT();

    for (int t = 0; t < nt; t++) {
        int b = t & 1;
        if (t + 1 < nt) {
            uint32_t nb = sbase + ((t + 1) & 1) * 32768;
            tile_load(nb,         ah_g, al_g, K, (t + 1) << 5, tid);
            tile_load(nb + 16384, bh_g, bl_g, K, (t + 1) << 5, tid);
            CP_COMMIT();
            CP_WAIT(1);
        } else {
            CP_WAIT(0);
        }
        __syncthreads();

        uint32_t sA = sbase + b * 32768;
        uint32_t sB = sA + 16384;
#pragma unroll
        for (int ks = 0; ks < 2; ks++) {
            uint32_t ahf[4][4], alf[4][4], bhf[2][4], blf[2][4];
#pragma unroll
            for (int f = 0; f < 4; f++) {
                int row = wm + f * 16 + (lane & 15);
                int jc = (lane >> 4) + ks * 2;
                ldsm4(ahf[f], sA + row * 128 + ((jc ^ (row & 7)) << 4));
                ldsm4(alf[f], sA + row * 128 + (((jc + 4) ^ (row & 7)) << 4));
            }
#pragma unroll
            for (int np = 0; np < 2; np++) {
                int row = wn + np * 16 + ((lane >> 4) << 3) + (lane & 7);
                int jc = ((lane >> 3) & 1) + ks * 2;
                ldsm4(bhf[np], sB + row * 128 + ((jc ^ (row & 7)) << 4));
                ldsm4(blf[np], sB + row * 128 + (((jc + 4) ^ (row & 7)) << 4));
            }
#pragma unroll
            for (int m = 0; m < 4; m++)
#pragma unroll
                for (int nf = 0; nf < 4; nf++) {
                    uint32_t* bhp = &bhf[nf >> 1][(nf & 1) * 2];
                    uint32_t* blp = &blf[nf >> 1][(nf & 1) * 2];
                    mma_bf16(acc[m][nf], ahf[m], bhp);
                    mma_bf16(acc[m][nf], ahf[m], blp);
                    mma_bf16(acc[m][nf], alf[m], bhp);
                }
        }
        __syncthreads();
    }
}

// fp32 output (+bias, +res)
__global__ __launch_bounds__(256, 1)
void k_gemm_f32(const __nv_bfloat16* __restrict__ Ah, const __nv_bfloat16* __restrict__ Al,
                const __nv_bfloat16* __restrict__ Bh, const __nv_bfloat16* __restrict__ Bl,
                const float* __restrict__ bias, const float* __restrict__ res,
                float* __restrict__ C, int K, int ldc) {
    extern __shared__ char smem[];
    const int tid = threadIdx.x, wid = tid >> 5, lane = tid & 31;
    const int bm = blockIdx.y * 128, bn = blockIdx.x * 128;
    const int wm = (wid >> 2) * 64, wn = (wid & 3) * 32;
    float acc[4][4][4] = {};
    gemm_core(acc, Ah, Al, Bh, Bl, K, bm, bn, smem);
#pragma unroll
    for (int m = 0; m < 4; m++) {
        int r0 = bm + wm + m * 16 + (lane >> 2);
#pragma unroll
        for (int nf = 0; nf < 4; nf++) {
            int col = bn + wn + nf * 8 + ((lane & 3) << 1);
            float v0 = acc[m][nf][0], v1 = acc[m][nf][1];
            float v2 = acc[m][nf][2], v3 = acc[m][nf][3];
            if (bias) {
                float b0 = bias[col], b1 = bias[col + 1];
                v0 += b0; v1 += b1; v2 += b0; v3 += b1;
            }
            if (res) {
                const float* rr0 = res + (size_t)r0 * ldc + col;
                const float* rr1 = res + (size_t)(r0 + 8) * ldc + col;
                v0 += rr0[0]; v1 += rr0[1]; v2 += rr1[0]; v3 += rr1[1];
            }
            *(float2*)(C + (size_t)r0 * ldc + col) = make_float2(v0, v1);
            *(float2*)(C + (size_t)(r0 + 8) * ldc + col) = make_float2(v2, v3);
        }
    }
}

// bf16 hi/lo output (+bias, relu) — for FFN1
__global__ __launch_bounds__(256, 1)
void k_gemm_bf16(const __nv_bfloat16* __restrict__ Ah, const __nv_bfloat16* __restrict__ Al,
                 const __nv_bfloat16* __restrict__ Bh, const __nv_bfloat16* __restrict__ Bl,
                 const float* __restrict__ bias,
                 __nv_bfloat16* __restrict__ Ch, __nv_bfloat16* __restrict__ Cl,
                 int K, int ldc, int relu) {
    extern __shared__ char smem[];
    const int tid = threadIdx.x, wid = tid >> 5, lane = tid & 31;
    const int bm = blockIdx.y * 128, bn = blockIdx.x * 128;
    const int wm = (wid >> 2) * 64, wn = (wid & 3) * 32;
    float acc[4][4][4] = {};
    gemm_core(acc, Ah, Al, Bh, Bl, K, bm, bn, smem);
#pragma unroll
    for (int m = 0; m < 4; m++) {
        int r0 = bm + wm + m * 16 + (lane >> 2);
#pragma unroll
        for (int nf = 0; nf < 4; nf++) {
            int col = bn + wn + nf * 8 + ((lane & 3) << 1);
            float v[4] = {acc[m][nf][0], acc[m][nf][1], acc[m][nf][2], acc[m][nf][3]};
            if (bias) {
                float b0 = bias[col], b1 = bias[col + 1];
                v[0] += b0; v[1] += b1; v[2] += b0; v[3] += b1;
            }
            if (relu) {
#pragma unroll
                for (int e = 0; e < 4; e++) v[e] = fmaxf(v[e], 0.f);
            }
            float h0 = __bfloat162float(__float2bfloat16(v[0]));
            float h1 = __bfloat162float(__float2bfloat16(v[1]));
            float h2 = __bfloat162float(__float2bfloat16(v[2]));
            float h3 = __bfloat162float(__float2bfloat16(v[3]));
            *(uint32_t*)(Ch + (size_t)r0 * ldc + col) = pack2bf(v[0], v[1]);
            *(uint32_t*)(Ch + (size_t)(r0 + 8) * ldc + col) = pack2bf(v[2], v[3]);
            *(uint32_t*)(Cl + (size_t)r0 * ldc + col) = pack2bf(v[0] - h0, v[1] - h1);
            *(uint32_t*)(Cl + (size_t)(r0 + 8) * ldc + col) = pack2bf(v[2] - h2, v[3] - h3);
        }
    }
}

// QKV gemm: N=3072; cols [0,D)->q hi/lo, [D,2D)->k hi/lo, [2D,3D)->vT via smem
__global__ __launch_bounds__(256, 1)
void k_qkv_gemm(const __nv_bfloat16* __restrict__ Ah, const __nv_bfloat16* __restrict__ Al,
                const __nv_bfloat16* __restrict__ Bh, const __nv_bfloat16* __restrict__ Bl,
                __nv_bfloat16* __restrict__ qh, __nv_bfloat16* __restrict__ ql,
                __nv_bfloat16* __restrict__ kh, __nv_bfloat16* __restrict__ kl,
                __nv_bfloat16* __restrict__ vth, __nv_bfloat16* __restrict__ vtl) {
    extern __shared__ char smem[];
    const int tid = threadIdx.x, wid = tid >> 5, lane = tid & 31;
    const int bm = blockIdx.y * 128, bn = blockIdx.x * 128;
    const int wm = (wid >> 2) * 64, wn = (wid & 3) * 32;
    float acc[4][4][4] = {};
    gemm_core(acc, Ah, Al, Bh, Bl, D, bm, bn, smem);

    if (bn < 2 * D) {
        __nv_bfloat16* oh = (bn < D) ? qh : kh;
        __nv_bfloat16* ol = (bn < D) ? ql : kl;
        int cb = (bn < D) ? bn : bn - D;
#pragma unroll
        for (int m = 0; m < 4; m++) {
            int r0 = bm + wm + m * 16 + (lane >> 2);
#pragma unroll
            for (int nf = 0; nf < 4; nf++) {
                int col = cb + wn + nf * 8 + ((lane & 3) << 1);
                float v0 = acc[m][nf][0], v1 = acc[m][nf][1];
                float v2 = acc[m][nf][2], v3 = acc[m][nf][3];
                float h0 = __bfloat162float(__float2bfloat16(v0));
                float h1 = __bfloat162float(__float2bfloat16(v1));
                float h2 = __bfloat162float(__float2bfloat16(v2));
                float h3 = __bfloat162float(__float2bfloat16(v3));
                *(uint32_t*)(oh + (size_t)r0 * D + col) = pack2bf(v0, v1);
                *(uint32_t*)(oh + (size_t)(r0 + 8) * D + col) = pack2bf(v2, v3);
                *(uint32_t*)(ol + (size_t)r0 * D + col) = pack2bf(v0 - h0, v1 - h1);
                *(uint32_t*)(ol + (size_t)(r0 + 8) * D + col) = pack2bf(v2 - h2, v3 - h3);
            }
        }
    } else {
        // stage 128x128 bf16 into smem transposed, write vT [D, S] coalesced
        __nv_bfloat16* sv = (__nv_bfloat16*)smem;   // [col][row], row-stride 136 halves
#pragma unroll
        for (int part = 0; part < 2; part++) {
#pragma unroll
            for (int m = 0; m < 4; m++) {
#pragma unroll
                for (int nf = 0; nf < 4; nf++) {
#pragma unroll
                    for (int e = 0; e < 4; e++) {
                        int rl = wm + m * 16 + (lane >> 2) + ((e >> 1) ? 8 : 0);
                        int cl = wn + nf * 8 + ((lane & 3) << 1) + (e & 1);
                        float v = acc[m][nf][e];
                        float hv = __bfloat162float(__float2bfloat16(v));
                        sv[cl * 136 + rl] = __float2bfloat16(part ? (v - hv) : v);
                    }
                }
            }
            __syncthreads();
            int col = tid >> 1, half = tid & 1;
            const uint4* src = (const uint4*)(smem + col * 272 + half * 128);
            __nv_bfloat16* dst = (part ? vtl : vth) +
                                 (size_t)(bn - 2 * D + col) * S + bm + half * 64;
#pragma unroll
            for (int j = 0; j < 8; j++) ((uint4*)dst)[j] = src[j];
            __syncthreads();
        }
    }
}

// ---------------------------------------------------------------------------
// flash attention: CTA = (qblock 64, head), 128 thr (4 warps, m16 each)
// ---------------------------------------------------------------------------
#define FA_SMEM (16384 + 2 * 32768)

__device__ __forceinline__ void fa_load(uint32_t sdst, const __nv_bfloat16* g,
                                        int ld, int tid) {
#pragma unroll
    for (int i = 0; i < 4; i++) {
        int cid = i * 128 + tid;
        int row = cid >> 3, c = cid & 7;
        CP16(sdst + row * 128 + ((c ^ (row & 7)) << 4), g + (size_t)row * ld + c * 8);
    }
}

__global__ __launch_bounds__(128)
void k_flash(const __nv_bfloat16* __restrict__ qh, const __nv_bfloat16* __restrict__ ql,
             const __nv_bfloat16* __restrict__ kh, const __nv_bfloat16* __restrict__ kl,
             const __nv_bfloat16* __restrict__ vth, const __nv_bfloat16* __restrict__ vtl,
             __nv_bfloat16* __restrict__ oh, __nv_bfloat16* __restrict__ ol) {
    extern __shared__ char smem[];
    uint32_t sb = smem_u32(smem);
    const int tid = threadIdx.x, w = tid >> 5, lane = tid & 31;
    const int qb = gridDim.x - 1 - blockIdx.x;
    const int hh = blockIdx.y;

    fa_load(sb,        qh + (size_t)(qb * 64) * D + hh * 64, D, tid);
    fa_load(sb + 8192, ql + (size_t)(qb * 64) * D + hh * 64, D, tid);
    {
        uint32_t st = sb + 16384;
        fa_load(st,         kh + (size_t)0 * D + hh * 64, D, tid);
        fa_load(st + 8192,  kl + (size_t)0 * D + hh * 64, D, tid);
        fa_load(st + 16384, vth + (size_t)(hh * 64) * S, S, tid);
        fa_load(st + 24576, vtl + (size_t)(hh * 64) * S, S, tid);
    }
    CP_COMMIT();

    uint32_t qhf[4][4], qlf[4][4];
    float o_acc[8][4] = {};
    float m0 = -1e30f, m1 = -1e30f, l0 = 0.f, l1 = 0.f;

    for (int kb = 0; kb <= qb; kb++) {
        if (kb + 1 <= qb) {
            uint32_t st = sb + 16384 + ((kb + 1) & 1) * 32768;
            fa_load(st,         kh + (size_t)((kb + 1) * 64) * D + hh * 64, D, tid);
            fa_load(st + 8192,  kl + (size_t)((kb + 1) * 64) * D + hh * 64, D, tid);
            fa_load(st + 16384, vth + (size_t)(hh * 64) * S + (kb + 1) * 64, S, tid);
            fa_load(st + 24576, vtl + (size_t)(hh * 64) * S + (kb + 1) * 64, S, tid);
            CP_COMMIT();
            CP_WAIT(1);
        } else {
            CP_WAIT(0);
        }
        __syncthreads();

        if (kb == 0) {
#pragma unroll
            for (int f = 0; f < 4; f++) {
                int row = w * 16 + (lane & 15);
                int jc = (lane >> 4) + f * 2;
                ldsm4(qhf[f], sb + row * 128 + ((jc ^ (row & 7)) << 4));
                ldsm4(qlf[f], sb + 8192 + row * 128 + ((jc ^ (row & 7)) << 4));
            }
        }

        uint32_t st = sb + 16384 + (kb & 1) * 32768;
        float s_acc[8][4] = {};
#pragma unroll
        for (int ks = 0; ks < 4; ks++) {
            uint32_t bh4[4][4], bl4[4][4];
#pragma unroll
            for (int np = 0; np < 4; np++) {
                int row = np * 16 + ((lane >> 4) << 3) + (lane & 7);
                int jc = ((lane >> 3) & 1) + ks * 2;
                ldsm4(bh4[np], st + row * 128 + ((jc ^ (row & 7)) << 4));
                ldsm4(bl4[np], st + 8192 + row * 128 + ((jc ^ (row & 7)) << 4));
            }
#pragma unroll
            for (int nf = 0; nf < 8; nf++) {
                uint32_t* bh = &bh4[nf >> 1][(nf & 1) * 2];
                uint32_t* bl = &bl4[nf >> 1][(nf & 1) * 2];
                mma_bf16(s_acc[nf], qhf[ks], bh);
                mma_bf16(s_acc[nf], qhf[ks], bl);
                mma_bf16(s_acc[nf], qlf[ks], bh);
            }
        }
        int r_lo = qb * 64 + w * 16 + (lane >> 2);
#pragma unroll
        for (int nf = 0; nf < 8; nf++)
#pragma unroll
            for (int e = 0; e < 4; e++) {
                float v = s_acc[nf][e] * 0.125f;
                if (kb == qb) {
                    int key = kb * 64 + nf * 8 + ((lane & 3) << 1) + (e & 1);
                    int qr = r_lo + ((e >> 1) ? 8 : 0);
                    if (key > qr) v = -1e30f;
                }
                s_acc[nf][e] = v;
            }
        float mx0 = -1e30f, mx1 = -1e30f;
#pragma unroll
        for (int nf = 0; nf < 8; nf++) {
            mx0 = fmaxf(mx0, fmaxf(s_acc[nf][0], s_acc[nf][1]));
            mx1 = fmaxf(mx1, fmaxf(s_acc[nf][2], s_acc[nf][3]));
        }
        mx0 = fmaxf(mx0, __shfl_xor_sync(0xffffffffu, mx0, 1));
        mx0 = fmaxf(mx0, __shfl_xor_sync(0xffffffffu, mx0, 2));
        mx1 = fmaxf(mx1, __shfl_xor_sync(0xffffffffu, mx1, 1));
        mx1 = fmaxf(mx1, __shfl_xor_sync(0xffffffffu, mx1, 2));
        float mn0 = fmaxf(m0, mx0), mn1 = fmaxf(m1, mx1);
        float a0 = __expf(m0 - mn0), a1 = __expf(m1 - mn1);
        float sum0 = 0.f, sum1 = 0.f;
#pragma unroll
        for (int nf = 0; nf < 8; nf++) {
            s_acc[nf][0] = __expf(s_acc[nf][0] - mn0);
            s_acc[nf][1] = __expf(s_acc[nf][1] - mn0);
            s_acc[nf][2] = __expf(s_acc[nf][2] - mn1);
            s_acc[nf][3] = __expf(s_acc[nf][3] - mn1);
            sum0 += s_acc[nf][0] + s_acc[nf][1];
            sum1 += s_acc[nf][2] + s_acc[nf][3];
        }
        sum0 += __shfl_xor_sync(0xffffffffu, sum0, 1);
        sum0 += __shfl_xor_sync(0xffffffffu, sum0, 2);
        sum1 += __shfl_xor_sync(0xffffffffu, sum1, 1);
        sum1 += __shfl_xor_sync(0xffffffffu, sum1, 2);
        l0 = l0 * a0 + sum0;
        l1 = l1 * a1 + sum1;
        m0 = mn0; m1 = mn1;
#pragma unroll
        for (int nf = 0; nf < 8; nf++) {
            o_acc[nf][0] *= a0; o_acc[nf][1] *= a0;
            o_acc[nf][2] *= a1; o_acc[nf][3] *= a1;
        }
        uint32_t pph[4][4], ppl[4][4];
#pragma unroll
        for (int g = 0; g < 4; g++) {
            float c0 = s_acc[2 * g][0], c1 = s_acc[2 * g][1];
            float c2 = s_acc[2 * g][2], c3 = s_acc[2 * g][3];
            float d0 = s_acc[2 * g + 1][0], d1 = s_acc[2 * g + 1][1];
            float d2 = s_acc[2 * g + 1][2], d3 = s_acc[2 * g + 1][3];
            pph[g][0] = pack2bf(c0, c1); pph[g][1] = pack2bf(c2, c3);
            pph[g][2] = pack2bf(d0, d1); pph[g][3] = pack2bf(d2, d3);
            ppl[g][0] = pack2bf(c0 - __bfloat162float(__float2bfloat16(c0)),
                                c1 - __bfloat162float(__float2bfloat16(c1)));
            ppl[g][1] = pack2bf(c2 - __bfloat162float(__float2bfloat16(c2)),
                                c3 - __bfloat162float(__float2bfloat16(c3)));
            ppl[g][2] = pack2bf(d0 - __bfloat162float(__float2bfloat16(d0)),
                                d1 - __bfloat162float(__float2bfloat16(d1)));
            ppl[g][3] = pack2bf(d2 - __bfloat162float(__float2bfloat16(d2)),
                                d3 - __bfloat162float(__float2bfloat16(d3)));
        }
        uint32_t sv = st + 16384;
#pragma unroll
        for (int ks = 0; ks < 4; ks++) {
            uint32_t bh4[4][4], bl4[4][4];
#pragma unroll
            for (int np = 0; np < 4; np++) {
                int row = np * 16 + ((lane >> 4) << 3) + (lane & 7);
                int jc = ((lane >> 3) & 1) + ks * 2;
                ldsm4(bh4[np], sv + row * 128 + ((jc ^ (row & 7)) << 4));
                ldsm4(bl4[np], sv + 8192 + row * 128 + ((jc ^ (row & 7)) << 4));
            }
#pragma unroll
            for (int nf = 0; nf < 8; nf++) {
                uint32_t* bh = &bh4[nf >> 1][(nf & 1) * 2];
                uint32_t* bl = &bl4[nf >> 1][(nf & 1) * 2];
                mma_bf16(o_acc[nf], pph[ks], bh);
                mma_bf16(o_acc[nf], ppl[ks], bh);
                mma_bf16(o_acc[nf], pph[ks], bl);
            }
        }
        __syncthreads();
    }

    float inv0 = 1.f / l0, inv1 = 1.f / l1;
    int row0 = qb * 64 + w * 16 + (lane >> 2);
#pragma unroll
    for (int nf = 0; nf < 8; nf++) {
        int col = hh * 64 + nf * 8 + ((lane & 3) << 1);
        float v0 = o_acc[nf][0] * inv0, v1 = o_acc[nf][1] * inv0;
        float v2 = o_acc[nf][2] * inv1, v3 = o_acc[nf][3] * inv1;
        float h0 = __bfloat162float(__float2bfloat16(v0));
        float h1 = __bfloat162float(__float2bfloat16(v1));
        float h2 = __bfloat162float(__float2bfloat16(v2));
        float h3 = __bfloat162float(__float2bfloat16(v3));
        *(uint32_t*)(oh + (size_t)row0 * D + col) = pack2bf(v0, v1);
        *(uint32_t*)(oh + (size_t)(row0 + 8) * D + col) = pack2bf(v2, v3);
        *(uint32_t*)(ol + (size_t)row0 * D + col) = pack2bf(v0 - h0, v1 - h1);
        *(uint32_t*)(ol + (size_t)(row0 + 8) * D + col) = pack2bf(v2 - h2, v3 - h3);
    }
}

// ---------------------------------------------------------------------------
// weight transpose + split: 64x64 tiles, 16 elem/thread, uint4 stores
// W [K,N] row-major -> th/tl [N,K] bf16
// ---------------------------------------------------------------------------
__global__ __launch_bounds__(256) void k_splitT(const float* __restrict__ W,
                                                __nv_bfloat16* __restrict__ th,
                                                __nv_bfloat16* __restrict__ tl,
                                                int N, int ldt) {
    __shared__ float s[64][65];
    int n0 = blockIdx.x * 64, k0 = blockIdx.y * 64;
    int t = threadIdx.x;
    {
        int rr = t >> 4, c4 = (t & 15) * 4;
#pragma unroll
        for (int i = 0; i < 4; i++) {
            int row = rr + i * 16;
            float4 v = *(const float4*)(W + (size_t)(k0 + row) * N + n0 + c4);
            s[row][c4 + 0] = v.x; s[row][c4 + 1] = v.y;
            s[row][c4 + 2] = v.z; s[row][c4 + 3] = v.w;
        }
    }
    __syncthreads();
    {
        int n = t >> 2, kk = (t & 3) * 16;
        float v[16];
#pragma unroll
        for (int j = 0; j < 16; j++) v[j] = s[kk + j][n];
        uint4 uh0, uh1, ul0, ul1;
        uh0.x = pack2bf(v[0], v[1]);   uh0.y = pack2bf(v[2], v[3]);
        uh0.z = pack2bf(v[4], v[5]);   uh0.w = pack2bf(v[6], v[7]);
        uh1.x = pack2bf(v[8], v[9]);   uh1.y = pack2bf(v[10], v[11]);
        uh1.z = pack2bf(v[12], v[13]); uh1.w = pack2bf(v[14], v[15]);
        float r[16];
#pragma unroll
        for (int j = 0; j < 16; j++) r[j] = v[j] - __bfloat162float(__float2bfloat16(v[j]));
        ul0.x = pack2bf(r[0], r[1]);   ul0.y = pack2bf(r[2], r[3]);
        ul0.z = pack2bf(r[4], r[5]);   ul0.w = pack2bf(r[6], r[7]);
        ul1.x = pack2bf(r[8], r[9]);   ul1.y = pack2bf(r[10], r[11]);
        ul1.z = pack2bf(r[12], r[13]); ul1.w = pack2bf(r[14], r[15]);
        size_t off = (size_t)(n0 + n) * ldt + k0 + kk;
        *(uint4*)(th + off) = uh0;
        *(uint4*)(th + off + 8) = uh1;
        *(uint4*)(tl + off) = ul0;
        *(uint4*)(tl + off + 8) = ul1;
    }
}

// ---------------------------------------------------------------------------
// embedding + positional encoding
// ---------------------------------------------------------------------------
__global__ __launch_bounds__(256) void k_embed(const int* __restrict__ x,
                                               const float* __restrict__ emb,
                                               float* __restrict__ h) {
    int s = blockIdx.y;
    int d = blockIdx.x * 256 + threadIdx.x;
    int tok = x[s];
    float e = emb[(size_t)tok * D + d];
    int i2 = d & ~1;
    float freq = expf((float)i2 * (-9.210340371976184f / (float)D));
    float ang = (float)s * freq;
    float pe = (d & 1) ? cosf(ang) : sinf(ang);
    h[(size_t)s * D + d] = e + pe;
}

// ---------------------------------------------------------------------------
// layernorm -> bf16 hi/lo
// ---------------------------------------------------------------------------
__global__ __launch_bounds__(256) void k_ln(const float* __restrict__ in,
                                            __nv_bfloat16* __restrict__ oh,
                                            __nv_bfloat16* __restrict__ ol,
                                            const float* __restrict__ w,
                                            const float* __restrict__ b) {
    int row = blockIdx.x;
    const float* xr = in + (size_t)row * D;
    int t = threadIdx.x;
    __shared__ float sh1[256];
    __shared__ float sh2[256];
    float s1 = 0.f, s2 = 0.f;
    for (int d = t; d < D; d += 256) {
        float v = xr[d];
        s1 += v; s2 += v * v;
    }
    sh1[t] = s1; sh2[t] = s2;
    __syncthreads();
    for (int o = 128; o > 0; o >>= 1) {
        if (t < o) { sh1[t] += sh1[t + o]; sh2[t] += sh2[t + o]; }
        __syncthreads();
    }
    float mean = sh1[0] * (1.0f / D);
    float var = sh2[0] * (1.0f / D) - mean * mean;
    float rstd = rsqrtf(var + EPSF);
    for (int d = t; d < D; d += 256) {
        float v = (xr[d] - mean) * rstd * w[d] + b[d];
        __nv_bfloat16 hv = __float2bfloat16(v);
        oh[(size_t)row * D + d] = hv;
        ol[(size_t)row * D + d] = __float2bfloat16(v - __bfloat162float(hv));
    }
}

// ---------------------------------------------------------------------------
// launch orchestration (two forked streams: s1 compute, s2 weight prep)
// ---------------------------------------------------------------------------
extern "C" void kernel_launch(void* const* d_in, const int* in_sizes, int n_in,
                              void* d_out, int out_size) {
    (void)in_sizes; (void)n_in; (void)out_size;
    const int*   x      = (const int*)d_in[0];
    const float* emb    = (const float*)d_in[1];
    const float* Wq     = (const float*)d_in[2];
    const float* Wk     = (const float*)d_in[3];
    const float* Wv     = (const float*)d_in[4];
    const float* Wo     = (const float*)d_in[5];
    const float* bo     = (const float*)d_in[6];
    const float* ln1_w  = (const float*)d_in[7];
    const float* ln1_b  = (const float*)d_in[8];
    const float* W1     = (const float*)d_in[9];
    const float* b1     = (const float*)d_in[10];
    const float* W2     = (const float*)d_in[11];
    const float* b2     = (const float*)d_in[12];
    const float* ln2_w  = (const float*)d_in[13];
    const float* ln2_b  = (const float*)d_in[14];
    const float* fn_w   = (const float*)d_in[15];
    const float* fn_b   = (const float*)d_in[16];
    const float* lmhead = (const float*)d_in[17];
    float* out = (float*)d_out;

    static float* ph = nullptr;
    static __nv_bfloat16 *acth, *actl, *ffh, *ffl, *qh, *ql, *kh, *kl, *vth, *vtl,
                         *qkvTh, *qkvTl, *woTh, *woTl, *w1Th, *w1Tl, *w2Th, *w2Tl,
                         *lmTh, *lmTl;
    static cudaStream_t s1, s2;
    static cudaEvent_t evFork, evW[L], evLM, evDone;
    if (!ph) {
        cudaGetSymbolAddress((void**)&ph,    g_h);
        cudaGetSymbolAddress((void**)&acth,  g_act_h);
        cudaGetSymbolAddress((void**)&actl,  g_act_l);
        cudaGetSymbolAddress((void**)&ffh,   g_ff_h);
        cudaGetSymbolAddress((void**)&ffl,   g_ff_l);
        cudaGetSymbolAddress((void**)&qh,    g_qh);
        cudaGetSymbolAddress((void**)&ql,    g_ql);
        cudaGetSymbolAddress((void**)&kh,    g_kh);
        cudaGetSymbolAddress((void**)&kl,    g_kl);
        cudaGetSymbolAddress((void**)&vth,   g_vth);
        cudaGetSymbolAddress((void**)&vtl,   g_vtl);
        cudaGetSymbolAddress((void**)&qkvTh, g_qkvT_h);
        cudaGetSymbolAddress((void**)&qkvTl, g_qkvT_l);
        cudaGetSymbolAddress((void**)&woTh,  g_woT_h);
        cudaGetSymbolAddress((void**)&woTl,  g_woT_l);
        cudaGetSymbolAddress((void**)&w1Th,  g_w1T_h);
        cudaGetSymbolAddress((void**)&w1Tl,  g_w1T_l);
        cudaGetSymbolAddress((void**)&w2Th,  g_w2T_h);
        cudaGetSymbolAddress((void**)&w2Tl,  g_w2T_l);
        cudaGetSymbolAddress((void**)&lmTh,  g_lmT_h);
        cudaGetSymbolAddress((void**)&lmTl,  g_lmT_l);
        cudaFuncSetAttribute(k_gemm_f32,  cudaFuncAttributeMaxDynamicSharedMemorySize, MG_SMEM);
        cudaFuncSetAttribute(k_gemm_bf16, cudaFuncAttributeMaxDynamicSharedMemorySize, MG_SMEM);
        cudaFuncSetAttribute(k_qkv_gemm,  cudaFuncAttributeMaxDynamicSharedMemorySize, MG_SMEM);
        cudaFuncSetAttribute(k_flash,     cudaFuncAttributeMaxDynamicSharedMemorySize, FA_SMEM);
        cudaStreamCreateWithFlags(&s1, cudaStreamNonBlocking);
        cudaStreamCreateWithFlags(&s2, cudaStreamNonBlocking);
        cudaEventCreateWithFlags(&evFork, cudaEventDisableTiming);
        for (int l = 0; l < L; l++) cudaEventCreateWithFlags(&evW[l], cudaEventDisableTiming);
        cudaEventCreateWithFlags(&evLM, cudaEventDisableTiming);
        cudaEventCreateWithFlags(&evDone, cudaEventDisableTiming);
    }

    // fork
    cudaEventRecord(evFork, 0);
    cudaStreamWaitEvent(s1, evFork, 0);
    cudaStreamWaitEvent(s2, evFork, 0);

    // s2: weight prep, layer order, then LM head
    dim3 gTDD(D / 64, D / 64);
    for (int l = 0; l < L; l++) {
        size_t wo = (size_t)l * D * D;
        size_t qo = (size_t)l * 3 * D * D;
        k_splitT<<<gTDD, 256, 0, s2>>>(Wq + wo, qkvTh + qo,             qkvTl + qo,             D, D);
        k_splitT<<<gTDD, 256, 0, s2>>>(Wk + wo, qkvTh + qo + D * D,     qkvTl + qo + D * D,     D, D);
        k_splitT<<<gTDD, 256, 0, s2>>>(Wv + wo, qkvTh + qo + 2 * D * D, qkvTl + qo + 2 * D * D, D, D);
        k_splitT<<<gTDD, 256, 0, s2>>>(Wo + wo, woTh + wo, woTl + wo, D, D);
        k_splitT<<<dim3(FF / 64, D / 64), 256, 0, s2>>>(W1 + (size_t)l * D * FF,
                                                        w1Th + (size_t)l * FF * D,
                                                        w1Tl + (size_t)l * FF * D, FF, D);
        k_splitT<<<dim3(D / 64, FF / 64), 256, 0, s2>>>(W2 + (size_t)l * FF * D,
                                                        w2Th + (size_t)l * D * FF,
                                                        w2Tl + (size_t)l * D * FF, D, FF);
        cudaEventRecord(evW[l], s2);
    }
    k_splitT<<<dim3(V / 64, D / 64), 256, 0, s2>>>(lmhead, lmTh, lmTl, V, D);
    cudaEventRecord(evLM, s2);

    // s1: compute
    k_embed<<<dim3(D / 256, S), 256, 0, s1>>>(x, emb, ph);

    for (int l = 0; l < L; l++) {
        size_t wo = (size_t)l * D * D;
        size_t qo = (size_t)l * 3 * D * D;
        cudaStreamWaitEvent(s1, evW[l], 0);
        // --- attention ---
        k_ln<<<S, 256, 0, s1>>>(ph, acth, actl, ln1_w + (size_t)l * D, ln1_b + (size_t)l * D);
        k_qkv_gemm<<<dim3(3 * D / 128, S / 128), 256, MG_SMEM, s1>>>(
            acth, actl, qkvTh + qo, qkvTl + qo, qh, ql, kh, kl, vth, vtl);
        k_flash<<<dim3(S / 64, H), 128, FA_SMEM, s1>>>(qh, ql, kh, kl, vth, vtl, acth, actl);
        k_gemm_f32<<<dim3(D / 128, S / 128), 256, MG_SMEM, s1>>>(
            acth, actl, woTh + wo, woTl + wo, bo + (size_t)l * D, ph, ph, D, D);
        // --- FFN ---
        k_ln<<<S, 256, 0, s1>>>(ph, acth, actl, ln2_w + (size_t)l * D, ln2_b + (size_t)l * D);
        k_gemm_bf16<<<dim3(FF / 128, S / 128), 256, MG_SMEM, s1>>>(
            acth, actl, w1Th + (size_t)l * FF * D, w1Tl + (size_t)l * FF * D,
            b1 + (size_t)l * FF, ffh, ffl, D, FF, 1);
        k_gemm_f32<<<dim3(D / 128, S / 128), 256, MG_SMEM, s1>>>(
            ffh, ffl, w2Th + (size_t)l * D * FF, w2Tl + (size_t)l * D * FF,
            b2 + (size_t)l * D, ph, ph, FF, D);
    }

    // final LN + LM head
    cudaStreamWaitEvent(s1, evLM, 0);
    k_ln<<<S, 256, 0, s1>>>(ph, acth, actl, fn_w, fn_b);
    k_gemm_f32<<<dim3(V / 128, S / 128), 256, MG_SMEM, s1>>>(
        acth, actl, lmTh, lmTl, nullptr, nullptr, out, D, V);

    // join
    cudaEventRecord(evDone, s1);
    cudaStreamWaitEvent(0, evDone, 0);
}

// round 6
// speedup vs baseline: 2.7366x; 1.0106x over previous
#include <cuda_runtime.h>
#include <cuda_bf16.h>
#include <math.h>
#include <stdint.h>

#define S 1024
#define D 1024
#define H 16
#define HD 64
#define L 4
#define FF 4096
#define V 32000
#define EPSF 1e-5f

// ---------------------------------------------------------------------------
// device scratch
// ---------------------------------------------------------------------------
__device__ __align__(16) float g_h[S * D];

__device__ __align__(16) __nv_bfloat16 g_act_h[S * FF];
__device__ __align__(16) __nv_bfloat16 g_act_l[S * FF];
__device__ __align__(16) __nv_bfloat16 g_ff_h[S * FF];
__device__ __align__(16) __nv_bfloat16 g_ff_l[S * FF];
__device__ __align__(16) __nv_bfloat16 g_qh[S * D];
__device__ __align__(16) __nv_bfloat16 g_ql[S * D];
__device__ __align__(16) __nv_bfloat16 g_kh[S * D];
__device__ __align__(16) __nv_bfloat16 g_kl[S * D];
__device__ __align__(16) __nv_bfloat16 g_vth[D * S];
__device__ __align__(16) __nv_bfloat16 g_vtl[D * S];

// weights: K-major [K,N] bf16 hi/lo (no transpose!)
__device__ __align__(16) __nv_bfloat16 g_qkv_h[(size_t)L * 3 * D * D];   // [3][D,D] per layer
__device__ __align__(16) __nv_bfloat16 g_qkv_l[(size_t)L * 3 * D * D];
__device__ __align__(16) __nv_bfloat16 g_wo_h[(size_t)L * D * D];
__device__ __align__(16) __nv_bfloat16 g_wo_l[(size_t)L * D * D];
__device__ __align__(16) __nv_bfloat16 g_w1_h[(size_t)L * D * FF];
__device__ __align__(16) __nv_bfloat16 g_w1_l[(size_t)L * D * FF];
__device__ __align__(16) __nv_bfloat16 g_w2_h[(size_t)L * FF * D];
__device__ __align__(16) __nv_bfloat16 g_w2_l[(size_t)L * FF * D];
__device__ __align__(16) __nv_bfloat16 g_lm_h[(size_t)D * V];
__device__ __align__(16) __nv_bfloat16 g_lm_l[(size_t)D * V];

// ---------------------------------------------------------------------------
// PTX helpers (base sm_103-safe)
// ---------------------------------------------------------------------------
__device__ __forceinline__ uint32_t smem_u32(const void* p) {
    uint32_t a;
    asm("{ .reg .u64 t; cvta.to.shared.u64 t, %1; cvt.u32.u64 %0, t; }" : "=r"(a) : "l"(p));
    return a;
}
#define CP16(dst, src) \
    asm volatile("cp.async.cg.shared.global [%0], [%1], 16;" :: "r"(dst), "l"(src))
#define CP_COMMIT() asm volatile("cp.async.commit_group;" ::: "memory")
#define CP_WAIT(n)  asm volatile("cp.async.wait_group %0;" :: "n"(n) : "memory")

__device__ __forceinline__ void ldsm4(uint32_t* r, uint32_t addr) {
    asm volatile("ldmatrix.sync.aligned.m8n8.x4.shared.b16 {%0,%1,%2,%3}, [%4];"
                 : "=r"(r[0]), "=r"(r[1]), "=r"(r[2]), "=r"(r[3]) : "r"(addr));
}
__device__ __forceinline__ void ldsm4t(uint32_t* r, uint32_t addr) {
    asm volatile("ldmatrix.sync.aligned.m8n8.x4.trans.shared.b16 {%0,%1,%2,%3}, [%4];"
                 : "=r"(r[0]), "=r"(r[1]), "=r"(r[2]), "=r"(r[3]) : "r"(addr));
}
__device__ __forceinline__ void mma_bf16(float* d, const uint32_t* a, const uint32_t* b) {
    asm volatile(
        "mma.sync.aligned.m16n8k16.row.col.f32.bf16.bf16.f32 "
        "{%0,%1,%2,%3}, {%4,%5,%6,%7}, {%8,%9}, {%0,%1,%2,%3};"
        : "+f"(d[0]), "+f"(d[1]), "+f"(d[2]), "+f"(d[3])
        : "r"(a[0]), "r"(a[1]), "r"(a[2]), "r"(a[3]), "r"(b[0]), "r"(b[1]));
}
__device__ __forceinline__ uint32_t pack2bf(float a, float b) {
    unsigned short ra = __bfloat16_as_ushort(__float2bfloat16(a));
    unsigned short rb = __bfloat16_as_ushort(__float2bfloat16(b));
    return (uint32_t)ra | ((uint32_t)rb << 16);
}

// ---------------------------------------------------------------------------
// GEMM core: C[M,N] = A[M,K] @ B[K,N]; A row-major hi/lo, B K-major hi/lo.
// 128x128 tile, K-tile 32, 256 thr. Stage: A 16KB | Bh 8KB | Bl 8KB.
// ---------------------------------------------------------------------------
#define MG_SMEM (2 * 32768)

__device__ __forceinline__ void tile_load_A(uint32_t sdst,
                                            const __nv_bfloat16* gh,
                                            const __nv_bfloat16* gl,
                                            int ld, int k0, int tid) {
#pragma unroll
    for (int i = 0; i < 4; i++) {
        int cid = i * 256 + tid;
        int row = cid >> 3, sub = cid & 7;
        const __nv_bfloat16* src =
            ((sub & 4) ? gl : gh) + (size_t)row * ld + k0 + (sub & 3) * 8;
        uint32_t dst = sdst + row * 128 + ((sub ^ (row & 7)) << 4);
        CP16(dst, src);
    }
}

// B tile: [32 k-rows][128 n cols] hi then lo; row pitch 256B; 16 chunks/row,
// swizzle chunk c -> c ^ ((row&7)<<1)
__device__ __forceinline__ void tile_load_B(uint32_t sdst,
                                            const __nv_bfloat16* gh,
                                            const __nv_bfloat16* gl,
                                            int ldb, int bn, int k0, int tid) {
#pragma unroll
    for (int i = 0; i < 4; i++) {
        int cid = i * 256 + tid;           // 0..1023
        int half = cid >> 9;               // 0 = hi, 1 = lo
        int rem = cid & 511;
        int row = rem >> 4, c = rem & 15;
        const __nv_bfloat16* src =
            (half ? gl : gh) + (size_t)(k0 + row) * ldb + bn + c * 8;
        uint32_t dst = sdst + half * 8192 + row * 256 +
                       ((c ^ ((row & 7) << 1)) << 4);
        CP16(dst, src);
    }
}

__device__ __forceinline__ void gemm_core(float (&acc)[4][4][4],
                                          const __nv_bfloat16* Ah, const __nv_bfloat16* Al,
                                          const __nv_bfloat16* Bh, const __nv_bfloat16* Bl,
                                          int K, int ldb, int bm, int bn, char* smem) {
    const int tid = threadIdx.x;
    const int wid = tid >> 5, lane = tid & 31;
    const int wm = (wid >> 2) * 64, wn = (wid & 3) * 32;
    uint32_t sbase = smem_u32(smem);

    const __nv_bfloat16* ah_g = Ah + (size_t)bm * K;
    const __nv_bfloat16* al_g = Al + (size_t)bm * K;

    const int nt = K >> 5;
    tile_load_A(sbase, ah_g, al_g, K, 0, tid);
    tile_load_B(sbase + 16384, Bh, Bl, ldb, bn, 0, tid);
    CP_COMMIT();

    // precomputed B-frag lane address offsets
    const int kr_base = (lane & 7) + ((lane >> 3) & 1) * 8;   // 0..15 within k16
    const int nc8 = (lane >> 4);                               // 0 or 1 (n +8)

    for (int t = 0; t < nt; t++) {
        int b = t & 1;
        if (t + 1 < nt) {
            uint32_t nb = sbase + ((t + 1) & 1) * 32768;
            tile_load_A(nb, ah_g, al_g, K, (t + 1) << 5, tid);
            tile_load_B(nb + 16384, Bh, Bl, ldb, bn, (t + 1) << 5, tid);
            CP_COMMIT();
            CP_WAIT(1);
        } else {
            CP_WAIT(0);
        }
        __syncthreads();

        uint32_t sA = sbase + b * 32768;
        uint32_t sB = sA + 16384;
#pragma unroll
        for (int ks = 0; ks < 2; ks++) {
            uint32_t ahf[4][4], alf[4][4], bhf[2][4], blf[2][4];
#pragma unroll
            for (int f = 0; f < 4; f++) {
                int row = wm + f * 16 + (lane & 15);
                int jc = (lane >> 4) + ks * 2;
                ldsm4(ahf[f], sA + row * 128 + ((jc ^ (row & 7)) << 4));
                ldsm4(alf[f], sA + row * 128 + (((jc + 4) ^ (row & 7)) << 4));
            }
#pragma unroll
            for (int np = 0; np < 2; np++) {
                int krow = ks * 16 + kr_base;
                int ncol = wn + np * 16 + nc8 * 8;
                int c = ncol >> 3;
                uint32_t a = sB + krow * 256 + ((c ^ ((krow & 7) << 1)) << 4);
                ldsm4t(bhf[np], a);
                ldsm4t(blf[np], a + 8192);
            }
#pragma unroll
            for (int m = 0; m < 4; m++)
#pragma unroll
                for (int nf = 0; nf < 4; nf++) {
                    uint32_t* bhp = &bhf[nf >> 1][(nf & 1) * 2];
                    uint32_t* blp = &blf[nf >> 1][(nf & 1) * 2];
                    mma_bf16(acc[m][nf], ahf[m], bhp);
                    mma_bf16(acc[m][nf], ahf[m], blp);
                    mma_bf16(acc[m][nf], alf[m], bhp);
                }
        }
        __syncthreads();
    }
}

// fp32 output (+bias, +res)
__global__ __launch_bounds__(256, 1)
void k_gemm_f32(const __nv_bfloat16* __restrict__ Ah, const __nv_bfloat16* __restrict__ Al,
                const __nv_bfloat16* __restrict__ Bh, const __nv_bfloat16* __restrict__ Bl,
                const float* __restrict__ bias, const float* __restrict__ res,
                float* __restrict__ C, int K, int ldb, int ldc) {
    extern __shared__ char smem[];
    const int tid = threadIdx.x, wid = tid >> 5, lane = tid & 31;
    const int bm = blockIdx.y * 128, bn = blockIdx.x * 128;
    const int wm = (wid >> 2) * 64, wn = (wid & 3) * 32;
    float acc[4][4][4] = {};
    gemm_core(acc, Ah, Al, Bh, Bl, K, ldb, bm, bn, smem);
#pragma unroll
    for (int m = 0; m < 4; m++) {
        int r0 = bm + wm + m * 16 + (lane >> 2);
#pragma unroll
        for (int nf = 0; nf < 4; nf++) {
            int col = bn + wn + nf * 8 + ((lane & 3) << 1);
            float v0 = acc[m][nf][0], v1 = acc[m][nf][1];
            float v2 = acc[m][nf][2], v3 = acc[m][nf][3];
            if (bias) {
                float b0 = bias[col], b1 = bias[col + 1];
                v0 += b0; v1 += b1; v2 += b0; v3 += b1;
            }
            if (res) {
                const float* rr0 = res + (size_t)r0 * ldc + col;
                const float* rr1 = res + (size_t)(r0 + 8) * ldc + col;
                v0 += rr0[0]; v1 += rr0[1]; v2 += rr1[0]; v3 += rr1[1];
            }
            *(float2*)(C + (size_t)r0 * ldc + col) = make_float2(v0, v1);
            *(float2*)(C + (size_t)(r0 + 8) * ldc + col) = make_float2(v2, v3);
        }
    }
}

// bf16 hi/lo output (+bias, relu) — for FFN1
__global__ __launch_bounds__(256, 1)
void k_gemm_bf16(const __nv_bfloat16* __restrict__ Ah, const __nv_bfloat16* __restrict__ Al,
                 const __nv_bfloat16* __restrict__ Bh, const __nv_bfloat16* __restrict__ Bl,
                 const float* __restrict__ bias,
                 __nv_bfloat16* __restrict__ Ch, __nv_bfloat16* __restrict__ Cl,
                 int K, int ldb, int ldc, int relu) {
    extern __shared__ char smem[];
    const int tid = threadIdx.x, wid = tid >> 5, lane = tid & 31;
    const int bm = blockIdx.y * 128, bn = blockIdx.x * 128;
    const int wm = (wid >> 2) * 64, wn = (wid & 3) * 32;
    float acc[4][4][4] = {};
    gemm_core(acc, Ah, Al, Bh, Bl, K, ldb, bm, bn, smem);
#pragma unroll
    for (int m = 0; m < 4; m++) {
        int r0 = bm + wm + m * 16 + (lane >> 2);
#pragma unroll
        for (int nf = 0; nf < 4; nf++) {
            int col = bn + wn + nf * 8 + ((lane & 3) << 1);
            float v[4] = {acc[m][nf][0], acc[m][nf][1], acc[m][nf][2], acc[m][nf][3]};
            if (bias) {
                float b0 = bias[col], b1 = bias[col + 1];
                v[0] += b0; v[1] += b1; v[2] += b0; v[3] += b1;
            }
            if (relu) {
#pragma unroll
                for (int e = 0; e < 4; e++) v[e] = fmaxf(v[e], 0.f);
            }
            float h0 = __bfloat162float(__float2bfloat16(v[0]));
            float h1 = __bfloat162float(__float2bfloat16(v[1]));
            float h2 = __bfloat162float(__float2bfloat16(v[2]));
            float h3 = __bfloat162float(__float2bfloat16(v[3]));
            *(uint32_t*)(Ch + (size_t)r0 * ldc + col) = pack2bf(v[0], v[1]);
            *(uint32_t*)(Ch + (size_t)(r0 + 8) * ldc + col) = pack2bf(v[2], v[3]);
            *(uint32_t*)(Cl + (size_t)r0 * ldc + col) = pack2bf(v[0] - h0, v[1] - h1);
            *(uint32_t*)(Cl + (size_t)(r0 + 8) * ldc + col) = pack2bf(v[2] - h2, v[3] - h3);
        }
    }
}

// QKV gemm: B = [3][D,D] block-concat; cols [0,D)->q, [D,2D)->k, [2D,3D)->vT
__global__ __launch_bounds__(256, 1)
void k_qkv_gemm(const __nv_bfloat16* __restrict__ Ah, const __nv_bfloat16* __restrict__ Al,
                const __nv_bfloat16* __restrict__ Bh, const __nv_bfloat16* __restrict__ Bl,
                __nv_bfloat16* __restrict__ qh, __nv_bfloat16* __restrict__ ql,
                __nv_bfloat16* __restrict__ kh, __nv_bfloat16* __restrict__ kl,
                __nv_bfloat16* __restrict__ vth, __nv_bfloat16* __restrict__ vtl) {
    extern __shared__ char smem[];
    const int tid = threadIdx.x, wid = tid >> 5, lane = tid & 31;
    const int bm = blockIdx.y * 128, bn = blockIdx.x * 128;
    const int wm = (wid >> 2) * 64, wn = (wid & 3) * 32;
    const int widx = bn >> 10;            // which of Wq/Wk/Wv
    const int bn_eff = bn & 1023;
    float acc[4][4][4] = {};
    gemm_core(acc, Ah, Al, Bh + (size_t)widx * D * D, Bl + (size_t)widx * D * D,
              D, D, bm, bn_eff, smem);

    if (widx < 2) {
        __nv_bfloat16* oh = (widx == 0) ? qh : kh;
        __nv_bfloat16* ol = (widx == 0) ? ql : kl;
#pragma unroll
        for (int m = 0; m < 4; m++) {
            int r0 = bm + wm + m * 16 + (lane >> 2);
#pragma unroll
            for (int nf = 0; nf < 4; nf++) {
                int col = bn_eff + wn + nf * 8 + ((lane & 3) << 1);
                float v0 = acc[m][nf][0], v1 = acc[m][nf][1];
                float v2 = acc[m][nf][2], v3 = acc[m][nf][3];
                float h0 = __bfloat162float(__float2bfloat16(v0));
                float h1 = __bfloat162float(__float2bfloat16(v1));
                float h2 = __bfloat162float(__float2bfloat16(v2));
                float h3 = __bfloat162float(__float2bfloat16(v3));
                *(uint32_t*)(oh + (size_t)r0 * D + col) = pack2bf(v0, v1);
                *(uint32_t*)(oh + (size_t)(r0 + 8) * D + col) = pack2bf(v2, v3);
                *(uint32_t*)(ol + (size_t)r0 * D + col) = pack2bf(v0 - h0, v1 - h1);
                *(uint32_t*)(ol + (size_t)(r0 + 8) * D + col) = pack2bf(v2 - h2, v3 - h3);
            }
        }
    } else {
        // stage 128x128 bf16 into smem transposed, write vT [D, S] coalesced
        __nv_bfloat16* sv = (__nv_bfloat16*)smem;   // [col][row], row-stride 136 halves
#pragma unroll
        for (int part = 0; part < 2; part++) {
#pragma unroll
            for (int m = 0; m < 4; m++) {
#pragma unroll
                for (int nf = 0; nf < 4; nf++) {
#pragma unroll
                    for (int e = 0; e < 4; e++) {
                        int rl = wm + m * 16 + (lane >> 2) + ((e >> 1) ? 8 : 0);
                        int cl = wn + nf * 8 + ((lane & 3) << 1) + (e & 1);
                        float v = acc[m][nf][e];
                        float hv = __bfloat162float(__float2bfloat16(v));
                        sv[cl * 136 + rl] = __float2bfloat16(part ? (v - hv) : v);
                    }
                }
            }
            __syncthreads();
            int col = tid >> 1, half = tid & 1;
            const uint4* src = (const uint4*)(smem + col * 272 + half * 128);
            __nv_bfloat16* dst = (part ? vtl : vth) +
                                 (size_t)(bn_eff + col) * S + bm + half * 64;
#pragma unroll
            for (int j = 0; j < 8; j++) ((uint4*)dst)[j] = src[j];
            __syncthreads();
        }
    }
}

// ---------------------------------------------------------------------------
// flash attention: CTA = (qblock 64, head), 128 thr (4 warps)
// ---------------------------------------------------------------------------
#define FA_SMEM (16384 + 2 * 32768)

__device__ __forceinline__ void fa_load(uint32_t sdst, const __nv_bfloat16* g,
                                        int ld, int tid) {
#pragma unroll
    for (int i = 0; i < 4; i++) {
        int cid = i * 128 + tid;
        int row = cid >> 3, c = cid & 7;
        CP16(sdst + row * 128 + ((c ^ (row & 7)) << 4), g + (size_t)row * ld + c * 8);
    }
}

__global__ __launch_bounds__(128)
void k_flash(const __nv_bfloat16* __restrict__ qh, const __nv_bfloat16* __restrict__ ql,
             const __nv_bfloat16* __restrict__ kh, const __nv_bfloat16* __restrict__ kl,
             const __nv_bfloat16* __restrict__ vth, const __nv_bfloat16* __restrict__ vtl,
             __nv_bfloat16* __restrict__ oh, __nv_bfloat16* __restrict__ ol) {
    extern __shared__ char smem[];
    uint32_t sb = smem_u32(smem);
    const int tid = threadIdx.x, w = tid >> 5, lane = tid & 31;
    const int qb = gridDim.x - 1 - blockIdx.x;
    const int hh = blockIdx.y;

    fa_load(sb,        qh + (size_t)(qb * 64) * D + hh * 64, D, tid);
    fa_load(sb + 8192, ql + (size_t)(qb * 64) * D + hh * 64, D, tid);
    {
        uint32_t st = sb + 16384;
        fa_load(st,         kh + (size_t)0 * D + hh * 64, D, tid);
        fa_load(st + 8192,  kl + (size_t)0 * D + hh * 64, D, tid);
        fa_load(st + 16384, vth + (size_t)(hh * 64) * S, S, tid);
        fa_load(st + 24576, vtl + (size_t)(hh * 64) * S, S, tid);
    }
    CP_COMMIT();

    uint32_t qhf[4][4], qlf[4][4];
    float o_acc[8][4] = {};
    float m0 = -1e30f, m1 = -1e30f, l0 = 0.f, l1 = 0.f;

    for (int kb = 0; kb <= qb; kb++) {
        if (kb + 1 <= qb) {
            uint32_t st = sb + 16384 + ((kb + 1) & 1) * 32768;
            fa_load(st,         kh + (size_t)((kb + 1) * 64) * D + hh * 64, D, tid);
            fa_load(st + 8192,  kl + (size_t)((kb + 1) * 64) * D + hh * 64, D, tid);
            fa_load(st + 16384, vth + (size_t)(hh * 64) * S + (kb + 1) * 64, S, tid);
            fa_load(st + 24576, vtl + (size_t)(hh * 64) * S + (kb + 1) * 64, S, tid);
            CP_COMMIT();
            CP_WAIT(1);
        } else {
            CP_WAIT(0);
        }
        __syncthreads();

        if (kb == 0) {
#pragma unroll
            for (int f = 0; f < 4; f++) {
                int row = w * 16 + (lane & 15);
                int jc = (lane >> 4) + f * 2;
                ldsm4(qhf[f], sb + row * 128 + ((jc ^ (row & 7)) << 4));
                ldsm4(qlf[f], sb + 8192 + row * 128 + ((jc ^ (row & 7)) << 4));
            }
        }

        uint32_t st = sb + 16384 + (kb & 1) * 32768;
        float s_acc[8][4] = {};
#pragma unroll
        for (int ks = 0; ks < 4; ks++) {
            uint32_t bh4[4][4], bl4[4][4];
#pragma unroll
            for (int np = 0; np < 4; np++) {
                int row = np * 16 + ((lane >> 4) << 3) + (lane & 7);
                int jc = ((lane >> 3) & 1) + ks * 2;
                ldsm4(bh4[np], st + row * 128 + ((jc ^ (row & 7)) << 4));
                ldsm4(bl4[np], st + 8192 + row * 128 + ((jc ^ (row & 7)) << 4));
            }
#pragma unroll
            for (int nf = 0; nf < 8; nf++) {
                uint32_t* bh = &bh4[nf >> 1][(nf & 1) * 2];
                uint32_t* bl = &bl4[nf >> 1][(nf & 1) * 2];
                mma_bf16(s_acc[nf], qhf[ks], bh);
                mma_bf16(s_acc[nf], qhf[ks], bl);
                mma_bf16(s_acc[nf], qlf[ks], bh);
            }
        }
        int r_lo = qb * 64 + w * 16 + (lane >> 2);
#pragma unroll
        for (int nf = 0; nf < 8; nf++)
#pragma unroll
            for (int e = 0; e < 4; e++) {
                float v = s_acc[nf][e] * 0.125f;
                if (kb == qb) {
                    int key = kb * 64 + nf * 8 + ((lane & 3) << 1) + (e & 1);
                    int qr = r_lo + ((e >> 1) ? 8 : 0);
                    if (key > qr) v = -1e30f;
                }
                s_acc[nf][e] = v;
            }
        float mx0 = -1e30f, mx1 = -1e30f;
#pragma unroll
        for (int nf = 0; nf < 8; nf++) {
            mx0 = fmaxf(mx0, fmaxf(s_acc[nf][0], s_acc[nf][1]));
            mx1 = fmaxf(mx1, fmaxf(s_acc[nf][2], s_acc[nf][3]));
        }
        mx0 = fmaxf(mx0, __shfl_xor_sync(0xffffffffu, mx0, 1));
        mx0 = fmaxf(mx0, __shfl_xor_sync(0xffffffffu, mx0, 2));
        mx1 = fmaxf(mx1, __shfl_xor_sync(0xffffffffu, mx1, 1));
        mx1 = fmaxf(mx1, __shfl_xor_sync(0xffffffffu, mx1, 2));
        float mn0 = fmaxf(m0, mx0), mn1 = fmaxf(m1, mx1);
        float a0 = __expf(m0 - mn0), a1 = __expf(m1 - mn1);
        float sum0 = 0.f, sum1 = 0.f;
#pragma unroll
        for (int nf = 0; nf < 8; nf++) {
            s_acc[nf][0] = __expf(s_acc[nf][0] - mn0);
            s_acc[nf][1] = __expf(s_acc[nf][1] - mn0);
            s_acc[nf][2] = __expf(s_acc[nf][2] - mn1);
            s_acc[nf][3] = __expf(s_acc[nf][3] - mn1);
            sum0 += s_acc[nf][0] + s_acc[nf][1];
            sum1 += s_acc[nf][2] + s_acc[nf][3];
        }
        sum0 += __shfl_xor_sync(0xffffffffu, sum0, 1);
        sum0 += __shfl_xor_sync(0xffffffffu, sum0, 2);
        sum1 += __shfl_xor_sync(0xffffffffu, sum1, 1);
        sum1 += __shfl_xor_sync(0xffffffffu, sum1, 2);
        l0 = l0 * a0 + sum0;
        l1 = l1 * a1 + sum1;
        m0 = mn0; m1 = mn1;
#pragma unroll
        for (int nf = 0; nf < 8; nf++) {
            o_acc[nf][0] *= a0; o_acc[nf][1] *= a0;
            o_acc[nf][2] *= a1; o_acc[nf][3] *= a1;
        }
        uint32_t pph[4][4], ppl[4][4];
#pragma unroll
        for (int g = 0; g < 4; g++) {
            float c0 = s_acc[2 * g][0], c1 = s_acc[2 * g][1];
            float c2 = s_acc[2 * g][2], c3 = s_acc[2 * g][3];
            float d0 = s_acc[2 * g + 1][0], d1 = s_acc[2 * g + 1][1];
            float d2 = s_acc[2 * g + 1][2], d3 = s_acc[2 * g + 1][3];
            pph[g][0] = pack2bf(c0, c1); pph[g][1] = pack2bf(c2, c3);
            pph[g][2] = pack2bf(d0, d1); pph[g][3] = pack2bf(d2, d3);
            ppl[g][0] = pack2bf(c0 - __bfloat162float(__float2bfloat16(c0)),
                                c1 - __bfloat162float(__float2bfloat16(c1)));
            ppl[g][1] = pack2bf(c2 - __bfloat162float(__float2bfloat16(c2)),
                                c3 - __bfloat162float(__float2bfloat16(c3)));
            ppl[g][2] = pack2bf(d0 - __bfloat162float(__float2bfloat16(d0)),
                                d1 - __bfloat162float(__float2bfloat16(d1)));
            ppl[g][3] = pack2bf(d2 - __bfloat162float(__float2bfloat16(d2)),
                                d3 - __bfloat162float(__float2bfloat16(d3)));
        }
        uint32_t sv = st + 16384;
#pragma unroll
        for (int ks = 0; ks < 4; ks++) {
            uint32_t bh4[4][4], bl4[4][4];
#pragma unroll
            for (int np = 0; np < 4; np++) {
                int row = np * 16 + ((lane >> 4) << 3) + (lane & 7);
                int jc = ((lane >> 3) & 1) + ks * 2;
                ldsm4(bh4[np], sv + row * 128 + ((jc ^ (row & 7)) << 4));
                ldsm4(bl4[np], sv + 8192 + row * 128 + ((jc ^ (row & 7)) << 4));
            }
#pragma unroll
            for (int nf = 0; nf < 8; nf++) {
                uint32_t* bh = &bh4[nf >> 1][(nf & 1) * 2];
                uint32_t* bl = &bl4[nf >> 1][(nf & 1) * 2];
                mma_bf16(o_acc[nf], pph[ks], bh);
                mma_bf16(o_acc[nf], ppl[ks], bh);
                mma_bf16(o_acc[nf], pph[ks], bl);
            }
        }
        __syncthreads();
    }

    float inv0 = 1.f / l0, inv1 = 1.f / l1;
    int row0 = qb * 64 + w * 16 + (lane >> 2);
#pragma unroll
    for (int nf = 0; nf < 8; nf++) {
        int col = hh * 64 + nf * 8 + ((lane & 3) << 1);
        float v0 = o_acc[nf][0] * inv0, v1 = o_acc[nf][1] * inv0;
        float v2 = o_acc[nf][2] * inv1, v3 = o_acc[nf][3] * inv1;
        float h0 = __bfloat162float(__float2bfloat16(v0));
        float h1 = __bfloat162float(__float2bfloat16(v1));
        float h2 = __bfloat162float(__float2bfloat16(v2));
        float h3 = __bfloat162float(__float2bfloat16(v3));
        *(uint32_t*)(oh + (size_t)row0 * D + col) = pack2bf(v0, v1);
        *(uint32_t*)(oh + (size_t)(row0 + 8) * D + col) = pack2bf(v2, v3);
        *(uint32_t*)(ol + (size_t)row0 * D + col) = pack2bf(v0 - h0, v1 - h1);
        *(uint32_t*)(ol + (size_t)(row0 + 8) * D + col) = pack2bf(v2 - h2, v3 - h3);
    }
}

// ---------------------------------------------------------------------------
// flat weight split: fp32 [K,N] -> bf16 hi/lo [K,N], 8 elems/thread, streaming
// n must be divisible by 2048 (grid = n/2048)
// ---------------------------------------------------------------------------
__global__ __launch_bounds__(256) void k_split_flat(const float* __restrict__ W,
                                                    __nv_bfloat16* __restrict__ th,
                                                    __nv_bfloat16* __restrict__ tl) {
    size_t gid = (size_t)blockIdx.x * 256 + threadIdx.x;
    float4 a = ((const float4*)W)[2 * gid];
    float4 b = ((const float4*)W)[2 * gid + 1];
    uint4 uh, ul;
    uh.x = pack2bf(a.x, a.y); uh.y = pack2bf(a.z, a.w);
    uh.z = pack2bf(b.x, b.y); uh.w = pack2bf(b.z, b.w);
    ul.x = pack2bf(a.x - __bfloat162float(__float2bfloat16(a.x)),
                   a.y - __bfloat162float(__float2bfloat16(a.y)));
    ul.y = pack2bf(a.z - __bfloat162float(__float2bfloat16(a.z)),
                   a.w - __bfloat162float(__float2bfloat16(a.w)));
    ul.z = pack2bf(b.x - __bfloat162float(__float2bfloat16(b.x)),
                   b.y - __bfloat162float(__float2bfloat16(b.y)));
    ul.w = pack2bf(b.z - __bfloat162float(__float2bfloat16(b.z)),
                   b.w - __bfloat162float(__float2bfloat16(b.w)));
    ((uint4*)th)[gid] = uh;
    ((uint4*)tl)[gid] = ul;
}

// ---------------------------------------------------------------------------
// embedding + positional encoding
// ---------------------------------------------------------------------------
__global__ __launch_bounds__(256) void k_embed(const int* __restrict__ x,
                                               const float* __restrict__ emb,
                                               float* __restrict__ h) {
    int s = blockIdx.y;
    int d = blockIdx.x * 256 + threadIdx.x;
    int tok = x[s];
    float e = emb[(size_t)tok * D + d];
    int i2 = d & ~1;
    float freq = expf((float)i2 * (-9.210340371976184f / (float)D));
    float ang = (float)s * freq;
    float pe = (d & 1) ? cosf(ang) : sinf(ang);
    h[(size_t)s * D + d] = e + pe;
}

// ---------------------------------------------------------------------------
// layernorm -> bf16 hi/lo
// ---------------------------------------------------------------------------
__global__ __launch_bounds__(256) void k_ln(const float* __restrict__ in,
                                            __nv_bfloat16* __restrict__ oh,
                                            __nv_bfloat16* __restrict__ ol,
                                            const float* __restrict__ w,
                                            const float* __restrict__ b) {
    int row = blockIdx.x;
    const float* xr = in + (size_t)row * D;
    int t = threadIdx.x;
    __shared__ float sh1[256];
    __shared__ float sh2[256];
    float s1 = 0.f, s2 = 0.f;
    for (int d = t; d < D; d += 256) {
        float v = xr[d];
        s1 += v; s2 += v * v;
    }
    sh1[t] = s1; sh2[t] = s2;
    __syncthreads();
    for (int o = 128; o > 0; o >>= 1) {
        if (t < o) { sh1[t] += sh1[t + o]; sh2[t] += sh2[t + o]; }
        __syncthreads();
    }
    float mean = sh1[0] * (1.0f / D);
    float var = sh2[0] * (1.0f / D) - mean * mean;
    float rstd = rsqrtf(var + EPSF);
    for (int d = t; d < D; d += 256) {
        float v = (xr[d] - mean) * rstd * w[d] + b[d];
        __nv_bfloat16 hv = __float2bfloat16(v);
        oh[(size_t)row * D + d] = hv;
        ol[(size_t)row * D + d] = __float2bfloat16(v - __bfloat162float(hv));
    }
}

// ---------------------------------------------------------------------------
// launch orchestration (s1 compute, s2 weight prep)
// ---------------------------------------------------------------------------
extern "C" void kernel_launch(void* const* d_in, const int* in_sizes, int n_in,
                              void* d_out, int out_size) {
    (void)in_sizes; (void)n_in; (void)out_size;
    const int*   x      = (const int*)d_in[0];
    const float* emb    = (const float*)d_in[1];
    const float* Wq     = (const float*)d_in[2];
    const float* Wk     = (const float*)d_in[3];
    const float* Wv     = (const float*)d_in[4];
    const float* Wo     = (const float*)d_in[5];
    const float* bo     = (const float*)d_in[6];
    const float* ln1_w  = (const float*)d_in[7];
    const float* ln1_b  = (const float*)d_in[8];
    const float* W1     = (const float*)d_in[9];
    const float* b1     = (const float*)d_in[10];
    const float* W2     = (const float*)d_in[11];
    const float* b2     = (const float*)d_in[12];
    const float* ln2_w  = (const float*)d_in[13];
    const float* ln2_b  = (const float*)d_in[14];
    const float* fn_w   = (const float*)d_in[15];
    const float* fn_b   = (const float*)d_in[16];
    const float* lmhead = (const float*)d_in[17];
    float* out = (float*)d_out;

    static float* ph = nullptr;
    static __nv_bfloat16 *acth, *actl, *ffh, *ffl, *qh, *ql, *kh, *kl, *vth, *vtl,
                         *qkvh, *qkvl, *woh, *wol, *w1h, *w1l, *w2h, *w2l, *lmh, *lml;
    static cudaStream_t s1, s2;
    static cudaEvent_t evFork, evW[L], evLM, evDone;
    if (!ph) {
        cudaGetSymbolAddress((void**)&ph,   g_h);
        cudaGetSymbolAddress((void**)&acth, g_act_h);
        cudaGetSymbolAddress((void**)&actl, g_act_l);
        cudaGetSymbolAddress((void**)&ffh,  g_ff_h);
        cudaGetSymbolAddress((void**)&ffl,  g_ff_l);
        cudaGetSymbolAddress((void**)&qh,   g_qh);
        cudaGetSymbolAddress((void**)&ql,   g_ql);
        cudaGetSymbolAddress((void**)&kh,   g_kh);
        cudaGetSymbolAddress((void**)&kl,   g_kl);
        cudaGetSymbolAddress((void**)&vth,  g_vth);
        cudaGetSymbolAddress((void**)&vtl,  g_vtl);
        cudaGetSymbolAddress((void**)&qkvh, g_qkv_h);
        cudaGetSymbolAddress((void**)&qkvl, g_qkv_l);
        cudaGetSymbolAddress((void**)&woh,  g_wo_h);
        cudaGetSymbolAddress((void**)&wol,  g_wo_l);
        cudaGetSymbolAddress((void**)&w1h,  g_w1_h);
        cudaGetSymbolAddress((void**)&w1l,  g_w1_l);
        cudaGetSymbolAddress((void**)&w2h,  g_w2_h);
        cudaGetSymbolAddress((void**)&w2l,  g_w2_l);
        cudaGetSymbolAddress((void**)&lmh,  g_lm_h);
        cudaGetSymbolAddress((void**)&lml,  g_lm_l);
        cudaFuncSetAttribute(k_gemm_f32,  cudaFuncAttributeMaxDynamicSharedMemorySize, MG_SMEM);
        cudaFuncSetAttribute(k_gemm_bf16, cudaFuncAttributeMaxDynamicSharedMemorySize, MG_SMEM);
        cudaFuncSetAttribute(k_qkv_gemm,  cudaFuncAttributeMaxDynamicSharedMemorySize, MG_SMEM);
        cudaFuncSetAttribute(k_flash,     cudaFuncAttributeMaxDynamicSharedMemorySize, FA_SMEM);
        cudaStreamCreateWithFlags(&s1, cudaStreamNonBlocking);
        cudaStreamCreateWithFlags(&s2, cudaStreamNonBlocking);
        cudaEventCreateWithFlags(&evFork, cudaEventDisableTiming);
        for (int l = 0; l < L; l++) cudaEventCreateWithFlags(&evW[l], cudaEventDisableTiming);
        cudaEventCreateWithFlags(&evLM, cudaEventDisableTiming);
        cudaEventCreateWithFlags(&evDone, cudaEventDisableTiming);
    }

    // fork
    cudaEventRecord(evFork, 0);
    cudaStreamWaitEvent(s1, evFork, 0);
    cudaStreamWaitEvent(s2, evFork, 0);

    // s2: weight prep (flat streaming splits; no transpose)
    const int gDD = D * D / 2048;       // 512
    const int gDF = D * FF / 2048;      // 2048
    for (int l = 0; l < L; l++) {
        size_t wo = (size_t)l * D * D;
        size_t qo = (size_t)l * 3 * D * D;
        k_split_flat<<<gDD, 256, 0, s2>>>(Wq + wo, qkvh + qo,             qkvl + qo);
        k_split_flat<<<gDD, 256, 0, s2>>>(Wk + wo, qkvh + qo + D * D,     qkvl + qo + D * D);
        k_split_flat<<<gDD, 256, 0, s2>>>(Wv + wo, qkvh + qo + 2 * D * D, qkvl + qo + 2 * D * D);
        k_split_flat<<<gDD, 256, 0, s2>>>(Wo + wo, woh + wo, wol + wo);
        k_split_flat<<<gDF, 256, 0, s2>>>(W1 + (size_t)l * D * FF,
                                          w1h + (size_t)l * D * FF, w1l + (size_t)l * D * FF);
        k_split_flat<<<gDF, 256, 0, s2>>>(W2 + (size_t)l * FF * D,
                                          w2h + (size_t)l * FF * D, w2l + (size_t)l * FF * D);
        cudaEventRecord(evW[l], s2);
    }
    k_split_flat<<<(int)((size_t)D * V / 2048), 256, 0, s2>>>(lmhead, lmh, lml);
    cudaEventRecord(evLM, s2);

    // s1: compute
    k_embed<<<dim3(D / 256, S), 256, 0, s1>>>(x, emb, ph);

    for (int l = 0; l < L; l++) {
        size_t wo = (size_t)l * D * D;
        size_t qo = (size_t)l * 3 * D * D;
        cudaStreamWaitEvent(s1, evW[l], 0);
        // --- attention ---
        k_ln<<<S, 256, 0, s1>>>(ph, acth, actl, ln1_w + (size_t)l * D, ln1_b + (size_t)l * D);
        k_qkv_gemm<<<dim3(3 * D / 128, S / 128), 256, MG_SMEM, s1>>>(
            acth, actl, qkvh + qo, qkvl + qo, qh, ql, kh, kl, vth, vtl);
        k_flash<<<dim3(S / 64, H), 128, FA_SMEM, s1>>>(qh, ql, kh, kl, vth, vtl, acth, actl);
        k_gemm_f32<<<dim3(D / 128, S / 128), 256, MG_SMEM, s1>>>(
            acth, actl, woh + wo, wol + wo, bo + (size_t)l * D, ph, ph, D, D, D);
        // --- FFN ---
        k_ln<<<S, 256, 0, s1>>>(ph, acth, actl, ln2_w + (size_t)l * D, ln2_b + (size_t)l * D);
        k_gemm_bf16<<<dim3(FF / 128, S / 128), 256, MG_SMEM, s1>>>(
            acth, actl, w1h + (size_t)l * D * FF, w1l + (size_t)l * D * FF,
            b1 + (size_t)l * FF, ffh, ffl, D, FF, FF, 1);
        k_gemm_f32<<<dim3(D / 128, S / 128), 256, MG_SMEM, s1>>>(
            ffh, ffl, w2h + (size_t)l * FF * D, w2l + (size_t)l * FF * D,
            b2 + (size_t)l * D, ph, ph, FF, D, D);
    }

    // final LN + LM head
    cudaStreamWaitEvent(s1, evLM, 0);
    k_ln<<<S, 256, 0, s1>>>(ph, acth, actl, fn_w, fn_b);
    k_gemm_f32<<<dim3(V / 128, S / 128), 256, MG_SMEM, s1>>>(
        acth, actl, lmh, lml, nullptr, nullptr, out, D, V, V);

    // join
    cudaEventRecord(evDone, s1);
    cudaStreamWaitEvent(0, evDone, 0);
}

// round 7
// speedup vs baseline: 3.3392x; 1.2202x over previous
#include <cuda_runtime.h>
#include <cuda_bf16.h>
#include <math.h>
#include <stdint.h>

#define S 1024
#define D 1024
#define H 16
#define HD 64
#define L 4
#define FF 4096
#define V 32000
#define EPSF 1e-5f

// ---------------------------------------------------------------------------
// device scratch
// ---------------------------------------------------------------------------
__device__ __align__(16) float g_h[S * D];

__device__ __align__(16) __nv_bfloat16 g_act_h[S * FF];
__device__ __align__(16) __nv_bfloat16 g_act_l[S * FF];
__device__ __align__(16) __nv_bfloat16 g_ff_h[S * FF];
__device__ __align__(16) __nv_bfloat16 g_ff_l[S * FF];
__device__ __align__(16) __nv_bfloat16 g_qh[S * D];
__device__ __align__(16) __nv_bfloat16 g_ql[S * D];
__device__ __align__(16) __nv_bfloat16 g_kh[S * D];
__device__ __align__(16) __nv_bfloat16 g_kl[S * D];
__device__ __align__(16) __nv_bfloat16 g_vth[D * S];
__device__ __align__(16) __nv_bfloat16 g_vtl[D * S];

// weights: K-major [K,N] bf16 hi/lo
__device__ __align__(16) __nv_bfloat16 g_qkv_h[(size_t)L * 3 * D * D];
__device__ __align__(16) __nv_bfloat16 g_qkv_l[(size_t)L * 3 * D * D];
__device__ __align__(16) __nv_bfloat16 g_wo_h[(size_t)L * D * D];
__device__ __align__(16) __nv_bfloat16 g_wo_l[(size_t)L * D * D];
__device__ __align__(16) __nv_bfloat16 g_w1_h[(size_t)L * D * FF];
__device__ __align__(16) __nv_bfloat16 g_w1_l[(size_t)L * D * FF];
__device__ __align__(16) __nv_bfloat16 g_w2_h[(size_t)L * FF * D];
__device__ __align__(16) __nv_bfloat16 g_w2_l[(size_t)L * FF * D];
__device__ __align__(16) __nv_bfloat16 g_lm_h[(size_t)D * V];
__device__ __align__(16) __nv_bfloat16 g_lm_l[(size_t)D * V];

// ---------------------------------------------------------------------------
// PTX helpers
// ---------------------------------------------------------------------------
__device__ __forceinline__ uint32_t smem_u32(const void* p) {
    uint32_t a;
    asm("{ .reg .u64 t; cvta.to.shared.u64 t, %1; cvt.u32.u64 %0, t; }" : "=r"(a) : "l"(p));
    return a;
}
#define CP16(dst, src) \
    asm volatile("cp.async.cg.shared.global [%0], [%1], 16;" :: "r"(dst), "l"(src))
#define CP_COMMIT() asm volatile("cp.async.commit_group;" ::: "memory")
#define CP_WAIT(n)  asm volatile("cp.async.wait_group %0;" :: "n"(n) : "memory")

__device__ __forceinline__ void ldsm4(uint32_t* r, uint32_t addr) {
    asm volatile("ldmatrix.sync.aligned.m8n8.x4.shared.b16 {%0,%1,%2,%3}, [%4];"
                 : "=r"(r[0]), "=r"(r[1]), "=r"(r[2]), "=r"(r[3]) : "r"(addr));
}
__device__ __forceinline__ void ldsm4t(uint32_t* r, uint32_t addr) {
    asm volatile("ldmatrix.sync.aligned.m8n8.x4.trans.shared.b16 {%0,%1,%2,%3}, [%4];"
                 : "=r"(r[0]), "=r"(r[1]), "=r"(r[2]), "=r"(r[3]) : "r"(addr));
}
__device__ __forceinline__ void mma_bf16(float* d, const uint32_t* a, const uint32_t* b) {
    asm volatile(
        "mma.sync.aligned.m16n8k16.row.col.f32.bf16.bf16.f32 "
        "{%0,%1,%2,%3}, {%4,%5,%6,%7}, {%8,%9}, {%0,%1,%2,%3};"
        : "+f"(d[0]), "+f"(d[1]), "+f"(d[2]), "+f"(d[3])
        : "r"(a[0]), "r"(a[1]), "r"(a[2]), "r"(a[3]), "r"(b[0]), "r"(b[1]));
}
__device__ __forceinline__ uint32_t pack2bf(float a, float b) {
    unsigned short ra = __bfloat16_as_ushort(__float2bfloat16(a));
    unsigned short rb = __bfloat16_as_ushort(__float2bfloat16(b));
    return (uint32_t)ra | ((uint32_t)rb << 16);
}

// ---------------------------------------------------------------------------
// GEMM cores. A row-major hi/lo [M,K]; B K-major hi/lo [K,N].
// 128-wide-N core: tile 128x128, stage = A 16KB | Bh 8KB | Bl 8KB (32KB)
// 64-wide-N core : tile 128x64,  stage = A 16KB | Bh 4KB | Bl 4KB (24KB)
// ---------------------------------------------------------------------------
#define MG_SMEM (2 * 32768)
#define MG64_SMEM (2 * 24576)

__device__ __forceinline__ void tile_load_A(uint32_t sdst,
                                            const __nv_bfloat16* gh,
                                            const __nv_bfloat16* gl,
                                            int ld, int k0, int tid) {
#pragma unroll
    for (int i = 0; i < 4; i++) {
        int cid = i * 256 + tid;
        int row = cid >> 3, sub = cid & 7;
        const __nv_bfloat16* src =
            ((sub & 4) ? gl : gh) + (size_t)row * ld + k0 + (sub & 3) * 8;
        uint32_t dst = sdst + row * 128 + ((sub ^ (row & 7)) << 4);
        CP16(dst, src);
    }
}

__device__ __forceinline__ void tile_load_B(uint32_t sdst,
                                            const __nv_bfloat16* gh,
                                            const __nv_bfloat16* gl,
                                            int ldb, int bn, int k0, int tid) {
#pragma unroll
    for (int i = 0; i < 4; i++) {
        int cid = i * 256 + tid;
        int half = cid >> 9;
        int rem = cid & 511;
        int row = rem >> 4, c = rem & 15;
        const __nv_bfloat16* src =
            (half ? gl : gh) + (size_t)(k0 + row) * ldb + bn + c * 8;
        uint32_t dst = sdst + half * 8192 + row * 256 +
                       ((c ^ ((row & 7) << 1)) << 4);
        CP16(dst, src);
    }
}

// B tile 32x64: row pitch 128B, 8 chunks/row, swizzle c ^ (row&7)
__device__ __forceinline__ void tile_load_B64(uint32_t sdst,
                                              const __nv_bfloat16* gh,
                                              const __nv_bfloat16* gl,
                                              int ldb, int bn, int k0, int tid) {
#pragma unroll
    for (int i = 0; i < 2; i++) {
        int cid = i * 256 + tid;           // 0..511
        int half = cid >> 8;
        int rem = cid & 255;
        int row = rem >> 3, c = rem & 7;
        const __nv_bfloat16* src =
            (half ? gl : gh) + (size_t)(k0 + row) * ldb + bn + c * 8;
        uint32_t dst = sdst + half * 4096 + row * 128 + ((c ^ (row & 7)) << 4);
        CP16(dst, src);
    }
}

// register-lean core: A-fragments processed in two chunks of 2 m-frags
__device__ __forceinline__ void gemm_core(float (&acc)[4][4][4],
                                          const __nv_bfloat16* Ah, const __nv_bfloat16* Al,
                                          const __nv_bfloat16* Bh, const __nv_bfloat16* Bl,
                                          int K, int ldb, int bm, int bn, char* smem) {
    const int tid = threadIdx.x;
    const int wid = tid >> 5, lane = tid & 31;
    const int wm = (wid >> 2) * 64, wn = (wid & 3) * 32;
    uint32_t sbase = smem_u32(smem);

    const __nv_bfloat16* ah_g = Ah + (size_t)bm * K;
    const __nv_bfloat16* al_g = Al + (size_t)bm * K;

    const int nt = K >> 5;
    tile_load_A(sbase, ah_g, al_g, K, 0, tid);
    tile_load_B(sbase + 16384, Bh, Bl, ldb, bn, 0, tid);
    CP_COMMIT();

    const int kr_base = (lane & 7) + ((lane >> 3) & 1) * 8;
    const int nc8 = (lane >> 4);

    for (int t = 0; t < nt; t++) {
        int b = t & 1;
        if (t + 1 < nt) {
            uint32_t nb = sbase + ((t + 1) & 1) * 32768;
            tile_load_A(nb, ah_g, al_g, K, (t + 1) << 5, tid);
            tile_load_B(nb + 16384, Bh, Bl, ldb, bn, (t + 1) << 5, tid);
            CP_COMMIT();
            CP_WAIT(1);
        } else {
            CP_WAIT(0);
        }
        __syncthreads();

        uint32_t sA = sbase + b * 32768;
        uint32_t sB = sA + 16384;
#pragma unroll
        for (int ks = 0; ks < 2; ks++) {
            uint32_t bhf[2][4], blf[2][4];
#pragma unroll
            for (int np = 0; np < 2; np++) {
                int krow = ks * 16 + kr_base;
                int ncol = wn + np * 16 + nc8 * 8;
                int c = ncol >> 3;
                uint32_t a = sB + krow * 256 + ((c ^ ((krow & 7) << 1)) << 4);
                ldsm4t(bhf[np], a);
                ldsm4t(blf[np], a + 8192);
            }
#pragma unroll
            for (int mp = 0; mp < 2; mp++) {
                uint32_t ahf[2][4], alf[2][4];
#pragma unroll
                for (int f2 = 0; f2 < 2; f2++) {
                    int row = wm + (mp * 2 + f2) * 16 + (lane & 15);
                    int jc = (lane >> 4) + ks * 2;
                    ldsm4(ahf[f2], sA + row * 128 + ((jc ^ (row & 7)) << 4));
                    ldsm4(alf[f2], sA + row * 128 + (((jc + 4) ^ (row & 7)) << 4));
                }
#pragma unroll
                for (int m2 = 0; m2 < 2; m2++)
#pragma unroll
                    for (int nf = 0; nf < 4; nf++) {
                        uint32_t* bhp = &bhf[nf >> 1][(nf & 1) * 2];
                        uint32_t* blp = &blf[nf >> 1][(nf & 1) * 2];
                        float* ac = acc[mp * 2 + m2][nf];
                        mma_bf16(ac, ahf[m2], bhp);
                        mma_bf16(ac, ahf[m2], blp);
                        mma_bf16(ac, alf[m2], bhp);
                    }
            }
        }
        __syncthreads();
    }
}

// 128x64 core: warps 4m x 2n, warp tile 32x32
__device__ __forceinline__ void gemm_core64(float (&acc)[2][4][4],
                                            const __nv_bfloat16* Ah, const __nv_bfloat16* Al,
                                            const __nv_bfloat16* Bh, const __nv_bfloat16* Bl,
                                            int K, int ldb, int bm, int bn, char* smem) {
    const int tid = threadIdx.x;
    const int wid = tid >> 5, lane = tid & 31;
    const int wm = (wid >> 1) * 32, wn = (wid & 1) * 32;
    uint32_t sbase = smem_u32(smem);

    const __nv_bfloat16* ah_g = Ah + (size_t)bm * K;
    const __nv_bfloat16* al_g = Al + (size_t)bm * K;

    const int nt = K >> 5;
    tile_load_A(sbase, ah_g, al_g, K, 0, tid);
    tile_load_B64(sbase + 16384, Bh, Bl, ldb, bn, 0, tid);
    CP_COMMIT();

    const int kr_base = (lane & 7) + ((lane >> 3) & 1) * 8;
    const int nc8 = (lane >> 4);

    for (int t = 0; t < nt; t++) {
        int b = t & 1;
        if (t + 1 < nt) {
            uint32_t nb = sbase + ((t + 1) & 1) * 24576;
            tile_load_A(nb, ah_g, al_g, K, (t + 1) << 5, tid);
            tile_load_B64(nb + 16384, Bh, Bl, ldb, bn, (t + 1) << 5, tid);
            CP_COMMIT();
            CP_WAIT(1);
        } else {
            CP_WAIT(0);
        }
        __syncthreads();

        uint32_t sA = sbase + b * 24576;
        uint32_t sB = sA + 16384;
#pragma unroll
        for (int ks = 0; ks < 2; ks++) {
            uint32_t bhf[2][4], blf[2][4];
#pragma unroll
            for (int np = 0; np < 2; np++) {
                int krow = ks * 16 + kr_base;
                int ncol = wn + np * 16 + nc8 * 8;
                int c = ncol >> 3;
                uint32_t a = sB + krow * 128 + ((c ^ (krow & 7)) << 4);
                ldsm4t(bhf[np], a);
                ldsm4t(blf[np], a + 4096);
            }
            uint32_t ahf[2][4], alf[2][4];
#pragma unroll
            for (int f = 0; f < 2; f++) {
                int row = wm + f * 16 + (lane & 15);
                int jc = (lane >> 4) + ks * 2;
                ldsm4(ahf[f], sA + row * 128 + ((jc ^ (row & 7)) << 4));
                ldsm4(alf[f], sA + row * 128 + (((jc + 4) ^ (row & 7)) << 4));
            }
#pragma unroll
            for (int m = 0; m < 2; m++)
#pragma unroll
                for (int nf = 0; nf < 4; nf++) {
                    uint32_t* bhp = &bhf[nf >> 1][(nf & 1) * 2];
                    uint32_t* blp = &blf[nf >> 1][(nf & 1) * 2];
                    float* ac = acc[m][nf];
                    mma_bf16(ac, ahf[m], bhp);
                    mma_bf16(ac, ahf[m], blp);
                    mma_bf16(ac, alf[m], bhp);
                }
        }
        __syncthreads();
    }
}

// fp32 output (+bias, +res), 128-wide N
__global__ __launch_bounds__(256, 2)
void k_gemm_f32(const __nv_bfloat16* __restrict__ Ah, const __nv_bfloat16* __restrict__ Al,
                const __nv_bfloat16* __restrict__ Bh, const __nv_bfloat16* __restrict__ Bl,
                const float* __restrict__ bias, const float* __restrict__ res,
                float* __restrict__ C, int K, int ldb, int ldc) {
    extern __shared__ char smem[];
    const int tid = threadIdx.x, wid = tid >> 5, lane = tid & 31;
    const int bm = blockIdx.y * 128, bn = blockIdx.x * 128;
    const int wm = (wid >> 2) * 64, wn = (wid & 3) * 32;
    float acc[4][4][4] = {};
    gemm_core(acc, Ah, Al, Bh, Bl, K, ldb, bm, bn, smem);
#pragma unroll
    for (int m = 0; m < 4; m++) {
        int r0 = bm + wm + m * 16 + (lane >> 2);
#pragma unroll
        for (int nf = 0; nf < 4; nf++) {
            int col = bn + wn + nf * 8 + ((lane & 3) << 1);
            float v0 = acc[m][nf][0], v1 = acc[m][nf][1];
            float v2 = acc[m][nf][2], v3 = acc[m][nf][3];
            if (bias) {
                float b0 = bias[col], b1 = bias[col + 1];
                v0 += b0; v1 += b1; v2 += b0; v3 += b1;
            }
            if (res) {
                const float* rr0 = res + (size_t)r0 * ldc + col;
                const float* rr1 = res + (size_t)(r0 + 8) * ldc + col;
                v0 += rr0[0]; v1 += rr0[1]; v2 += rr1[0]; v3 += rr1[1];
            }
            *(float2*)(C + (size_t)r0 * ldc + col) = make_float2(v0, v1);
            *(float2*)(C + (size_t)(r0 + 8) * ldc + col) = make_float2(v2, v3);
        }
    }
}

// fp32 output (+bias, +res), 64-wide N
__global__ __launch_bounds__(256, 2)
void k_gemm_f32_n64(const __nv_bfloat16* __restrict__ Ah, const __nv_bfloat16* __restrict__ Al,
                    const __nv_bfloat16* __restrict__ Bh, const __nv_bfloat16* __restrict__ Bl,
                    const float* __restrict__ bias, const float* __restrict__ res,
                    float* __restrict__ C, int K, int ldb, int ldc) {
    extern __shared__ char smem[];
    const int tid = threadIdx.x, wid = tid >> 5, lane = tid & 31;
    const int bm = blockIdx.y * 128, bn = blockIdx.x * 64;
    const int wm = (wid >> 1) * 32, wn = (wid & 1) * 32;
    float acc[2][4][4] = {};
    gemm_core64(acc, Ah, Al, Bh, Bl, K, ldb, bm, bn, smem);
#pragma unroll
    for (int m = 0; m < 2; m++) {
        int r0 = bm + wm + m * 16 + (lane >> 2);
#pragma unroll
        for (int nf = 0; nf < 4; nf++) {
            int col = bn + wn + nf * 8 + ((lane & 3) << 1);
            float v0 = acc[m][nf][0], v1 = acc[m][nf][1];
            float v2 = acc[m][nf][2], v3 = acc[m][nf][3];
            if (bias) {
                float b0 = bias[col], b1 = bias[col + 1];
                v0 += b0; v1 += b1; v2 += b0; v3 += b1;
            }
            if (res) {
                const float* rr0 = res + (size_t)r0 * ldc + col;
                const float* rr1 = res + (size_t)(r0 + 8) * ldc + col;
                v0 += rr0[0]; v1 += rr0[1]; v2 += rr1[0]; v3 += rr1[1];
            }
            *(float2*)(C + (size_t)r0 * ldc + col) = make_float2(v0, v1);
            *(float2*)(C + (size_t)(r0 + 8) * ldc + col) = make_float2(v2, v3);
        }
    }
}

// bf16 hi/lo output (+bias, relu) — FFN1
__global__ __launch_bounds__(256, 2)
void k_gemm_bf16(const __nv_bfloat16* __restrict__ Ah, const __nv_bfloat16* __restrict__ Al,
                 const __nv_bfloat16* __restrict__ Bh, const __nv_bfloat16* __restrict__ Bl,
                 const float* __restrict__ bias,
                 __nv_bfloat16* __restrict__ Ch, __nv_bfloat16* __restrict__ Cl,
                 int K, int ldb, int ldc, int relu) {
    extern __shared__ char smem[];
    const int tid = threadIdx.x, wid = tid >> 5, lane = tid & 31;
    const int bm = blockIdx.y * 128, bn = blockIdx.x * 128;
    const int wm = (wid >> 2) * 64, wn = (wid & 3) * 32;
    float acc[4][4][4] = {};
    gemm_core(acc, Ah, Al, Bh, Bl, K, ldb, bm, bn, smem);
#pragma unroll
    for (int m = 0; m < 4; m++) {
        int r0 = bm + wm + m * 16 + (lane >> 2);
#pragma unroll
        for (int nf = 0; nf < 4; nf++) {
            int col = bn + wn + nf * 8 + ((lane & 3) << 1);
            float v[4] = {acc[m][nf][0], acc[m][nf][1], acc[m][nf][2], acc[m][nf][3]};
            if (bias) {
                float b0 = bias[col], b1 = bias[col + 1];
                v[0] += b0; v[1] += b1; v[2] += b0; v[3] += b1;
            }
            if (relu) {
#pragma unroll
                for (int e = 0; e < 4; e++) v[e] = fmaxf(v[e], 0.f);
            }
            float h0 = __bfloat162float(__float2bfloat16(v[0]));
            float h1 = __bfloat162float(__float2bfloat16(v[1]));
            float h2 = __bfloat162float(__float2bfloat16(v[2]));
            float h3 = __bfloat162float(__float2bfloat16(v[3]));
            *(uint32_t*)(Ch + (size_t)r0 * ldc + col) = pack2bf(v[0], v[1]);
            *(uint32_t*)(Ch + (size_t)(r0 + 8) * ldc + col) = pack2bf(v[2], v[3]);
            *(uint32_t*)(Cl + (size_t)r0 * ldc + col) = pack2bf(v[0] - h0, v[1] - h1);
            *(uint32_t*)(Cl + (size_t)(r0 + 8) * ldc + col) = pack2bf(v[2] - h2, v[3] - h3);
        }
    }
}

// QKV gemm: B = [3][D,D]; cols [0,D)->q, [D,2D)->k, [2D,3D)->vT via smem
__global__ __launch_bounds__(256, 2)
void k_qkv_gemm(const __nv_bfloat16* __restrict__ Ah, const __nv_bfloat16* __restrict__ Al,
                const __nv_bfloat16* __restrict__ Bh, const __nv_bfloat16* __restrict__ Bl,
                __nv_bfloat16* __restrict__ qh, __nv_bfloat16* __restrict__ ql,
                __nv_bfloat16* __restrict__ kh, __nv_bfloat16* __restrict__ kl,
                __nv_bfloat16* __restrict__ vth, __nv_bfloat16* __restrict__ vtl) {
    extern __shared__ char smem[];
    const int tid = threadIdx.x, wid = tid >> 5, lane = tid & 31;
    const int bm = blockIdx.y * 128, bn = blockIdx.x * 128;
    const int wm = (wid >> 2) * 64, wn = (wid & 3) * 32;
    const int widx = bn >> 10;
    const int bn_eff = bn & 1023;
    float acc[4][4][4] = {};
    gemm_core(acc, Ah, Al, Bh + (size_t)widx * D * D, Bl + (size_t)widx * D * D,
              D, D, bm, bn_eff, smem);

    if (widx < 2) {
        __nv_bfloat16* oh = (widx == 0) ? qh : kh;
        __nv_bfloat16* ol = (widx == 0) ? ql : kl;
#pragma unroll
        for (int m = 0; m < 4; m++) {
            int r0 = bm + wm + m * 16 + (lane >> 2);
#pragma unroll
            for (int nf = 0; nf < 4; nf++) {
                int col = bn_eff + wn + nf * 8 + ((lane & 3) << 1);
                float v0 = acc[m][nf][0], v1 = acc[m][nf][1];
                float v2 = acc[m][nf][2], v3 = acc[m][nf][3];
                float h0 = __bfloat162float(__float2bfloat16(v0));
                float h1 = __bfloat162float(__float2bfloat16(v1));
                float h2 = __bfloat162float(__float2bfloat16(v2));
                float h3 = __bfloat162float(__float2bfloat16(v3));
                *(uint32_t*)(oh + (size_t)r0 * D + col) = pack2bf(v0, v1);
                *(uint32_t*)(oh + (size_t)(r0 + 8) * D + col) = pack2bf(v2, v3);
                *(uint32_t*)(ol + (size_t)r0 * D + col) = pack2bf(v0 - h0, v1 - h1);
                *(uint32_t*)(ol + (size_t)(r0 + 8) * D + col) = pack2bf(v2 - h2, v3 - h3);
            }
        }
    } else {
        __nv_bfloat16* sv = (__nv_bfloat16*)smem;
#pragma unroll
        for (int part = 0; part < 2; part++) {
#pragma unroll
            for (int m = 0; m < 4; m++) {
#pragma unroll
                for (int nf = 0; nf < 4; nf++) {
#pragma unroll
                    for (int e = 0; e < 4; e++) {
                        int rl = wm + m * 16 + (lane >> 2) + ((e >> 1) ? 8 : 0);
                        int cl = wn + nf * 8 + ((lane & 3) << 1) + (e & 1);
                        float v = acc[m][nf][e];
                        float hv = __bfloat162float(__float2bfloat16(v));
                        sv[cl * 136 + rl] = __float2bfloat16(part ? (v - hv) : v);
                    }
                }
            }
            __syncthreads();
            int col = tid >> 1, half = tid & 1;
            const uint4* src = (const uint4*)(smem + col * 272 + half * 128);
            __nv_bfloat16* dst = (part ? vtl : vth) +
                                 (size_t)(bn_eff + col) * S + bm + half * 64;
#pragma unroll
            for (int j = 0; j < 8; j++) ((uint4*)dst)[j] = src[j];
            __syncthreads();
        }
    }
}

// ---------------------------------------------------------------------------
// flash attention: CTA = (qblock 64, head), 128 thr
// ---------------------------------------------------------------------------
#define FA_SMEM (16384 + 2 * 32768)

__device__ __forceinline__ void fa_load(uint32_t sdst, const __nv_bfloat16* g,
                                        int ld, int tid) {
#pragma unroll
    for (int i = 0; i < 4; i++) {
        int cid = i * 128 + tid;
        int row = cid >> 3, c = cid & 7;
        CP16(sdst + row * 128 + ((c ^ (row & 7)) << 4), g + (size_t)row * ld + c * 8);
    }
}

__global__ __launch_bounds__(128)
void k_flash(const __nv_bfloat16* __restrict__ qh, const __nv_bfloat16* __restrict__ ql,
             const __nv_bfloat16* __restrict__ kh, const __nv_bfloat16* __restrict__ kl,
             const __nv_bfloat16* __restrict__ vth, const __nv_bfloat16* __restrict__ vtl,
             __nv_bfloat16* __restrict__ oh, __nv_bfloat16* __restrict__ ol) {
    extern __shared__ char smem[];
    uint32_t sb = smem_u32(smem);
    const int tid = threadIdx.x, w = tid >> 5, lane = tid & 31;
    const int qb = gridDim.x - 1 - blockIdx.x;
    const int hh = blockIdx.y;

    fa_load(sb,        qh + (size_t)(qb * 64) * D + hh * 64, D, tid);
    fa_load(sb + 8192, ql + (size_t)(qb * 64) * D + hh * 64, D, tid);
    {
        uint32_t st = sb + 16384;
        fa_load(st,         kh + hh * 64, D, tid);
        fa_load(st + 8192,  kl + hh * 64, D, tid);
        fa_load(st + 16384, vth + (size_t)(hh * 64) * S, S, tid);
        fa_load(st + 24576, vtl + (size_t)(hh * 64) * S, S, tid);
    }
    CP_COMMIT();

    uint32_t qhf[4][4], qlf[4][4];
    float o_acc[8][4] = {};
    float m0 = -1e30f, m1 = -1e30f, l0 = 0.f, l1 = 0.f;

    for (int kb = 0; kb <= qb; kb++) {
        if (kb + 1 <= qb) {
            uint32_t st = sb + 16384 + ((kb + 1) & 1) * 32768;
            fa_load(st,         kh + (size_t)((kb + 1) * 64) * D + hh * 64, D, tid);
            fa_load(st + 8192,  kl + (size_t)((kb + 1) * 64) * D + hh * 64, D, tid);
            fa_load(st + 16384, vth + (size_t)(hh * 64) * S + (kb + 1) * 64, S, tid);
            fa_load(st + 24576, vtl + (size_t)(hh * 64) * S + (kb + 1) * 64, S, tid);
            CP_COMMIT();
            CP_WAIT(1);
        } else {
            CP_WAIT(0);
        }
        __syncthreads();

        if (kb == 0) {
#pragma unroll
            for (int f = 0; f < 4; f++) {
                int row = w * 16 + (lane & 15);
                int jc = (lane >> 4) + f * 2;
                ldsm4(qhf[f], sb + row * 128 + ((jc ^ (row & 7)) << 4));
                ldsm4(qlf[f], sb + 8192 + row * 128 + ((jc ^ (row & 7)) << 4));
            }
        }

        uint32_t st = sb + 16384 + (kb & 1) * 32768;
        float s_acc[8][4] = {};
#pragma unroll
        for (int ks = 0; ks < 4; ks++) {
            uint32_t bh4[4][4], bl4[4][4];
#pragma unroll
            for (int np = 0; np < 4; np++) {
                int row = np * 16 + ((lane >> 4) << 3) + (lane & 7);
                int jc = ((lane >> 3) & 1) + ks * 2;
                ldsm4(bh4[np], st + row * 128 + ((jc ^ (row & 7)) << 4));
                ldsm4(bl4[np], st + 8192 + row * 128 + ((jc ^ (row & 7)) << 4));
            }
#pragma unroll
            for (int nf = 0; nf < 8; nf++) {
                uint32_t* bh = &bh4[nf >> 1][(nf & 1) * 2];
                uint32_t* bl = &bl4[nf >> 1][(nf & 1) * 2];
                mma_bf16(s_acc[nf], qhf[ks], bh);
                mma_bf16(s_acc[nf], qhf[ks], bl);
                mma_bf16(s_acc[nf], qlf[ks], bh);
            }
        }
        int r_lo = qb * 64 + w * 16 + (lane >> 2);
#pragma unroll
        for (int nf = 0; nf < 8; nf++)
#pragma unroll
            for (int e = 0; e < 4; e++) {
                float v = s_acc[nf][e] * 0.125f;
                if (kb == qb) {
                    int key = kb * 64 + nf * 8 + ((lane & 3) << 1) + (e & 1);
                    int qr = r_lo + ((e >> 1) ? 8 : 0);
                    if (key > qr) v = -1e30f;
                }
                s_acc[nf][e] = v;
            }
        float mx0 = -1e30f, mx1 = -1e30f;
#pragma unroll
        for (int nf = 0; nf < 8; nf++) {
            mx0 = fmaxf(mx0, fmaxf(s_acc[nf][0], s_acc[nf][1]));
            mx1 = fmaxf(mx1, fmaxf(s_acc[nf][2], s_acc[nf][3]));
        }
        mx0 = fmaxf(mx0, __shfl_xor_sync(0xffffffffu, mx0, 1));
        mx0 = fmaxf(mx0, __shfl_xor_sync(0xffffffffu, mx0, 2));
        mx1 = fmaxf(mx1, __shfl_xor_sync(0xffffffffu, mx1, 1));
        mx1 = fmaxf(mx1, __shfl_xor_sync(0xffffffffu, mx1, 2));
        float mn0 = fmaxf(m0, mx0), mn1 = fmaxf(m1, mx1);
        float a0 = __expf(m0 - mn0), a1 = __expf(m1 - mn1);
        float sum0 = 0.f, sum1 = 0.f;
#pragma unroll
        for (int nf = 0; nf < 8; nf++) {
            s_acc[nf][0] = __expf(s_acc[nf][0] - mn0);
            s_acc[nf][1] = __expf(s_acc[nf][1] - mn0);
            s_acc[nf][2] = __expf(s_acc[nf][2] - mn1);
            s_acc[nf][3] = __expf(s_acc[nf][3] - mn1);
            sum0 += s_acc[nf][0] + s_acc[nf][1];
            sum1 += s_acc[nf][2] + s_acc[nf][3];
        }
        sum0 += __shfl_xor_sync(0xffffffffu, sum0, 1);
        sum0 += __shfl_xor_sync(0xffffffffu, sum0, 2);
        sum1 += __shfl_xor_sync(0xffffffffu, sum1, 1);
        sum1 += __shfl_xor_sync(0xffffffffu, sum1, 2);
        l0 = l0 * a0 + sum0;
        l1 = l1 * a1 + sum1;
        m0 = mn0; m1 = mn1;
#pragma unroll
        for (int nf = 0; nf < 8; nf++) {
            o_acc[nf][0] *= a0; o_acc[nf][1] *= a0;
            o_acc[nf][2] *= a1; o_acc[nf][3] *= a1;
        }
        uint32_t pph[4][4], ppl[4][4];
#pragma unroll
        for (int g = 0; g < 4; g++) {
            float c0 = s_acc[2 * g][0], c1 = s_acc[2 * g][1];
            float c2 = s_acc[2 * g][2], c3 = s_acc[2 * g][3];
            float d0 = s_acc[2 * g + 1][0], d1 = s_acc[2 * g + 1][1];
            float d2 = s_acc[2 * g + 1][2], d3 = s_acc[2 * g + 1][3];
            pph[g][0] = pack2bf(c0, c1); pph[g][1] = pack2bf(c2, c3);
            pph[g][2] = pack2bf(d0, d1); pph[g][3] = pack2bf(d2, d3);
            ppl[g][0] = pack2bf(c0 - __bfloat162float(__float2bfloat16(c0)),
                                c1 - __bfloat162float(__float2bfloat16(c1)));
            ppl[g][1] = pack2bf(c2 - __bfloat162float(__float2bfloat16(c2)),
                                c3 - __bfloat162float(__float2bfloat16(c3)));
            ppl[g][2] = pack2bf(d0 - __bfloat162float(__float2bfloat16(d0)),
                                d1 - __bfloat162float(__float2bfloat16(d1)));
            ppl[g][3] = pack2bf(d2 - __bfloat162float(__float2bfloat16(d2)),
                                d3 - __bfloat162float(__float2bfloat16(d3)));
        }
        uint32_t sv = st + 16384;
#pragma unroll
        for (int ks = 0; ks < 4; ks++) {
            uint32_t bh4[4][4], bl4[4][4];
#pragma unroll
            for (int np = 0; np < 4; np++) {
                int row = np * 16 + ((lane >> 4) << 3) + (lane & 7);
                int jc = ((lane >> 3) & 1) + ks * 2;
                ldsm4(bh4[np], sv + row * 128 + ((jc ^ (row & 7)) << 4));
                ldsm4(bl4[np], sv + 8192 + row * 128 + ((jc ^ (row & 7)) << 4));
            }
#pragma unroll
            for (int nf = 0; nf < 8; nf++) {
                uint32_t* bh = &bh4[nf >> 1][(nf & 1) * 2];
                uint32_t* bl = &bl4[nf >> 1][(nf & 1) * 2];
                mma_bf16(o_acc[nf], pph[ks], bh);
                mma_bf16(o_acc[nf], ppl[ks], bh);
                mma_bf16(o_acc[nf], pph[ks], bl);
            }
        }
        __syncthreads();
    }

    float inv0 = 1.f / l0, inv1 = 1.f / l1;
    int row0 = qb * 64 + w * 16 + (lane >> 2);
#pragma unroll
    for (int nf = 0; nf < 8; nf++) {
        int col = hh * 64 + nf * 8 + ((lane & 3) << 1);
        float v0 = o_acc[nf][0] * inv0, v1 = o_acc[nf][1] * inv0;
        float v2 = o_acc[nf][2] * inv1, v3 = o_acc[nf][3] * inv1;
        float h0 = __bfloat162float(__float2bfloat16(v0));
        float h1 = __bfloat162float(__float2bfloat16(v1));
        float h2 = __bfloat162float(__float2bfloat16(v2));
        float h3 = __bfloat162float(__float2bfloat16(v3));
        *(uint32_t*)(oh + (size_t)row0 * D + col) = pack2bf(v0, v1);
        *(uint32_t*)(oh + (size_t)(row0 + 8) * D + col) = pack2bf(v2, v3);
        *(uint32_t*)(ol + (size_t)row0 * D + col) = pack2bf(v0 - h0, v1 - h1);
        *(uint32_t*)(ol + (size_t)(row0 + 8) * D + col) = pack2bf(v2 - h2, v3 - h3);
    }
}

// ---------------------------------------------------------------------------
// flat weight split
// ---------------------------------------------------------------------------
__global__ __launch_bounds__(256) void k_split_flat(const float* __restrict__ W,
                                                    __nv_bfloat16* __restrict__ th,
                                                    __nv_bfloat16* __restrict__ tl) {
    size_t gid = (size_t)blockIdx.x * 256 + threadIdx.x;
    float4 a = ((const float4*)W)[2 * gid];
    float4 b = ((const float4*)W)[2 * gid + 1];
    uint4 uh, ul;
    uh.x = pack2bf(a.x, a.y); uh.y = pack2bf(a.z, a.w);
    uh.z = pack2bf(b.x, b.y); uh.w = pack2bf(b.z, b.w);
    ul.x = pack2bf(a.x - __bfloat162float(__float2bfloat16(a.x)),
                   a.y - __bfloat162float(__float2bfloat16(a.y)));
    ul.y = pack2bf(a.z - __bfloat162float(__float2bfloat16(a.z)),
                   a.w - __bfloat162float(__float2bfloat16(a.w)));
    ul.z = pack2bf(b.x - __bfloat162float(__float2bfloat16(b.x)),
                   b.y - __bfloat162float(__float2bfloat16(b.y)));
    ul.w = pack2bf(b.z - __bfloat162float(__float2bfloat16(b.z)),
                   b.w - __bfloat162float(__float2bfloat16(b.w)));
    ((uint4*)th)[gid] = uh;
    ((uint4*)tl)[gid] = ul;
}

// ---------------------------------------------------------------------------
// embedding + positional encoding
// ---------------------------------------------------------------------------
__global__ __launch_bounds__(256) void k_embed(const int* __restrict__ x,
                                               const float* __restrict__ emb,
                                               float* __restrict__ h) {
    int s = blockIdx.y;
    int d = blockIdx.x * 256 + threadIdx.x;
    int tok = x[s];
    float e = emb[(size_t)tok * D + d];
    int i2 = d & ~1;
    float freq = expf((float)i2 * (-9.210340371976184f / (float)D));
    float ang = (float)s * freq;
    float pe = (d & 1) ? cosf(ang) : sinf(ang);
    h[(size_t)s * D + d] = e + pe;
}

// ---------------------------------------------------------------------------
// layernorm -> bf16 hi/lo
// ---------------------------------------------------------------------------
__global__ __launch_bounds__(256) void k_ln(const float* __restrict__ in,
                                            __nv_bfloat16* __restrict__ oh,
                                            __nv_bfloat16* __restrict__ ol,
                                            const float* __restrict__ w,
                                            const float* __restrict__ b) {
    int row = blockIdx.x;
    const float* xr = in + (size_t)row * D;
    int t = threadIdx.x;
    __shared__ float sh1[256];
    __shared__ float sh2[256];
    float s1 = 0.f, s2 = 0.f;
    for (int d = t; d < D; d += 256) {
        float v = xr[d];
        s1 += v; s2 += v * v;
    }
    sh1[t] = s1; sh2[t] = s2;
    __syncthreads();
    for (int o = 128; o > 0; o >>= 1) {
        if (t < o) { sh1[t] += sh1[t + o]; sh2[t] += sh2[t + o]; }
        __syncthreads();
    }
    float mean = sh1[0] * (1.0f / D);
    float var = sh2[0] * (1.0f / D) - mean * mean;
    float rstd = rsqrtf(var + EPSF);
    for (int d = t; d < D; d += 256) {
        float v = (xr[d] - mean) * rstd * w[d] + b[d];
        __nv_bfloat16 hv = __float2bfloat16(v);
        oh[(size_t)row * D + d] = hv;
        ol[(size_t)row * D + d] = __float2bfloat16(v - __bfloat162float(hv));
    }
}

// ---------------------------------------------------------------------------
// launch orchestration
// ---------------------------------------------------------------------------
extern "C" void kernel_launch(void* const* d_in, const int* in_sizes, int n_in,
                              void* d_out, int out_size) {
    (void)in_sizes; (void)n_in; (void)out_size;
    const int*   x      = (const int*)d_in[0];
    const float* emb    = (const float*)d_in[1];
    const float* Wq     = (const float*)d_in[2];
    const float* Wk     = (const float*)d_in[3];
    const float* Wv     = (const float*)d_in[4];
    const float* Wo     = (const float*)d_in[5];
    const float* bo     = (const float*)d_in[6];
    const float* ln1_w  = (const float*)d_in[7];
    const float* ln1_b  = (const float*)d_in[8];
    const float* W1     = (const float*)d_in[9];
    const float* b1     = (const float*)d_in[10];
    const float* W2     = (const float*)d_in[11];
    const float* b2     = (const float*)d_in[12];
    const float* ln2_w  = (const float*)d_in[13];
    const float* ln2_b  = (const float*)d_in[14];
    const float* fn_w   = (const float*)d_in[15];
    const float* fn_b   = (const float*)d_in[16];
    const float* lmhead = (const float*)d_in[17];
    float* out = (float*)d_out;

    static float* ph = nullptr;
    static __nv_bfloat16 *acth, *actl, *ffh, *ffl, *qh, *ql, *kh, *kl, *vth, *vtl,
                         *qkvh, *qkvl, *woh, *wol, *w1h, *w1l, *w2h, *w2l, *lmh, *lml;
    static cudaStream_t s1, s2;
    static cudaEvent_t evFork, evW[L], evLM, evDone;
    if (!ph) {
        cudaGetSymbolAddress((void**)&ph,   g_h);
        cudaGetSymbolAddress((void**)&acth, g_act_h);
        cudaGetSymbolAddress((void**)&actl, g_act_l);
        cudaGetSymbolAddress((void**)&ffh,  g_ff_h);
        cudaGetSymbolAddress((void**)&ffl,  g_ff_l);
        cudaGetSymbolAddress((void**)&qh,   g_qh);
        cudaGetSymbolAddress((void**)&ql,   g_ql);
        cudaGetSymbolAddress((void**)&kh,   g_kh);
        cudaGetSymbolAddress((void**)&kl,   g_kl);
        cudaGetSymbolAddress((void**)&vth,  g_vth);
        cudaGetSymbolAddress((void**)&vtl,  g_vtl);
        cudaGetSymbolAddress((void**)&qkvh, g_qkv_h);
        cudaGetSymbolAddress((void**)&qkvl, g_qkv_l);
        cudaGetSymbolAddress((void**)&woh,  g_wo_h);
        cudaGetSymbolAddress((void**)&wol,  g_wo_l);
        cudaGetSymbolAddress((void**)&w1h,  g_w1_h);
        cudaGetSymbolAddress((void**)&w1l,  g_w1_l);
        cudaGetSymbolAddress((void**)&w2h,  g_w2_h);
        cudaGetSymbolAddress((void**)&w2l,  g_w2_l);
        cudaGetSymbolAddress((void**)&lmh,  g_lm_h);
        cudaGetSymbolAddress((void**)&lml,  g_lm_l);
        cudaFuncSetAttribute(k_gemm_f32,     cudaFuncAttributeMaxDynamicSharedMemorySize, MG_SMEM);
        cudaFuncSetAttribute(k_gemm_f32_n64, cudaFuncAttributeMaxDynamicSharedMemorySize, MG64_SMEM);
        cudaFuncSetAttribute(k_gemm_bf16,    cudaFuncAttributeMaxDynamicSharedMemorySize, MG_SMEM);
        cudaFuncSetAttribute(k_qkv_gemm,     cudaFuncAttributeMaxDynamicSharedMemorySize, MG_SMEM);
        cudaFuncSetAttribute(k_flash,        cudaFuncAttributeMaxDynamicSharedMemorySize, FA_SMEM);
        cudaStreamCreateWithFlags(&s1, cudaStreamNonBlocking);
        cudaStreamCreateWithFlags(&s2, cudaStreamNonBlocking);
        cudaEventCreateWithFlags(&evFork, cudaEventDisableTiming);
        for (int l = 0; l < L; l++) cudaEventCreateWithFlags(&evW[l], cudaEventDisableTiming);
        cudaEventCreateWithFlags(&evLM, cudaEventDisableTiming);
        cudaEventCreateWithFlags(&evDone, cudaEventDisableTiming);
    }

    // fork
    cudaEventRecord(evFork, 0);
    cudaStreamWaitEvent(s1, evFork, 0);
    cudaStreamWaitEvent(s2, evFork, 0);

    // s2: weight prep
    const int gDD = D * D / 2048;
    const int gDF = D * FF / 2048;
    for (int l = 0; l < L; l++) {
        size_t wo = (size_t)l * D * D;
        size_t qo = (size_t)l * 3 * D * D;
        k_split_flat<<<gDD, 256, 0, s2>>>(Wq + wo, qkvh + qo,             qkvl + qo);
        k_split_flat<<<gDD, 256, 0, s2>>>(Wk + wo, qkvh + qo + D * D,     qkvl + qo + D * D);
        k_split_flat<<<gDD, 256, 0, s2>>>(Wv + wo, qkvh + qo + 2 * D * D, qkvl + qo + 2 * D * D);
        k_split_flat<<<gDD, 256, 0, s2>>>(Wo + wo, woh + wo, wol + wo);
        k_split_flat<<<gDF, 256, 0, s2>>>(W1 + (size_t)l * D * FF,
                                          w1h + (size_t)l * D * FF, w1l + (size_t)l * D * FF);
        k_split_flat<<<gDF, 256, 0, s2>>>(W2 + (size_t)l * FF * D,
                                          w2h + (size_t)l * FF * D, w2l + (size_t)l * FF * D);
        cudaEventRecord(evW[l], s2);
    }
    k_split_flat<<<(int)((size_t)D * V / 2048), 256, 0, s2>>>(lmhead, lmh, lml);
    cudaEventRecord(evLM, s2);

    // s1: compute
    k_embed<<<dim3(D / 256, S), 256, 0, s1>>>(x, emb, ph);

    for (int l = 0; l < L; l++) {
        size_t wo = (size_t)l * D * D;
        size_t qo = (size_t)l * 3 * D * D;
        cudaStreamWaitEvent(s1, evW[l], 0);
        // --- attention ---
        k_ln<<<S, 256, 0, s1>>>(ph, acth, actl, ln1_w + (size_t)l * D, ln1_b + (size_t)l * D);
        k_qkv_gemm<<<dim3(3 * D / 128, S / 128), 256, MG_SMEM, s1>>>(
            acth, actl, qkvh + qo, qkvl + qo, qh, ql, kh, kl, vth, vtl);
        k_flash<<<dim3(S / 64, H), 128, FA_SMEM, s1>>>(qh, ql, kh, kl, vth, vtl, acth, actl);
        k_gemm_f32_n64<<<dim3(D / 64, S / 128), 256, MG64_SMEM, s1>>>(
            acth, actl, woh + wo, wol + wo, bo + (size_t)l * D, ph, ph, D, D, D);
        // --- FFN ---
        k_ln<<<S, 256, 0, s1>>>(ph, acth, actl, ln2_w + (size_t)l * D, ln2_b + (size_t)l * D);
        k_gemm_bf16<<<dim3(FF / 128, S / 128), 256, MG_SMEM, s1>>>(
            acth, actl, w1h + (size_t)l * D * FF, w1l + (size_t)l * D * FF,
            b1 + (size_t)l * FF, ffh, ffl, D, FF, FF, 1);
        k_gemm_f32_n64<<<dim3(D / 64, S / 128), 256, MG64_SMEM, s1>>>(
            ffh, ffl, w2h + (size_t)l * FF * D, w2l + (size_t)l * FF * D,
            b2 + (size_t)l * D, ph, ph, FF, D, D);
    }

    // final LN + LM head
    cudaStreamWaitEvent(s1, evLM, 0);
    k_ln<<<S, 256, 0, s1>>>(ph, acth, actl, fn_w, fn_b);
    k_gemm_f32<<<dim3(V / 128, S / 128), 256, MG_SMEM, s1>>>(
        acth, actl, lmh, lml, nullptr, nullptr, out, D, V, V);

    // join
    cudaEventRecord(evDone, s1);
    cudaStreamWaitEvent(0, evDone, 0);
}

// round 8
// speedup vs baseline: 3.3459x; 1.0020x over previous
#include <cuda_runtime.h>
#include <cuda_bf16.h>
#include <math.h>
#include <stdint.h>

#define S 1024
#define D 1024
#define H 16
#define HD 64
#define L 4
#define FF 4096
#define V 32000
#define EPSF 1e-5f

// ---------------------------------------------------------------------------
// device scratch
// ---------------------------------------------------------------------------
__device__ __align__(16) float g_h[S * D];

__device__ __align__(16) __nv_bfloat16 g_act_h[S * FF];
__device__ __align__(16) __nv_bfloat16 g_act_l[S * FF];
__device__ __align__(16) __nv_bfloat16 g_ff_h[S * FF];
__device__ __align__(16) __nv_bfloat16 g_ff_l[S * FF];
__device__ __align__(16) __nv_bfloat16 g_qh[S * D];
__device__ __align__(16) __nv_bfloat16 g_ql[S * D];
__device__ __align__(16) __nv_bfloat16 g_kh[S * D];
__device__ __align__(16) __nv_bfloat16 g_kl[S * D];
__device__ __align__(16) __nv_bfloat16 g_vth[D * S];
__device__ __align__(16) __nv_bfloat16 g_vtl[D * S];

// weights: K-major [K,N] bf16 hi/lo
__device__ __align__(16) __nv_bfloat16 g_qkv_h[(size_t)L * 3 * D * D];
__device__ __align__(16) __nv_bfloat16 g_qkv_l[(size_t)L * 3 * D * D];
__device__ __align__(16) __nv_bfloat16 g_wo_h[(size_t)L * D * D];
__device__ __align__(16) __nv_bfloat16 g_wo_l[(size_t)L * D * D];
__device__ __align__(16) __nv_bfloat16 g_w1_h[(size_t)L * D * FF];
__device__ __align__(16) __nv_bfloat16 g_w1_l[(size_t)L * D * FF];
__device__ __align__(16) __nv_bfloat16 g_w2_h[(size_t)L * FF * D];
__device__ __align__(16) __nv_bfloat16 g_w2_l[(size_t)L * FF * D];
__device__ __align__(16) __nv_bfloat16 g_lm_h[(size_t)D * V];
__device__ __align__(16) __nv_bfloat16 g_lm_l[(size_t)D * V];

// ---------------------------------------------------------------------------
// PTX helpers
// ---------------------------------------------------------------------------
__device__ __forceinline__ uint32_t smem_u32(const void* p) {
    uint32_t a;
    asm("{ .reg .u64 t; cvta.to.shared.u64 t, %1; cvt.u32.u64 %0, t; }" : "=r"(a) : "l"(p));
    return a;
}
#define CP16(dst, src) \
    asm volatile("cp.async.cg.shared.global [%0], [%1], 16;" :: "r"(dst), "l"(src))
#define CP_COMMIT() asm volatile("cp.async.commit_group;" ::: "memory")
#define CP_WAIT(n)  asm volatile("cp.async.wait_group %0;" :: "n"(n) : "memory")

__device__ __forceinline__ void ldsm4(uint32_t* r, uint32_t addr) {
    asm volatile("ldmatrix.sync.aligned.m8n8.x4.shared.b16 {%0,%1,%2,%3}, [%4];"
                 : "=r"(r[0]), "=r"(r[1]), "=r"(r[2]), "=r"(r[3]) : "r"(addr));
}
__device__ __forceinline__ void ldsm4t(uint32_t* r, uint32_t addr) {
    asm volatile("ldmatrix.sync.aligned.m8n8.x4.trans.shared.b16 {%0,%1,%2,%3}, [%4];"
                 : "=r"(r[0]), "=r"(r[1]), "=r"(r[2]), "=r"(r[3]) : "r"(addr));
}
__device__ __forceinline__ void mma_bf16(float* d, const uint32_t* a, const uint32_t* b) {
    asm volatile(
        "mma.sync.aligned.m16n8k16.row.col.f32.bf16.bf16.f32 "
        "{%0,%1,%2,%3}, {%4,%5,%6,%7}, {%8,%9}, {%0,%1,%2,%3};"
        : "+f"(d[0]), "+f"(d[1]), "+f"(d[2]), "+f"(d[3])
        : "r"(a[0]), "r"(a[1]), "r"(a[2]), "r"(a[3]), "r"(b[0]), "r"(b[1]));
}
__device__ __forceinline__ uint32_t pack2bf(float a, float b) {
    unsigned short ra = __bfloat16_as_ushort(__float2bfloat16(a));
    unsigned short rb = __bfloat16_as_ushort(__float2bfloat16(b));
    return (uint32_t)ra | ((uint32_t)rb << 16);
}

// ---------------------------------------------------------------------------
// GEMM cores. A row-major hi/lo [M,K]; B K-major hi/lo [K,N].
// 3-stage cp.async pipeline, one __syncthreads per K-tile.
// 128-wide-N core: stage = A 16KB | Bh 8KB | Bl 8KB (32KB), 3 stages = 96KB
// 64-wide-N core : stage = A 16KB | Bh 4KB | Bl 4KB (24KB), 3 stages = 72KB
// ---------------------------------------------------------------------------
#define MG_SMEM (3 * 32768)
#define MG64_SMEM (3 * 24576)

__device__ __forceinline__ void tile_load_A(uint32_t sdst,
                                            const __nv_bfloat16* gh,
                                            const __nv_bfloat16* gl,
                                            int ld, int k0, int tid) {
#pragma unroll
    for (int i = 0; i < 4; i++) {
        int cid = i * 256 + tid;
        int row = cid >> 3, sub = cid & 7;
        const __nv_bfloat16* src =
            ((sub & 4) ? gl : gh) + (size_t)row * ld + k0 + (sub & 3) * 8;
        uint32_t dst = sdst + row * 128 + ((sub ^ (row & 7)) << 4);
        CP16(dst, src);
    }
}

__device__ __forceinline__ void tile_load_B(uint32_t sdst,
                                            const __nv_bfloat16* gh,
                                            const __nv_bfloat16* gl,
                                            int ldb, int bn, int k0, int tid) {
#pragma unroll
    for (int i = 0; i < 4; i++) {
        int cid = i * 256 + tid;
        int half = cid >> 9;
        int rem = cid & 511;
        int row = rem >> 4, c = rem & 15;
        const __nv_bfloat16* src =
            (half ? gl : gh) + (size_t)(k0 + row) * ldb + bn + c * 8;
        uint32_t dst = sdst + half * 8192 + row * 256 +
                       ((c ^ ((row & 7) << 1)) << 4);
        CP16(dst, src);
    }
}

__device__ __forceinline__ void tile_load_B64(uint32_t sdst,
                                              const __nv_bfloat16* gh,
                                              const __nv_bfloat16* gl,
                                              int ldb, int bn, int k0, int tid) {
#pragma unroll
    for (int i = 0; i < 2; i++) {
        int cid = i * 256 + tid;
        int half = cid >> 8;
        int rem = cid & 255;
        int row = rem >> 3, c = rem & 7;
        const __nv_bfloat16* src =
            (half ? gl : gh) + (size_t)(k0 + row) * ldb + bn + c * 8;
        uint32_t dst = sdst + half * 4096 + row * 128 + ((c ^ (row & 7)) << 4);
        CP16(dst, src);
    }
}

__device__ __forceinline__ void gemm_core(float (&acc)[4][4][4],
                                          const __nv_bfloat16* Ah, const __nv_bfloat16* Al,
                                          const __nv_bfloat16* Bh, const __nv_bfloat16* Bl,
                                          int K, int ldb, int bm, int bn, char* smem) {
    const int tid = threadIdx.x;
    const int wid = tid >> 5, lane = tid & 31;
    const int wm = (wid >> 2) * 64, wn = (wid & 3) * 32;
    uint32_t sbase = smem_u32(smem);

    const __nv_bfloat16* ah_g = Ah + (size_t)bm * K;
    const __nv_bfloat16* al_g = Al + (size_t)bm * K;

    const int nt = K >> 5;
    // prologue: stages 0, 1
    tile_load_A(sbase, ah_g, al_g, K, 0, tid);
    tile_load_B(sbase + 16384, Bh, Bl, ldb, bn, 0, tid);
    CP_COMMIT();
    tile_load_A(sbase + 32768, ah_g, al_g, K, 32, tid);
    tile_load_B(sbase + 32768 + 16384, Bh, Bl, ldb, bn, 32, tid);
    CP_COMMIT();

    const int kr_base = (lane & 7) + ((lane >> 3) & 1) * 8;
    const int nc8 = (lane >> 4);

    int br = 0, bw = 2;
    for (int t = 0; t < nt; t++) {
        if (t + 1 < nt) { CP_WAIT(1); } else { CP_WAIT(0); }
        __syncthreads();
        if (t + 2 < nt) {
            uint32_t nb = sbase + bw * 32768;
            tile_load_A(nb, ah_g, al_g, K, (t + 2) << 5, tid);
            tile_load_B(nb + 16384, Bh, Bl, ldb, bn, (t + 2) << 5, tid);
            CP_COMMIT();
        }

        uint32_t sA = sbase + br * 32768;
        uint32_t sB = sA + 16384;
#pragma unroll
        for (int ks = 0; ks < 2; ks++) {
            uint32_t bhf[2][4], blf[2][4];
#pragma unroll
            for (int np = 0; np < 2; np++) {
                int krow = ks * 16 + kr_base;
                int ncol = wn + np * 16 + nc8 * 8;
                int c = ncol >> 3;
                uint32_t a = sB + krow * 256 + ((c ^ ((krow & 7) << 1)) << 4);
                ldsm4t(bhf[np], a);
                ldsm4t(blf[np], a + 8192);
            }
#pragma unroll
            for (int mp = 0; mp < 2; mp++) {
                uint32_t ahf[2][4], alf[2][4];
#pragma unroll
                for (int f2 = 0; f2 < 2; f2++) {
                    int row = wm + (mp * 2 + f2) * 16 + (lane & 15);
                    int jc = (lane >> 4) + ks * 2;
                    ldsm4(ahf[f2], sA + row * 128 + ((jc ^ (row & 7)) << 4));
                    ldsm4(alf[f2], sA + row * 128 + (((jc + 4) ^ (row & 7)) << 4));
                }
#pragma unroll
                for (int m2 = 0; m2 < 2; m2++)
#pragma unroll
                    for (int nf = 0; nf < 4; nf++) {
                        uint32_t* bhp = &bhf[nf >> 1][(nf & 1) * 2];
                        uint32_t* blp = &blf[nf >> 1][(nf & 1) * 2];
                        float* ac = acc[mp * 2 + m2][nf];
                        mma_bf16(ac, ahf[m2], bhp);
                        mma_bf16(ac, ahf[m2], blp);
                        mma_bf16(ac, alf[m2], bhp);
                    }
            }
        }
        br = (br == 2) ? 0 : br + 1;
        bw = (bw == 2) ? 0 : bw + 1;
    }
}

__device__ __forceinline__ void gemm_core64(float (&acc)[2][4][4],
                                            const __nv_bfloat16* Ah, const __nv_bfloat16* Al,
                                            const __nv_bfloat16* Bh, const __nv_bfloat16* Bl,
                                            int K, int ldb, int bm, int bn, char* smem) {
    const int tid = threadIdx.x;
    const int wid = tid >> 5, lane = tid & 31;
    const int wm = (wid >> 1) * 32, wn = (wid & 1) * 32;
    uint32_t sbase = smem_u32(smem);

    const __nv_bfloat16* ah_g = Ah + (size_t)bm * K;
    const __nv_bfloat16* al_g = Al + (size_t)bm * K;

    const int nt = K >> 5;
    tile_load_A(sbase, ah_g, al_g, K, 0, tid);
    tile_load_B64(sbase + 16384, Bh, Bl, ldb, bn, 0, tid);
    CP_COMMIT();
    tile_load_A(sbase + 24576, ah_g, al_g, K, 32, tid);
    tile_load_B64(sbase + 24576 + 16384, Bh, Bl, ldb, bn, 32, tid);
    CP_COMMIT();

    const int kr_base = (lane & 7) + ((lane >> 3) & 1) * 8;
    const int nc8 = (lane >> 4);

    int br = 0, bw = 2;
    for (int t = 0; t < nt; t++) {
        if (t + 1 < nt) { CP_WAIT(1); } else { CP_WAIT(0); }
        __syncthreads();
        if (t + 2 < nt) {
            uint32_t nb = sbase + bw * 24576;
            tile_load_A(nb, ah_g, al_g, K, (t + 2) << 5, tid);
            tile_load_B64(nb + 16384, Bh, Bl, ldb, bn, (t + 2) << 5, tid);
            CP_COMMIT();
        }

        uint32_t sA = sbase + br * 24576;
        uint32_t sB = sA + 16384;
#pragma unroll
        for (int ks = 0; ks < 2; ks++) {
            uint32_t bhf[2][4], blf[2][4];
#pragma unroll
            for (int np = 0; np < 2; np++) {
                int krow = ks * 16 + kr_base;
                int ncol = wn + np * 16 + nc8 * 8;
                int c = ncol >> 3;
                uint32_t a = sB + krow * 128 + ((c ^ (krow & 7)) << 4);
                ldsm4t(bhf[np], a);
                ldsm4t(blf[np], a + 4096);
            }
            uint32_t ahf[2][4], alf[2][4];
#pragma unroll
            for (int f = 0; f < 2; f++) {
                int row = wm + f * 16 + (lane & 15);
                int jc = (lane >> 4) + ks * 2;
                ldsm4(ahf[f], sA + row * 128 + ((jc ^ (row & 7)) << 4));
                ldsm4(alf[f], sA + row * 128 + (((jc + 4) ^ (row & 7)) << 4));
            }
#pragma unroll
            for (int m = 0; m < 2; m++)
#pragma unroll
                for (int nf = 0; nf < 4; nf++) {
                    uint32_t* bhp = &bhf[nf >> 1][(nf & 1) * 2];
                    uint32_t* blp = &blf[nf >> 1][(nf & 1) * 2];
                    float* ac = acc[m][nf];
                    mma_bf16(ac, ahf[m], bhp);
                    mma_bf16(ac, ahf[m], blp);
                    mma_bf16(ac, alf[m], bhp);
                }
        }
        br = (br == 2) ? 0 : br + 1;
        bw = (bw == 2) ? 0 : bw + 1;
    }
}

// fp32 output (+bias, +res), 128-wide N
__global__ __launch_bounds__(256, 2)
void k_gemm_f32(const __nv_bfloat16* __restrict__ Ah, const __nv_bfloat16* __restrict__ Al,
                const __nv_bfloat16* __restrict__ Bh, const __nv_bfloat16* __restrict__ Bl,
                const float* __restrict__ bias, const float* __restrict__ res,
                float* __restrict__ C, int K, int ldb, int ldc) {
    extern __shared__ char smem[];
    const int tid = threadIdx.x, wid = tid >> 5, lane = tid & 31;
    const int bm = blockIdx.y * 128, bn = blockIdx.x * 128;
    const int wm = (wid >> 2) * 64, wn = (wid & 3) * 32;
    float acc[4][4][4] = {};
    gemm_core(acc, Ah, Al, Bh, Bl, K, ldb, bm, bn, smem);
#pragma unroll
    for (int m = 0; m < 4; m++) {
        int r0 = bm + wm + m * 16 + (lane >> 2);
#pragma unroll
        for (int nf = 0; nf < 4; nf++) {
            int col = bn + wn + nf * 8 + ((lane & 3) << 1);
            float v0 = acc[m][nf][0], v1 = acc[m][nf][1];
            float v2 = acc[m][nf][2], v3 = acc[m][nf][3];
            if (bias) {
                float b0 = bias[col], b1 = bias[col + 1];
                v0 += b0; v1 += b1; v2 += b0; v3 += b1;
            }
            if (res) {
                const float* rr0 = res + (size_t)r0 * ldc + col;
                const float* rr1 = res + (size_t)(r0 + 8) * ldc + col;
                v0 += rr0[0]; v1 += rr0[1]; v2 += rr1[0]; v3 += rr1[1];
            }
            *(float2*)(C + (size_t)r0 * ldc + col) = make_float2(v0, v1);
            *(float2*)(C + (size_t)(r0 + 8) * ldc + col) = make_float2(v2, v3);
        }
    }
}

// fp32 output (+bias, +res), 64-wide N
__global__ __launch_bounds__(256, 2)
void k_gemm_f32_n64(const __nv_bfloat16* __restrict__ Ah, const __nv_bfloat16* __restrict__ Al,
                    const __nv_bfloat16* __restrict__ Bh, const __nv_bfloat16* __restrict__ Bl,
                    const float* __restrict__ bias, const float* __restrict__ res,
                    float* __restrict__ C, int K, int ldb, int ldc) {
    extern __shared__ char smem[];
    const int tid = threadIdx.x, wid = tid >> 5, lane = tid & 31;
    const int bm = blockIdx.y * 128, bn = blockIdx.x * 64;
    const int wm = (wid >> 1) * 32, wn = (wid & 1) * 32;
    float acc[2][4][4] = {};
    gemm_core64(acc, Ah, Al, Bh, Bl, K, ldb, bm, bn, smem);
#pragma unroll
    for (int m = 0; m < 2; m++) {
        int r0 = bm + wm + m * 16 + (lane >> 2);
#pragma unroll
        for (int nf = 0; nf < 4; nf++) {
            int col = bn + wn + nf * 8 + ((lane & 3) << 1);
            float v0 = acc[m][nf][0], v1 = acc[m][nf][1];
            float v2 = acc[m][nf][2], v3 = acc[m][nf][3];
            if (bias) {
                float b0 = bias[col], b1 = bias[col + 1];
                v0 += b0; v1 += b1; v2 += b0; v3 += b1;
            }
            if (res) {
                const float* rr0 = res + (size_t)r0 * ldc + col;
                const float* rr1 = res + (size_t)(r0 + 8) * ldc + col;
                v0 += rr0[0]; v1 += rr0[1]; v2 += rr1[0]; v3 += rr1[1];
            }
            *(float2*)(C + (size_t)r0 * ldc + col) = make_float2(v0, v1);
            *(float2*)(C + (size_t)(r0 + 8) * ldc + col) = make_float2(v2, v3);
        }
    }
}

// bf16 hi/lo output (+bias, relu) — FFN1
__global__ __launch_bounds__(256, 2)
void k_gemm_bf16(const __nv_bfloat16* __restrict__ Ah, const __nv_bfloat16* __restrict__ Al,
                 const __nv_bfloat16* __restrict__ Bh, const __nv_bfloat16* __restrict__ Bl,
                 const float* __restrict__ bias,
                 __nv_bfloat16* __restrict__ Ch, __nv_bfloat16* __restrict__ Cl,
                 int K, int ldb, int ldc, int relu) {
    extern __shared__ char smem[];
    const int tid = threadIdx.x, wid = tid >> 5, lane = tid & 31;
    const int bm = blockIdx.y * 128, bn = blockIdx.x * 128;
    const int wm = (wid >> 2) * 64, wn = (wid & 3) * 32;
    float acc[4][4][4] = {};
    gemm_core(acc, Ah, Al, Bh, Bl, K, ldb, bm, bn, smem);
#pragma unroll
    for (int m = 0; m < 4; m++) {
        int r0 = bm + wm + m * 16 + (lane >> 2);
#pragma unroll
        for (int nf = 0; nf < 4; nf++) {
            int col = bn + wn + nf * 8 + ((lane & 3) << 1);
            float v[4] = {acc[m][nf][0], acc[m][nf][1], acc[m][nf][2], acc[m][nf][3]};
            if (bias) {
                float b0 = bias[col], b1 = bias[col + 1];
                v[0] += b0; v[1] += b1; v[2] += b0; v[3] += b1;
            }
            if (relu) {
#pragma unroll
                for (int e = 0; e < 4; e++) v[e] = fmaxf(v[e], 0.f);
            }
            float h0 = __bfloat162float(__float2bfloat16(v[0]));
            float h1 = __bfloat162float(__float2bfloat16(v[1]));
            float h2 = __bfloat162float(__float2bfloat16(v[2]));
            float h3 = __bfloat162float(__float2bfloat16(v[3]));
            *(uint32_t*)(Ch + (size_t)r0 * ldc + col) = pack2bf(v[0], v[1]);
            *(uint32_t*)(Ch + (size_t)(r0 + 8) * ldc + col) = pack2bf(v[2], v[3]);
            *(uint32_t*)(Cl + (size_t)r0 * ldc + col) = pack2bf(v[0] - h0, v[1] - h1);
            *(uint32_t*)(Cl + (size_t)(r0 + 8) * ldc + col) = pack2bf(v[2] - h2, v[3] - h3);
        }
    }
}

// QKV gemm: B = [3][D,D]; cols [0,D)->q, [D,2D)->k, [2D,3D)->vT via smem
__global__ __launch_bounds__(256, 2)
void k_qkv_gemm(const __nv_bfloat16* __restrict__ Ah, const __nv_bfloat16* __restrict__ Al,
                const __nv_bfloat16* __restrict__ Bh, const __nv_bfloat16* __restrict__ Bl,
                __nv_bfloat16* __restrict__ qh, __nv_bfloat16* __restrict__ ql,
                __nv_bfloat16* __restrict__ kh, __nv_bfloat16* __restrict__ kl,
                __nv_bfloat16* __restrict__ vth, __nv_bfloat16* __restrict__ vtl) {
    extern __shared__ char smem[];
    const int tid = threadIdx.x, wid = tid >> 5, lane = tid & 31;
    const int bm = blockIdx.y * 128, bn = blockIdx.x * 128;
    const int wm = (wid >> 2) * 64, wn = (wid & 3) * 32;
    const int widx = bn >> 10;
    const int bn_eff = bn & 1023;
    float acc[4][4][4] = {};
    gemm_core(acc, Ah, Al, Bh + (size_t)widx * D * D, Bl + (size_t)widx * D * D,
              D, D, bm, bn_eff, smem);

    if (widx < 2) {
        __nv_bfloat16* oh = (widx == 0) ? qh : kh;
        __nv_bfloat16* ol = (widx == 0) ? ql : kl;
#pragma unroll
        for (int m = 0; m < 4; m++) {
            int r0 = bm + wm + m * 16 + (lane >> 2);
#pragma unroll
            for (int nf = 0; nf < 4; nf++) {
                int col = bn_eff + wn + nf * 8 + ((lane & 3) << 1);
                float v0 = acc[m][nf][0], v1 = acc[m][nf][1];
                float v2 = acc[m][nf][2], v3 = acc[m][nf][3];
                float h0 = __bfloat162float(__float2bfloat16(v0));
                float h1 = __bfloat162float(__float2bfloat16(v1));
                float h2 = __bfloat162float(__float2bfloat16(v2));
                float h3 = __bfloat162float(__float2bfloat16(v3));
                *(uint32_t*)(oh + (size_t)r0 * D + col) = pack2bf(v0, v1);
                *(uint32_t*)(oh + (size_t)(r0 + 8) * D + col) = pack2bf(v2, v3);
                *(uint32_t*)(ol + (size_t)r0 * D + col) = pack2bf(v0 - h0, v1 - h1);
                *(uint32_t*)(ol + (size_t)(r0 + 8) * D + col) = pack2bf(v2 - h2, v3 - h3);
            }
        }
    } else {
        // smem reuse after mainloop: must drain all warps' ldsm reads first
        __syncthreads();
        __nv_bfloat16* sv = (__nv_bfloat16*)smem;
#pragma unroll
        for (int part = 0; part < 2; part++) {
#pragma unroll
            for (int m = 0; m < 4; m++) {
#pragma unroll
                for (int nf = 0; nf < 4; nf++) {
#pragma unroll
                    for (int e = 0; e < 4; e++) {
                        int rl = wm + m * 16 + (lane >> 2) + ((e >> 1) ? 8 : 0);
                        int cl = wn + nf * 8 + ((lane & 3) << 1) + (e & 1);
                        float v = acc[m][nf][e];
                        float hv = __bfloat162float(__float2bfloat16(v));
                        sv[cl * 136 + rl] = __float2bfloat16(part ? (v - hv) : v);
                    }
                }
            }
            __syncthreads();
            int col = tid >> 1, half = tid & 1;
            const uint4* src = (const uint4*)(smem + col * 272 + half * 128);
            __nv_bfloat16* dst = (part ? vtl : vth) +
                                 (size_t)(bn_eff + col) * S + bm + half * 64;
#pragma unroll
            for (int j = 0; j < 8; j++) ((uint4*)dst)[j] = src[j];
            __syncthreads();
        }
    }
}

// ---------------------------------------------------------------------------
// flash attention: CTA = (qblock 64, head), 128 thr
// ---------------------------------------------------------------------------
#define FA_SMEM (16384 + 2 * 32768)

__device__ __forceinline__ void fa_load(uint32_t sdst, const __nv_bfloat16* g,
                                        int ld, int tid) {
#pragma unroll
    for (int i = 0; i < 4; i++) {
        int cid = i * 128 + tid;
        int row = cid >> 3, c = cid & 7;
        CP16(sdst + row * 128 + ((c ^ (row & 7)) << 4), g + (size_t)row * ld + c * 8);
    }
}

__global__ __launch_bounds__(128)
void k_flash(const __nv_bfloat16* __restrict__ qh, const __nv_bfloat16* __restrict__ ql,
             const __nv_bfloat16* __restrict__ kh, const __nv_bfloat16* __restrict__ kl,
             const __nv_bfloat16* __restrict__ vth, const __nv_bfloat16* __restrict__ vtl,
             __nv_bfloat16* __restrict__ oh, __nv_bfloat16* __restrict__ ol) {
    extern __shared__ char smem[];
    uint32_t sb = smem_u32(smem);
    const int tid = threadIdx.x, w = tid >> 5, lane = tid & 31;
    const int qb = gridDim.x - 1 - blockIdx.x;
    const int hh = blockIdx.y;

    fa_load(sb,        qh + (size_t)(qb * 64) * D + hh * 64, D, tid);
    fa_load(sb + 8192, ql + (size_t)(qb * 64) * D + hh * 64, D, tid);
    {
        uint32_t st = sb + 16384;
        fa_load(st,         kh + hh * 64, D, tid);
        fa_load(st + 8192,  kl + hh * 64, D, tid);
        fa_load(st + 16384, vth + (size_t)(hh * 64) * S, S, tid);
        fa_load(st + 24576, vtl + (size_t)(hh * 64) * S, S, tid);
    }
    CP_COMMIT();

    uint32_t qhf[4][4], qlf[4][4];
    float o_acc[8][4] = {};
    float m0 = -1e30f, m1 = -1e30f, l0 = 0.f, l1 = 0.f;

    for (int kb = 0; kb <= qb; kb++) {
        if (kb + 1 <= qb) {
            uint32_t st = sb + 16384 + ((kb + 1) & 1) * 32768;
            fa_load(st,         kh + (size_t)((kb + 1) * 64) * D + hh * 64, D, tid);
            fa_load(st + 8192,  kl + (size_t)((kb + 1) * 64) * D + hh * 64, D, tid);
            fa_load(st + 16384, vth + (size_t)(hh * 64) * S + (kb + 1) * 64, S, tid);
            fa_load(st + 24576, vtl + (size_t)(hh * 64) * S + (kb + 1) * 64, S, tid);
            CP_COMMIT();
            CP_WAIT(1);
        } else {
            CP_WAIT(0);
        }
        __syncthreads();

        if (kb == 0) {
#pragma unroll
            for (int f = 0; f < 4; f++) {
                int row = w * 16 + (lane & 15);
                int jc = (lane >> 4) + f * 2;
                ldsm4(qhf[f], sb + row * 128 + ((jc ^ (row & 7)) << 4));
                ldsm4(qlf[f], sb + 8192 + row * 128 + ((jc ^ (row & 7)) << 4));
            }
        }

        uint32_t st = sb + 16384 + (kb & 1) * 32768;
        float s_acc[8][4] = {};
#pragma unroll
        for (int ks = 0; ks < 4; ks++) {
            uint32_t bh4[4][4], bl4[4][4];
#pragma unroll
            for (int np = 0; np < 4; np++) {
                int row = np * 16 + ((lane >> 4) << 3) + (lane & 7);
                int jc = ((lane >> 3) & 1) + ks * 2;
                ldsm4(bh4[np], st + row * 128 + ((jc ^ (row & 7)) << 4));
                ldsm4(bl4[np], st + 8192 + row * 128 + ((jc ^ (row & 7)) << 4));
            }
#pragma unroll
            for (int nf = 0; nf < 8; nf++) {
                uint32_t* bh = &bh4[nf >> 1][(nf & 1) * 2];
                uint32_t* bl = &bl4[nf >> 1][(nf & 1) * 2];
                mma_bf16(s_acc[nf], qhf[ks], bh);
                mma_bf16(s_acc[nf], qhf[ks], bl);
                mma_bf16(s_acc[nf], qlf[ks], bh);
            }
        }
        int r_lo = qb * 64 + w * 16 + (lane >> 2);
#pragma unroll
        for (int nf = 0; nf < 8; nf++)
#pragma unroll
            for (int e = 0; e < 4; e++) {
                float v = s_acc[nf][e] * 0.125f;
                if (kb == qb) {
                    int key = kb * 64 + nf * 8 + ((lane & 3) << 1) + (e & 1);
                    int qr = r_lo + ((e >> 1) ? 8 : 0);
                    if (key > qr) v = -1e30f;
                }
                s_acc[nf][e] = v;
            }
        float mx0 = -1e30f, mx1 = -1e30f;
#pragma unroll
        for (int nf = 0; nf < 8; nf++) {
            mx0 = fmaxf(mx0, fmaxf(s_acc[nf][0], s_acc[nf][1]));
            mx1 = fmaxf(mx1, fmaxf(s_acc[nf][2], s_acc[nf][3]));
        }
        mx0 = fmaxf(mx0, __shfl_xor_sync(0xffffffffu, mx0, 1));
        mx0 = fmaxf(mx0, __shfl_xor_sync(0xffffffffu, mx0, 2));
        mx1 = fmaxf(mx1, __shfl_xor_sync(0xffffffffu, mx1, 1));
        mx1 = fmaxf(mx1, __shfl_xor_sync(0xffffffffu, mx1, 2));
        float mn0 = fmaxf(m0, mx0), mn1 = fmaxf(m1, mx1);
        float a0 = __expf(m0 - mn0), a1 = __expf(m1 - mn1);
        float sum0 = 0.f, sum1 = 0.f;
#pragma unroll
        for (int nf = 0; nf < 8; nf++) {
            s_acc[nf][0] = __expf(s_acc[nf][0] - mn0);
            s_acc[nf][1] = __expf(s_acc[nf][1] - mn0);
            s_acc[nf][2] = __expf(s_acc[nf][2] - mn1);
            s_acc[nf][3] = __expf(s_acc[nf][3] - mn1);
            sum0 += s_acc[nf][0] + s_acc[nf][1];
            sum1 += s_acc[nf][2] + s_acc[nf][3];
        }
        sum0 += __shfl_xor_sync(0xffffffffu, sum0, 1);
        sum0 += __shfl_xor_sync(0xffffffffu, sum0, 2);
        sum1 += __shfl_xor_sync(0xffffffffu, sum1, 1);
        sum1 += __shfl_xor_sync(0xffffffffu, sum1, 2);
        l0 = l0 * a0 + sum0;
        l1 = l1 * a1 + sum1;
        m0 = mn0; m1 = mn1;
#pragma unroll
        for (int nf = 0; nf < 8; nf++) {
            o_acc[nf][0] *= a0; o_acc[nf][1] *= a0;
            o_acc[nf][2] *= a1; o_acc[nf][3] *= a1;
        }
        uint32_t pph[4][4], ppl[4][4];
#pragma unroll
        for (int g = 0; g < 4; g++) {
            float c0 = s_acc[2 * g][0], c1 = s_acc[2 * g][1];
            float c2 = s_acc[2 * g][2], c3 = s_acc[2 * g][3];
            float d0 = s_acc[2 * g + 1][0], d1 = s_acc[2 * g + 1][1];
            float d2 = s_acc[2 * g + 1][2], d3 = s_acc[2 * g + 1][3];
            pph[g][0] = pack2bf(c0, c1); pph[g][1] = pack2bf(c2, c3);
            pph[g][2] = pack2bf(d0, d1); pph[g][3] = pack2bf(d2, d3);
            ppl[g][0] = pack2bf(c0 - __bfloat162float(__float2bfloat16(c0)),
                                c1 - __bfloat162float(__float2bfloat16(c1)));
            ppl[g][1] = pack2bf(c2 - __bfloat162float(__float2bfloat16(c2)),
                                c3 - __bfloat162float(__float2bfloat16(c3)));
            ppl[g][2] = pack2bf(d0 - __bfloat162float(__float2bfloat16(d0)),
                                d1 - __bfloat162float(__float2bfloat16(d1)));
            ppl[g][3] = pack2bf(d2 - __bfloat162float(__float2bfloat16(d2)),
                                d3 - __bfloat162float(__float2bfloat16(d3)));
        }
        uint32_t sv = st + 16384;
#pragma unroll
        for (int ks = 0; ks < 4; ks++) {
            uint32_t bh4[4][4], bl4[4][4];
#pragma unroll
            for (int np = 0; np < 4; np++) {
                int row = np * 16 + ((lane >> 4) << 3) + (lane & 7);
                int jc = ((lane >> 3) & 1) + ks * 2;
                ldsm4(bh4[np], sv + row * 128 + ((jc ^ (row & 7)) << 4));
                ldsm4(bl4[np], sv + 8192 + row * 128 + ((jc ^ (row & 7)) << 4));
            }
#pragma unroll
            for (int nf = 0; nf < 8; nf++) {
                uint32_t* bh = &bh4[nf >> 1][(nf & 1) * 2];
                uint32_t* bl = &bl4[nf >> 1][(nf & 1) * 2];
                mma_bf16(o_acc[nf], pph[ks], bh);
                mma_bf16(o_acc[nf], ppl[ks], bh);
                mma_bf16(o_acc[nf], pph[ks], bl);
            }
        }
        __syncthreads();
    }

    float inv0 = 1.f / l0, inv1 = 1.f / l1;
    int row0 = qb * 64 + w * 16 + (lane >> 2);
#pragma unroll
    for (int nf = 0; nf < 8; nf++) {
        int col = hh * 64 + nf * 8 + ((lane & 3) << 1);
        float v0 = o_acc[nf][0] * inv0, v1 = o_acc[nf][1] * inv0;
        float v2 = o_acc[nf][2] * inv1, v3 = o_acc[nf][3] * inv1;
        float h0 = __bfloat162float(__float2bfloat16(v0));
        float h1 = __bfloat162float(__float2bfloat16(v1));
        float h2 = __bfloat162float(__float2bfloat16(v2));
        float h3 = __bfloat162float(__float2bfloat16(v3));
        *(uint32_t*)(oh + (size_t)row0 * D + col) = pack2bf(v0, v1);
        *(uint32_t*)(oh + (size_t)(row0 + 8) * D + col) = pack2bf(v2, v3);
        *(uint32_t*)(ol + (size_t)row0 * D + col) = pack2bf(v0 - h0, v1 - h1);
        *(uint32_t*)(ol + (size_t)(row0 + 8) * D + col) = pack2bf(v2 - h2, v3 - h3);
    }
}

// ---------------------------------------------------------------------------
// flat weight split
// ---------------------------------------------------------------------------
__global__ __launch_bounds__(256) void k_split_flat(const float* __restrict__ W,
                                                    __nv_bfloat16* __restrict__ th,
                                                    __nv_bfloat16* __restrict__ tl) {
    size_t gid = (size_t)blockIdx.x * 256 + threadIdx.x;
    float4 a = ((const float4*)W)[2 * gid];
    float4 b = ((const float4*)W)[2 * gid + 1];
    uint4 uh, ul;
    uh.x = pack2bf(a.x, a.y); uh.y = pack2bf(a.z, a.w);
    uh.z = pack2bf(b.x, b.y); uh.w = pack2bf(b.z, b.w);
    ul.x = pack2bf(a.x - __bfloat162float(__float2bfloat16(a.x)),
                   a.y - __bfloat162float(__float2bfloat16(a.y)));
    ul.y = pack2bf(a.z - __bfloat162float(__float2bfloat16(a.z)),
                   a.w - __bfloat162float(__float2bfloat16(a.w)));
    ul.z = pack2bf(b.x - __bfloat162float(__float2bfloat16(b.x)),
                   b.y - __bfloat162float(__float2bfloat16(b.y)));
    ul.w = pack2bf(b.z - __bfloat162float(__float2bfloat16(b.z)),
                   b.w - __bfloat162float(__float2bfloat16(b.w)));
    ((uint4*)th)[gid] = uh;
    ((uint4*)tl)[gid] = ul;
}

// ---------------------------------------------------------------------------
// embedding + positional encoding
// ---------------------------------------------------------------------------
__global__ __launch_bounds__(256) void k_embed(const int* __restrict__ x,
                                               const float* __restrict__ emb,
                                               float* __restrict__ h) {
    int s = blockIdx.y;
    int d = blockIdx.x * 256 + threadIdx.x;
    int tok = x[s];
    float e = emb[(size_t)tok * D + d];
    int i2 = d & ~1;
    float freq = expf((float)i2 * (-9.210340371976184f / (float)D));
    float ang = (float)s * freq;
    float pe = (d & 1) ? cosf(ang) : sinf(ang);
    h[(size_t)s * D + d] = e + pe;
}

// ---------------------------------------------------------------------------
// layernorm -> bf16 hi/lo
// ---------------------------------------------------------------------------
__global__ __launch_bounds__(256) void k_ln(const float* __restrict__ in,
                                            __nv_bfloat16* __restrict__ oh,
                                            __nv_bfloat16* __restrict__ ol,
                                            const float* __restrict__ w,
                                            const float* __restrict__ b) {
    int row = blockIdx.x;
    const float* xr = in + (size_t)row * D;
    int t = threadIdx.x;
    __shared__ float sh1[256];
    __shared__ float sh2[256];
    float s1 = 0.f, s2 = 0.f;
    for (int d = t; d < D; d += 256) {
        float v = xr[d];
        s1 += v; s2 += v * v;
    }
    sh1[t] = s1; sh2[t] = s2;
    __syncthreads();
    for (int o = 128; o > 0; o >>= 1) {
        if (t < o) { sh1[t] += sh1[t + o]; sh2[t] += sh2[t + o]; }
        __syncthreads();
    }
    float mean = sh1[0] * (1.0f / D);
    float var = sh2[0] * (1.0f / D) - mean * mean;
    float rstd = rsqrtf(var + EPSF);
    for (int d = t; d < D; d += 256) {
        float v = (xr[d] - mean) * rstd * w[d] + b[d];
        __nv_bfloat16 hv = __float2bfloat16(v);
        oh[(size_t)row * D + d] = hv;
        ol[(size_t)row * D + d] = __float2bfloat16(v - __bfloat162float(hv));
    }
}

// ---------------------------------------------------------------------------
// launch orchestration
// ---------------------------------------------------------------------------
extern "C" void kernel_launch(void* const* d_in, const int* in_sizes, int n_in,
                              void* d_out, int out_size) {
    (void)in_sizes; (void)n_in; (void)out_size;
    const int*   x      = (const int*)d_in[0];
    const float* emb    = (const float*)d_in[1];
    const float* Wq     = (const float*)d_in[2];
    const float* Wk     = (const float*)d_in[3];
    const float* Wv     = (const float*)d_in[4];
    const float* Wo     = (const float*)d_in[5];
    const float* bo     = (const float*)d_in[6];
    const float* ln1_w  = (const float*)d_in[7];
    const float* ln1_b  = (const float*)d_in[8];
    const float* W1     = (const float*)d_in[9];
    const float* b1     = (const float*)d_in[10];
    const float* W2     = (const float*)d_in[11];
    const float* b2     = (const float*)d_in[12];
    const float* ln2_w  = (const float*)d_in[13];
    const float* ln2_b  = (const float*)d_in[14];
    const float* fn_w   = (const float*)d_in[15];
    const float* fn_b   = (const float*)d_in[16];
    const float* lmhead = (const float*)d_in[17];
    float* out = (float*)d_out;

    static float* ph = nullptr;
    static __nv_bfloat16 *acth, *actl, *ffh, *ffl, *qh, *ql, *kh, *kl, *vth, *vtl,
                         *qkvh, *qkvl, *woh, *wol, *w1h, *w1l, *w2h, *w2l, *lmh, *lml;
    static cudaStream_t s1, s2;
    static cudaEvent_t evFork, evW[L], evLM, evDone;
    if (!ph) {
        cudaGetSymbolAddress((void**)&ph,   g_h);
        cudaGetSymbolAddress((void**)&acth, g_act_h);
        cudaGetSymbolAddress((void**)&actl, g_act_l);
        cudaGetSymbolAddress((void**)&ffh,  g_ff_h);
        cudaGetSymbolAddress((void**)&ffl,  g_ff_l);
        cudaGetSymbolAddress((void**)&qh,   g_qh);
        cudaGetSymbolAddress((void**)&ql,   g_ql);
        cudaGetSymbolAddress((void**)&kh,   g_kh);
        cudaGetSymbolAddress((void**)&kl,   g_kl);
        cudaGetSymbolAddress((void**)&vth,  g_vth);
        cudaGetSymbolAddress((void**)&vtl,  g_vtl);
        cudaGetSymbolAddress((void**)&qkvh, g_qkv_h);
        cudaGetSymbolAddress((void**)&qkvl, g_qkv_l);
        cudaGetSymbolAddress((void**)&woh,  g_wo_h);
        cudaGetSymbolAddress((void**)&wol,  g_wo_l);
        cudaGetSymbolAddress((void**)&w1h,  g_w1_h);
        cudaGetSymbolAddress((void**)&w1l,  g_w1_l);
        cudaGetSymbolAddress((void**)&w2h,  g_w2_h);
        cudaGetSymbolAddress((void**)&w2l,  g_w2_l);
        cudaGetSymbolAddress((void**)&lmh,  g_lm_h);
        cudaGetSymbolAddress((void**)&lml,  g_lm_l);
        cudaFuncSetAttribute(k_gemm_f32,     cudaFuncAttributeMaxDynamicSharedMemorySize, MG_SMEM);
        cudaFuncSetAttribute(k_gemm_f32_n64, cudaFuncAttributeMaxDynamicSharedMemorySize, MG64_SMEM);
        cudaFuncSetAttribute(k_gemm_bf16,    cudaFuncAttributeMaxDynamicSharedMemorySize, MG_SMEM);
        cudaFuncSetAttribute(k_qkv_gemm,     cudaFuncAttributeMaxDynamicSharedMemorySize, MG_SMEM);
        cudaFuncSetAttribute(k_flash,        cudaFuncAttributeMaxDynamicSharedMemorySize, FA_SMEM);
        cudaStreamCreateWithFlags(&s1, cudaStreamNonBlocking);
        cudaStreamCreateWithFlags(&s2, cudaStreamNonBlocking);
        cudaEventCreateWithFlags(&evFork, cudaEventDisableTiming);
        for (int l = 0; l < L; l++) cudaEventCreateWithFlags(&evW[l], cudaEventDisableTiming);
        cudaEventCreateWithFlags(&evLM, cudaEventDisableTiming);
        cudaEventCreateWithFlags(&evDone, cudaEventDisableTiming);
    }

    // fork
    cudaEventRecord(evFork, 0);
    cudaStreamWaitEvent(s1, evFork, 0);
    cudaStreamWaitEvent(s2, evFork, 0);

    // s2: weight prep
    const int gDD = D * D / 2048;
    const int gDF = D * FF / 2048;
    for (int l = 0; l < L; l++) {
        size_t wo = (size_t)l * D * D;
        size_t qo = (size_t)l * 3 * D * D;
        k_split_flat<<<gDD, 256, 0, s2>>>(Wq + wo, qkvh + qo,             qkvl + qo);
        k_split_flat<<<gDD, 256, 0, s2>>>(Wk + wo, qkvh + qo + D * D,     qkvl + qo + D * D);
        k_split_flat<<<gDD, 256, 0, s2>>>(Wv + wo, qkvh + qo + 2 * D * D, qkvl + qo + 2 * D * D);
        k_split_flat<<<gDD, 256, 0, s2>>>(Wo + wo, woh + wo, wol + wo);
        k_split_flat<<<gDF, 256, 0, s2>>>(W1 + (size_t)l * D * FF,
                                          w1h + (size_t)l * D * FF, w1l + (size_t)l * D * FF);
        k_split_flat<<<gDF, 256, 0, s2>>>(W2 + (size_t)l * FF * D,
                                          w2h + (size_t)l * FF * D, w2l + (size_t)l * FF * D);
        cudaEventRecord(evW[l], s2);
    }
    k_split_flat<<<(int)((size_t)D * V / 2048), 256, 0, s2>>>(lmhead, lmh, lml);
    cudaEventRecord(evLM, s2);

    // s1: compute
    k_embed<<<dim3(D / 256, S), 256, 0, s1>>>(x, emb, ph);

    for (int l = 0; l < L; l++) {
        size_t wo = (size_t)l * D * D;
        size_t qo = (size_t)l * 3 * D * D;
        cudaStreamWaitEvent(s1, evW[l], 0);
        // --- attention ---
        k_ln<<<S, 256, 0, s1>>>(ph, acth, actl, ln1_w + (size_t)l * D, ln1_b + (size_t)l * D);
        k_qkv_gemm<<<dim3(3 * D / 128, S / 128), 256, MG_SMEM, s1>>>(
            acth, actl, qkvh + qo, qkvl + qo, qh, ql, kh, kl, vth, vtl);
        k_flash<<<dim3(S / 64, H), 128, FA_SMEM, s1>>>(qh, ql, kh, kl, vth, vtl, acth, actl);
        k_gemm_f32_n64<<<dim3(D / 64, S / 128), 256, MG64_SMEM, s1>>>(
            acth, actl, woh + wo, wol + wo, bo + (size_t)l * D, ph, ph, D, D, D);
        // --- FFN ---
        k_ln<<<S, 256, 0, s1>>>(ph, acth, actl, ln2_w + (size_t)l * D, ln2_b + (size_t)l * D);
        k_gemm_bf16<<<dim3(FF / 128, S / 128), 256, MG_SMEM, s1>>>(
            acth, actl, w1h + (size_t)l * D * FF, w1l + (size_t)l * D * FF,
            b1 + (size_t)l * FF, ffh, ffl, D, FF, FF, 1);
        k_gemm_f32_n64<<<dim3(D / 64, S / 128), 256, MG64_SMEM, s1>>>(
            ffh, ffl, w2h + (size_t)l * FF * D, w2l + (size_t)l * FF * D,
            b2 + (size_t)l * D, ph, ph, FF, D, D);
    }

    // final LN + LM head
    cudaStreamWaitEvent(s1, evLM, 0);
    k_ln<<<S, 256, 0, s1>>>(ph, acth, actl, fn_w, fn_b);
    k_gemm_f32<<<dim3(V / 128, S / 128), 256, MG_SMEM, s1>>>(
        acth, actl, lmh, lml, nullptr, nullptr, out, D, V, V);

    // join
    cudaEventRecord(evDone, s1);
    cudaStreamWaitEvent(0, evDone, 0);
}

// round 9
// speedup vs baseline: 3.3821x; 1.0108x over previous
#include <cuda_runtime.h>
#include <cuda_bf16.h>
#include <math.h>
#include <stdint.h>

#define S 1024
#define D 1024
#define H 16
#define HD 64
#define L 4
#define FF 4096
#define V 32000
#define EPSF 1e-5f

// ---------------------------------------------------------------------------
// device scratch
// ---------------------------------------------------------------------------
__device__ __align__(16) float g_h[S * D];

__device__ __align__(16) __nv_bfloat16 g_act_h[S * FF];
__device__ __align__(16) __nv_bfloat16 g_act_l[S * FF];
__device__ __align__(16) __nv_bfloat16 g_ff_h[S * FF];
__device__ __align__(16) __nv_bfloat16 g_ff_l[S * FF];
__device__ __align__(16) __nv_bfloat16 g_qh[S * D];
__device__ __align__(16) __nv_bfloat16 g_ql[S * D];
__device__ __align__(16) __nv_bfloat16 g_kh[S * D];
__device__ __align__(16) __nv_bfloat16 g_kl[S * D];
__device__ __align__(16) __nv_bfloat16 g_vth[D * S];
__device__ __align__(16) __nv_bfloat16 g_vtl[D * S];

// weights: K-major [K,N] bf16 hi/lo
__device__ __align__(16) __nv_bfloat16 g_qkv_h[(size_t)L * 3 * D * D];
__device__ __align__(16) __nv_bfloat16 g_qkv_l[(size_t)L * 3 * D * D];
__device__ __align__(16) __nv_bfloat16 g_wo_h[(size_t)L * D * D];
__device__ __align__(16) __nv_bfloat16 g_wo_l[(size_t)L * D * D];
__device__ __align__(16) __nv_bfloat16 g_w1_h[(size_t)L * D * FF];
__device__ __align__(16) __nv_bfloat16 g_w1_l[(size_t)L * D * FF];
__device__ __align__(16) __nv_bfloat16 g_w2_h[(size_t)L * FF * D];
__device__ __align__(16) __nv_bfloat16 g_w2_l[(size_t)L * FF * D];
__device__ __align__(16) __nv_bfloat16 g_lm_h[(size_t)D * V];
__device__ __align__(16) __nv_bfloat16 g_lm_l[(size_t)D * V];

// ---------------------------------------------------------------------------
// PTX helpers
// ---------------------------------------------------------------------------
__device__ __forceinline__ uint32_t smem_u32(const void* p) {
    uint32_t a;
    asm("{ .reg .u64 t; cvta.to.shared.u64 t, %1; cvt.u32.u64 %0, t; }" : "=r"(a) : "l"(p));
    return a;
}
#define CP16(dst, src) \
    asm volatile("cp.async.cg.shared.global [%0], [%1], 16;" :: "r"(dst), "l"(src))
#define CP_COMMIT() asm volatile("cp.async.commit_group;" ::: "memory")
#define CP_WAIT(n)  asm volatile("cp.async.wait_group %0;" :: "n"(n) : "memory")

__device__ __forceinline__ void ldsm4(uint32_t* r, uint32_t addr) {
    asm volatile("ldmatrix.sync.aligned.m8n8.x4.shared.b16 {%0,%1,%2,%3}, [%4];"
                 : "=r"(r[0]), "=r"(r[1]), "=r"(r[2]), "=r"(r[3]) : "r"(addr));
}
__device__ __forceinline__ void ldsm4t(uint32_t* r, uint32_t addr) {
    asm volatile("ldmatrix.sync.aligned.m8n8.x4.trans.shared.b16 {%0,%1,%2,%3}, [%4];"
                 : "=r"(r[0]), "=r"(r[1]), "=r"(r[2]), "=r"(r[3]) : "r"(addr));
}
__device__ __forceinline__ void mma_bf16(float* d, const uint32_t* a, const uint32_t* b) {
    asm volatile(
        "mma.sync.aligned.m16n8k16.row.col.f32.bf16.bf16.f32 "
        "{%0,%1,%2,%3}, {%4,%5,%6,%7}, {%8,%9}, {%0,%1,%2,%3};"
        : "+f"(d[0]), "+f"(d[1]), "+f"(d[2]), "+f"(d[3])
        : "r"(a[0]), "r"(a[1]), "r"(a[2]), "r"(a[3]), "r"(b[0]), "r"(b[1]));
}
__device__ __forceinline__ uint32_t pack2bf(float a, float b) {
    unsigned short ra = __bfloat16_as_ushort(__float2bfloat16(a));
    unsigned short rb = __bfloat16_as_ushort(__float2bfloat16(b));
    return (uint32_t)ra | ((uint32_t)rb << 16);
}

// ---------------------------------------------------------------------------
// GEMM cores. A row-major hi/lo [M,K]; B K-major hi/lo [K,N]. 3-stage pipe.
// 128x128 core: stage = A 16KB | Bh 8KB | Bl 8KB (32KB)
// 64x64 core  : stage = A  8KB | Bh 4KB | Bl 4KB (16KB)  (for wave fill)
// ---------------------------------------------------------------------------
#define MG_SMEM (3 * 32768)
#define T64_SMEM (3 * 16384)

__device__ __forceinline__ void tile_load_A(uint32_t sdst,
                                            const __nv_bfloat16* gh,
                                            const __nv_bfloat16* gl,
                                            int ld, int k0, int tid) {
#pragma unroll
    for (int i = 0; i < 4; i++) {
        int cid = i * 256 + tid;
        int row = cid >> 3, sub = cid & 7;
        const __nv_bfloat16* src =
            ((sub & 4) ? gl : gh) + (size_t)row * ld + k0 + (sub & 3) * 8;
        uint32_t dst = sdst + row * 128 + ((sub ^ (row & 7)) << 4);
        CP16(dst, src);
    }
}

// A tile 64 rows (same per-row layout), 2 chunks/thread
__device__ __forceinline__ void tile_load_A64(uint32_t sdst,
                                              const __nv_bfloat16* gh,
                                              const __nv_bfloat16* gl,
                                              int ld, int k0, int tid) {
#pragma unroll
    for (int i = 0; i < 2; i++) {
        int cid = i * 256 + tid;
        int row = cid >> 3, sub = cid & 7;
        const __nv_bfloat16* src =
            ((sub & 4) ? gl : gh) + (size_t)row * ld + k0 + (sub & 3) * 8;
        uint32_t dst = sdst + row * 128 + ((sub ^ (row & 7)) << 4);
        CP16(dst, src);
    }
}

__device__ __forceinline__ void tile_load_B(uint32_t sdst,
                                            const __nv_bfloat16* gh,
                                            const __nv_bfloat16* gl,
                                            int ldb, int bn, int k0, int tid) {
#pragma unroll
    for (int i = 0; i < 4; i++) {
        int cid = i * 256 + tid;
        int half = cid >> 9;
        int rem = cid & 511;
        int row = rem >> 4, c = rem & 15;
        const __nv_bfloat16* src =
            (half ? gl : gh) + (size_t)(k0 + row) * ldb + bn + c * 8;
        uint32_t dst = sdst + half * 8192 + row * 256 +
                       ((c ^ ((row & 7) << 1)) << 4);
        CP16(dst, src);
    }
}

// B tile 32x64: row pitch 128B, 8 chunks/row, swizzle c ^ (row&7)
__device__ __forceinline__ void tile_load_B64(uint32_t sdst,
                                              const __nv_bfloat16* gh,
                                              const __nv_bfloat16* gl,
                                              int ldb, int bn, int k0, int tid) {
#pragma unroll
    for (int i = 0; i < 2; i++) {
        int cid = i * 256 + tid;
        int half = cid >> 8;
        int rem = cid & 255;
        int row = rem >> 3, c = rem & 7;
        const __nv_bfloat16* src =
            (half ? gl : gh) + (size_t)(k0 + row) * ldb + bn + c * 8;
        uint32_t dst = sdst + half * 4096 + row * 128 + ((c ^ (row & 7)) << 4);
        CP16(dst, src);
    }
}

__device__ __forceinline__ void gemm_core(float (&acc)[4][4][4],
                                          const __nv_bfloat16* Ah, const __nv_bfloat16* Al,
                                          const __nv_bfloat16* Bh, const __nv_bfloat16* Bl,
                                          int K, int ldb, int bm, int bn, char* smem) {
    const int tid = threadIdx.x;
    const int wid = tid >> 5, lane = tid & 31;
    const int wm = (wid >> 2) * 64, wn = (wid & 3) * 32;
    uint32_t sbase = smem_u32(smem);

    const __nv_bfloat16* ah_g = Ah + (size_t)bm * K;
    const __nv_bfloat16* al_g = Al + (size_t)bm * K;

    const int nt = K >> 5;
    tile_load_A(sbase, ah_g, al_g, K, 0, tid);
    tile_load_B(sbase + 16384, Bh, Bl, ldb, bn, 0, tid);
    CP_COMMIT();
    tile_load_A(sbase + 32768, ah_g, al_g, K, 32, tid);
    tile_load_B(sbase + 32768 + 16384, Bh, Bl, ldb, bn, 32, tid);
    CP_COMMIT();

    const int kr_base = (lane & 7) + ((lane >> 3) & 1) * 8;
    const int nc8 = (lane >> 4);

    int br = 0, bw = 2;
    for (int t = 0; t < nt; t++) {
        if (t + 1 < nt) { CP_WAIT(1); } else { CP_WAIT(0); }
        __syncthreads();
        if (t + 2 < nt) {
            uint32_t nb = sbase + bw * 32768;
            tile_load_A(nb, ah_g, al_g, K, (t + 2) << 5, tid);
            tile_load_B(nb + 16384, Bh, Bl, ldb, bn, (t + 2) << 5, tid);
            CP_COMMIT();
        }

        uint32_t sA = sbase + br * 32768;
        uint32_t sB = sA + 16384;
#pragma unroll
        for (int ks = 0; ks < 2; ks++) {
            uint32_t bhf[2][4], blf[2][4];
#pragma unroll
            for (int np = 0; np < 2; np++) {
                int krow = ks * 16 + kr_base;
                int ncol = wn + np * 16 + nc8 * 8;
                int c = ncol >> 3;
                uint32_t a = sB + krow * 256 + ((c ^ ((krow & 7) << 1)) << 4);
                ldsm4t(bhf[np], a);
                ldsm4t(blf[np], a + 8192);
            }
#pragma unroll
            for (int mp = 0; mp < 2; mp++) {
                uint32_t ahf[2][4], alf[2][4];
#pragma unroll
                for (int f2 = 0; f2 < 2; f2++) {
                    int row = wm + (mp * 2 + f2) * 16 + (lane & 15);
                    int jc = (lane >> 4) + ks * 2;
                    ldsm4(ahf[f2], sA + row * 128 + ((jc ^ (row & 7)) << 4));
                    ldsm4(alf[f2], sA + row * 128 + (((jc + 4) ^ (row & 7)) << 4));
                }
#pragma unroll
                for (int m2 = 0; m2 < 2; m2++)
#pragma unroll
                    for (int nf = 0; nf < 4; nf++) {
                        uint32_t* bhp = &bhf[nf >> 1][(nf & 1) * 2];
                        uint32_t* blp = &blf[nf >> 1][(nf & 1) * 2];
                        float* ac = acc[mp * 2 + m2][nf];
                        mma_bf16(ac, ahf[m2], bhp);
                        mma_bf16(ac, ahf[m2], blp);
                        mma_bf16(ac, alf[m2], bhp);
                    }
            }
        }
        br = (br == 2) ? 0 : br + 1;
        bw = (bw == 2) ? 0 : bw + 1;
    }
}

// 64x64 tile core: 256 thr, warps 4m x 2n, warp tile 16x32
__device__ __forceinline__ void gemm_core_t64(float (&acc)[4][4],
                                              const __nv_bfloat16* Ah, const __nv_bfloat16* Al,
                                              const __nv_bfloat16* Bh, const __nv_bfloat16* Bl,
                                              int K, int ldb, int bm, int bn, char* smem) {
    const int tid = threadIdx.x;
    const int wid = tid >> 5, lane = tid & 31;
    const int wm = (wid >> 1) * 16, wn = (wid & 1) * 32;
    uint32_t sbase = smem_u32(smem);

    const __nv_bfloat16* ah_g = Ah + (size_t)bm * K;
    const __nv_bfloat16* al_g = Al + (size_t)bm * K;

    const int nt = K >> 5;
    tile_load_A64(sbase, ah_g, al_g, K, 0, tid);
    tile_load_B64(sbase + 8192, Bh, Bl, ldb, bn, 0, tid);
    CP_COMMIT();
    tile_load_A64(sbase + 16384, ah_g, al_g, K, 32, tid);
    tile_load_B64(sbase + 16384 + 8192, Bh, Bl, ldb, bn, 32, tid);
    CP_COMMIT();

    const int kr_base = (lane & 7) + ((lane >> 3) & 1) * 8;
    const int nc8 = (lane >> 4);

    int br = 0, bw = 2;
    for (int t = 0; t < nt; t++) {
        if (t + 1 < nt) { CP_WAIT(1); } else { CP_WAIT(0); }
        __syncthreads();
        if (t + 2 < nt) {
            uint32_t nb = sbase + bw * 16384;
            tile_load_A64(nb, ah_g, al_g, K, (t + 2) << 5, tid);
            tile_load_B64(nb + 8192, Bh, Bl, ldb, bn, (t + 2) << 5, tid);
            CP_COMMIT();
        }

        uint32_t sA = sbase + br * 16384;
        uint32_t sB = sA + 8192;
#pragma unroll
        for (int ks = 0; ks < 2; ks++) {
            uint32_t bhf[2][4], blf[2][4];
#pragma unroll
            for (int np = 0; np < 2; np++) {
                int krow = ks * 16 + kr_base;
                int ncol = wn + np * 16 + nc8 * 8;
                int c = ncol >> 3;
                uint32_t a = sB + krow * 128 + ((c ^ (krow & 7)) << 4);
                ldsm4t(bhf[np], a);
                ldsm4t(blf[np], a + 4096);
            }
            uint32_t ahf[4], alf[4];
            {
                int row = wm + (lane & 15);
                int jc = (lane >> 4) + ks * 2;
                ldsm4(ahf, sA + row * 128 + ((jc ^ (row & 7)) << 4));
                ldsm4(alf, sA + row * 128 + (((jc + 4) ^ (row & 7)) << 4));
            }
#pragma unroll
            for (int nf = 0; nf < 4; nf++) {
                uint32_t* bhp = &bhf[nf >> 1][(nf & 1) * 2];
                uint32_t* blp = &blf[nf >> 1][(nf & 1) * 2];
                float* ac = acc[nf];
                mma_bf16(ac, ahf, bhp);
                mma_bf16(ac, ahf, blp);
                mma_bf16(ac, alf, bhp);
            }
        }
        br = (br == 2) ? 0 : br + 1;
        bw = (bw == 2) ? 0 : bw + 1;
    }
}

// fp32 output (+bias, +res), 128-wide N
__global__ __launch_bounds__(256, 2)
void k_gemm_f32(const __nv_bfloat16* __restrict__ Ah, const __nv_bfloat16* __restrict__ Al,
                const __nv_bfloat16* __restrict__ Bh, const __nv_bfloat16* __restrict__ Bl,
                const float* __restrict__ bias, const float* __restrict__ res,
                float* __restrict__ C, int K, int ldb, int ldc) {
    extern __shared__ char smem[];
    const int tid = threadIdx.x, wid = tid >> 5, lane = tid & 31;
    const int bm = blockIdx.y * 128, bn = blockIdx.x * 128;
    const int wm = (wid >> 2) * 64, wn = (wid & 3) * 32;
    float acc[4][4][4] = {};
    gemm_core(acc, Ah, Al, Bh, Bl, K, ldb, bm, bn, smem);
#pragma unroll
    for (int m = 0; m < 4; m++) {
        int r0 = bm + wm + m * 16 + (lane >> 2);
#pragma unroll
        for (int nf = 0; nf < 4; nf++) {
            int col = bn + wn + nf * 8 + ((lane & 3) << 1);
            float v0 = acc[m][nf][0], v1 = acc[m][nf][1];
            float v2 = acc[m][nf][2], v3 = acc[m][nf][3];
            if (bias) {
                float b0 = bias[col], b1 = bias[col + 1];
                v0 += b0; v1 += b1; v2 += b0; v3 += b1;
            }
            if (res) {
                const float* rr0 = res + (size_t)r0 * ldc + col;
                const float* rr1 = res + (size_t)(r0 + 8) * ldc + col;
                v0 += rr0[0]; v1 += rr0[1]; v2 += rr1[0]; v3 += rr1[1];
            }
            *(float2*)(C + (size_t)r0 * ldc + col) = make_float2(v0, v1);
            *(float2*)(C + (size_t)(r0 + 8) * ldc + col) = make_float2(v2, v3);
        }
    }
}

// fp32 output (+bias, +res), 64x64 tile — for Wo / FFN2 (wave fill)
__global__ __launch_bounds__(256, 2)
void k_gemm_f32_t64(const __nv_bfloat16* __restrict__ Ah, const __nv_bfloat16* __restrict__ Al,
                    const __nv_bfloat16* __restrict__ Bh, const __nv_bfloat16* __restrict__ Bl,
                    const float* __restrict__ bias, const float* __restrict__ res,
                    float* __restrict__ C, int K, int ldb, int ldc) {
    extern __shared__ char smem[];
    const int tid = threadIdx.x, wid = tid >> 5, lane = tid & 31;
    const int bm = blockIdx.y * 64, bn = blockIdx.x * 64;
    const int wm = (wid >> 1) * 16, wn = (wid & 1) * 32;
    float acc[4][4] = {};
    gemm_core_t64(acc, Ah, Al, Bh, Bl, K, ldb, bm, bn, smem);
    int r0 = bm + wm + (lane >> 2);
#pragma unroll
    for (int nf = 0; nf < 4; nf++) {
        int col = bn + wn + nf * 8 + ((lane & 3) << 1);
        float v0 = acc[nf][0], v1 = acc[nf][1];
        float v2 = acc[nf][2], v3 = acc[nf][3];
        if (bias) {
            float b0 = bias[col], b1 = bias[col + 1];
            v0 += b0; v1 += b1; v2 += b0; v3 += b1;
        }
        if (res) {
            const float* rr0 = res + (size_t)r0 * ldc + col;
            const float* rr1 = res + (size_t)(r0 + 8) * ldc + col;
            v0 += rr0[0]; v1 += rr0[1]; v2 += rr1[0]; v3 += rr1[1];
        }
        *(float2*)(C + (size_t)r0 * ldc + col) = make_float2(v0, v1);
        *(float2*)(C + (size_t)(r0 + 8) * ldc + col) = make_float2(v2, v3);
    }
}

// bf16 hi/lo output (+bias, relu) — FFN1
__global__ __launch_bounds__(256, 2)
void k_gemm_bf16(const __nv_bfloat16* __restrict__ Ah, const __nv_bfloat16* __restrict__ Al,
                 const __nv_bfloat16* __restrict__ Bh, const __nv_bfloat16* __restrict__ Bl,
                 const float* __restrict__ bias,
                 __nv_bfloat16* __restrict__ Ch, __nv_bfloat16* __restrict__ Cl,
                 int K, int ldb, int ldc, int relu) {
    extern __shared__ char smem[];
    const int tid = threadIdx.x, wid = tid >> 5, lane = tid & 31;
    const int bm = blockIdx.y * 128, bn = blockIdx.x * 128;
    const int wm = (wid >> 2) * 64, wn = (wid & 3) * 32;
    float acc[4][4][4] = {};
    gemm_core(acc, Ah, Al, Bh, Bl, K, ldb, bm, bn, smem);
#pragma unroll
    for (int m = 0; m < 4; m++) {
        int r0 = bm + wm + m * 16 + (lane >> 2);
#pragma unroll
        for (int nf = 0; nf < 4; nf++) {
            int col = bn + wn + nf * 8 + ((lane & 3) << 1);
            float v[4] = {acc[m][nf][0], acc[m][nf][1], acc[m][nf][2], acc[m][nf][3]};
            if (bias) {
                float b0 = bias[col], b1 = bias[col + 1];
                v[0] += b0; v[1] += b1; v[2] += b0; v[3] += b1;
            }
            if (relu) {
#pragma unroll
                for (int e = 0; e < 4; e++) v[e] = fmaxf(v[e], 0.f);
            }
            float h0 = __bfloat162float(__float2bfloat16(v[0]));
            float h1 = __bfloat162float(__float2bfloat16(v[1]));
            float h2 = __bfloat162float(__float2bfloat16(v[2]));
            float h3 = __bfloat162float(__float2bfloat16(v[3]));
            *(uint32_t*)(Ch + (size_t)r0 * ldc + col) = pack2bf(v[0], v[1]);
            *(uint32_t*)(Ch + (size_t)(r0 + 8) * ldc + col) = pack2bf(v[2], v[3]);
            *(uint32_t*)(Cl + (size_t)r0 * ldc + col) = pack2bf(v[0] - h0, v[1] - h1);
            *(uint32_t*)(Cl + (size_t)(r0 + 8) * ldc + col) = pack2bf(v[2] - h2, v[3] - h3);
        }
    }
}

// QKV gemm: B = [3][D,D]; cols [0,D)->q, [D,2D)->k, [2D,3D)->vT via smem
__global__ __launch_bounds__(256, 2)
void k_qkv_gemm(const __nv_bfloat16* __restrict__ Ah, const __nv_bfloat16* __restrict__ Al,
                const __nv_bfloat16* __restrict__ Bh, const __nv_bfloat16* __restrict__ Bl,
                __nv_bfloat16* __restrict__ qh, __nv_bfloat16* __restrict__ ql,
                __nv_bfloat16* __restrict__ kh, __nv_bfloat16* __restrict__ kl,
                __nv_bfloat16* __restrict__ vth, __nv_bfloat16* __restrict__ vtl) {
    extern __shared__ char smem[];
    const int tid = threadIdx.x, wid = tid >> 5, lane = tid & 31;
    const int bm = blockIdx.y * 128, bn = blockIdx.x * 128;
    const int wm = (wid >> 2) * 64, wn = (wid & 3) * 32;
    const int widx = bn >> 10;
    const int bn_eff = bn & 1023;
    float acc[4][4][4] = {};
    gemm_core(acc, Ah, Al, Bh + (size_t)widx * D * D, Bl + (size_t)widx * D * D,
              D, D, bm, bn_eff, smem);

    if (widx < 2) {
        __nv_bfloat16* oh = (widx == 0) ? qh : kh;
        __nv_bfloat16* ol = (widx == 0) ? ql : kl;
#pragma unroll
        for (int m = 0; m < 4; m++) {
            int r0 = bm + wm + m * 16 + (lane >> 2);
#pragma unroll
            for (int nf = 0; nf < 4; nf++) {
                int col = bn_eff + wn + nf * 8 + ((lane & 3) << 1);
                float v0 = acc[m][nf][0], v1 = acc[m][nf][1];
                float v2 = acc[m][nf][2], v3 = acc[m][nf][3];
                float h0 = __bfloat162float(__float2bfloat16(v0));
                float h1 = __bfloat162float(__float2bfloat16(v1));
                float h2 = __bfloat162float(__float2bfloat16(v2));
                float h3 = __bfloat162float(__float2bfloat16(v3));
                *(uint32_t*)(oh + (size_t)r0 * D + col) = pack2bf(v0, v1);
                *(uint32_t*)(oh + (size_t)(r0 + 8) * D + col) = pack2bf(v2, v3);
                *(uint32_t*)(ol + (size_t)r0 * D + col) = pack2bf(v0 - h0, v1 - h1);
                *(uint32_t*)(ol + (size_t)(r0 + 8) * D + col) = pack2bf(v2 - h2, v3 - h3);
            }
        }
    } else {
        // smem reuse after mainloop: drain all warps first
        __syncthreads();
        __nv_bfloat16* sv = (__nv_bfloat16*)smem;
#pragma unroll
        for (int part = 0; part < 2; part++) {
#pragma unroll
            for (int m = 0; m < 4; m++) {
#pragma unroll
                for (int nf = 0; nf < 4; nf++) {
#pragma unroll
                    for (int e = 0; e < 4; e++) {
                        int rl = wm + m * 16 + (lane >> 2) + ((e >> 1) ? 8 : 0);
                        int cl = wn + nf * 8 + ((lane & 3) << 1) + (e & 1);
                        float v = acc[m][nf][e];
                        float hv = __bfloat162float(__float2bfloat16(v));
                        sv[cl * 136 + rl] = __float2bfloat16(part ? (v - hv) : v);
                    }
                }
            }
            __syncthreads();
            int col = tid >> 1, half = tid & 1;
            const uint4* src = (const uint4*)(smem + col * 272 + half * 128);
            __nv_bfloat16* dst = (part ? vtl : vth) +
                                 (size_t)(bn_eff + col) * S + bm + half * 64;
#pragma unroll
            for (int j = 0; j < 8; j++) ((uint4*)dst)[j] = src[j];
            __syncthreads();
        }
    }
}

// ---------------------------------------------------------------------------
// flash attention: CTA = (qblock 64, head), 128 thr
// ---------------------------------------------------------------------------
#define FA_SMEM (16384 + 2 * 32768)

__device__ __forceinline__ void fa_load(uint32_t sdst, const __nv_bfloat16* g,
                                        int ld, int tid) {
#pragma unroll
    for (int i = 0; i < 4; i++) {
        int cid = i * 128 + tid;
        int row = cid >> 3, c = cid & 7;
        CP16(sdst + row * 128 + ((c ^ (row & 7)) << 4), g + (size_t)row * ld + c * 8);
    }
}

__global__ __launch_bounds__(128)
void k_flash(const __nv_bfloat16* __restrict__ qh, const __nv_bfloat16* __restrict__ ql,
             const __nv_bfloat16* __restrict__ kh, const __nv_bfloat16* __restrict__ kl,
             const __nv_bfloat16* __restrict__ vth, const __nv_bfloat16* __restrict__ vtl,
             __nv_bfloat16* __restrict__ oh, __nv_bfloat16* __restrict__ ol) {
    extern __shared__ char smem[];
    uint32_t sb = smem_u32(smem);
    const int tid = threadIdx.x, w = tid >> 5, lane = tid & 31;
    const int qb = gridDim.x - 1 - blockIdx.x;
    const int hh = blockIdx.y;

    fa_load(sb,        qh + (size_t)(qb * 64) * D + hh * 64, D, tid);
    fa_load(sb + 8192, ql + (size_t)(qb * 64) * D + hh * 64, D, tid);
    {
        uint32_t st = sb + 16384;
        fa_load(st,         kh + hh * 64, D, tid);
        fa_load(st + 8192,  kl + hh * 64, D, tid);
        fa_load(st + 16384, vth + (size_t)(hh * 64) * S, S, tid);
        fa_load(st + 24576, vtl + (size_t)(hh * 64) * S, S, tid);
    }
    CP_COMMIT();

    uint32_t qhf[4][4], qlf[4][4];
    float o_acc[8][4] = {};
    float m0 = -1e30f, m1 = -1e30f, l0 = 0.f, l1 = 0.f;

    for (int kb = 0; kb <= qb; kb++) {
        if (kb + 1 <= qb) {
            uint32_t st = sb + 16384 + ((kb + 1) & 1) * 32768;
            fa_load(st,         kh + (size_t)((kb + 1) * 64) * D + hh * 64, D, tid);
            fa_load(st + 8192,  kl + (size_t)((kb + 1) * 64) * D + hh * 64, D, tid);
            fa_load(st + 16384, vth + (size_t)(hh * 64) * S + (kb + 1) * 64, S, tid);
            fa_load(st + 24576, vtl + (size_t)(hh * 64) * S + (kb + 1) * 64, S, tid);
            CP_COMMIT();
            CP_WAIT(1);
        } else {
            CP_WAIT(0);
        }
        __syncthreads();

        if (kb == 0) {
#pragma unroll
            for (int f = 0; f < 4; f++) {
                int row = w * 16 + (lane & 15);
                int jc = (lane >> 4) + f * 2;
                ldsm4(qhf[f], sb + row * 128 + ((jc ^ (row & 7)) << 4));
                ldsm4(qlf[f], sb + 8192 + row * 128 + ((jc ^ (row & 7)) << 4));
            }
        }

        uint32_t st = sb + 16384 + (kb & 1) * 32768;
        float s_acc[8][4] = {};
#pragma unroll
        for (int ks = 0; ks < 4; ks++) {
            uint32_t bh4[4][4], bl4[4][4];
#pragma unroll
            for (int np = 0; np < 4; np++) {
                int row = np * 16 + ((lane >> 4) << 3) + (lane & 7);
                int jc = ((lane >> 3) & 1) + ks * 2;
                ldsm4(bh4[np], st + row * 128 + ((jc ^ (row & 7)) << 4));
                ldsm4(bl4[np], st + 8192 + row * 128 + ((jc ^ (row & 7)) << 4));
            }
#pragma unroll
            for (int nf = 0; nf < 8; nf++) {
                uint32_t* bh = &bh4[nf >> 1][(nf & 1) * 2];
                uint32_t* bl = &bl4[nf >> 1][(nf & 1) * 2];
                mma_bf16(s_acc[nf], qhf[ks], bh);
                mma_bf16(s_acc[nf], qhf[ks], bl);
                mma_bf16(s_acc[nf], qlf[ks], bh);
            }
        }
        int r_lo = qb * 64 + w * 16 + (lane >> 2);
#pragma unroll
        for (int nf = 0; nf < 8; nf++)
#pragma unroll
            for (int e = 0; e < 4; e++) {
                float v = s_acc[nf][e] * 0.125f;
                if (kb == qb) {
                    int key = kb * 64 + nf * 8 + ((lane & 3) << 1) + (e & 1);
                    int qr = r_lo + ((e >> 1) ? 8 : 0);
                    if (key > qr) v = -1e30f;
                }
                s_acc[nf][e] = v;
            }
        float mx0 = -1e30f, mx1 = -1e30f;
#pragma unroll
        for (int nf = 0; nf < 8; nf++) {
            mx0 = fmaxf(mx0, fmaxf(s_acc[nf][0], s_acc[nf][1]));
            mx1 = fmaxf(mx1, fmaxf(s_acc[nf][2], s_acc[nf][3]));
        }
        mx0 = fmaxf(mx0, __shfl_xor_sync(0xffffffffu, mx0, 1));
        mx0 = fmaxf(mx0, __shfl_xor_sync(0xffffffffu, mx0, 2));
        mx1 = fmaxf(mx1, __shfl_xor_sync(0xffffffffu, mx1, 1));
        mx1 = fmaxf(mx1, __shfl_xor_sync(0xffffffffu, mx1, 2));
        float mn0 = fmaxf(m0, mx0), mn1 = fmaxf(m1, mx1);
        float a0 = __expf(m0 - mn0), a1 = __expf(m1 - mn1);
        float sum0 = 0.f, sum1 = 0.f;
#pragma unroll
        for (int nf = 0; nf < 8; nf++) {
            s_acc[nf][0] = __expf(s_acc[nf][0] - mn0);
            s_acc[nf][1] = __expf(s_acc[nf][1] - mn0);
            s_acc[nf][2] = __expf(s_acc[nf][2] - mn1);
            s_acc[nf][3] = __expf(s_acc[nf][3] - mn1);
            sum0 += s_acc[nf][0] + s_acc[nf][1];
            sum1 += s_acc[nf][2] + s_acc[nf][3];
        }
        sum0 += __shfl_xor_sync(0xffffffffu, sum0, 1);
        sum0 += __shfl_xor_sync(0xffffffffu, sum0, 2);
        sum1 += __shfl_xor_sync(0xffffffffu, sum1, 1);
        sum1 += __shfl_xor_sync(0xffffffffu, sum1, 2);
        l0 = l0 * a0 + sum0;
        l1 = l1 * a1 + sum1;
        m0 = mn0; m1 = mn1;
#pragma unroll
        for (int nf = 0; nf < 8; nf++) {
            o_acc[nf][0] *= a0; o_acc[nf][1] *= a0;
            o_acc[nf][2] *= a1; o_acc[nf][3] *= a1;
        }
        uint32_t pph[4][4], ppl[4][4];
#pragma unroll
        for (int g = 0; g < 4; g++) {
            float c0 = s_acc[2 * g][0], c1 = s_acc[2 * g][1];
            float c2 = s_acc[2 * g][2], c3 = s_acc[2 * g][3];
            float d0 = s_acc[2 * g + 1][0], d1 = s_acc[2 * g + 1][1];
            float d2 = s_acc[2 * g + 1][2], d3 = s_acc[2 * g + 1][3];
            pph[g][0] = pack2bf(c0, c1); pph[g][1] = pack2bf(c2, c3);
            pph[g][2] = pack2bf(d0, d1); pph[g][3] = pack2bf(d2, d3);
            ppl[g][0] = pack2bf(c0 - __bfloat162float(__float2bfloat16(c0)),
                                c1 - __bfloat162float(__float2bfloat16(c1)));
            ppl[g][1] = pack2bf(c2 - __bfloat162float(__float2bfloat16(c2)),
                                c3 - __bfloat162float(__float2bfloat16(c3)));
            ppl[g][2] = pack2bf(d0 - __bfloat162float(__float2bfloat16(d0)),
                                d1 - __bfloat162float(__float2bfloat16(d1)));
            ppl[g][3] = pack2bf(d2 - __bfloat162float(__float2bfloat16(d2)),
                                d3 - __bfloat162float(__float2bfloat16(d3)));
        }
        uint32_t sv = st + 16384;
#pragma unroll
        for (int ks = 0; ks < 4; ks++) {
            uint32_t bh4[4][4], bl4[4][4];
#pragma unroll
            for (int np = 0; np < 4; np++) {
                int row = np * 16 + ((lane >> 4) << 3) + (lane & 7);
                int jc = ((lane >> 3) & 1) + ks * 2;
                ldsm4(bh4[np], sv + row * 128 + ((jc ^ (row & 7)) << 4));
                ldsm4(bl4[np], sv + 8192 + row * 128 + ((jc ^ (row & 7)) << 4));
            }
#pragma unroll
            for (int nf = 0; nf < 8; nf++) {
                uint32_t* bh = &bh4[nf >> 1][(nf & 1) * 2];
                uint32_t* bl = &bl4[nf >> 1][(nf & 1) * 2];
                mma_bf16(o_acc[nf], pph[ks], bh);
                mma_bf16(o_acc[nf], ppl[ks], bh);
                mma_bf16(o_acc[nf], pph[ks], bl);
            }
        }
        __syncthreads();
    }

    float inv0 = 1.f / l0, inv1 = 1.f / l1;
    int row0 = qb * 64 + w * 16 + (lane >> 2);
#pragma unroll
    for (int nf = 0; nf < 8; nf++) {
        int col = hh * 64 + nf * 8 + ((lane & 3) << 1);
        float v0 = o_acc[nf][0] * inv0, v1 = o_acc[nf][1] * inv0;
        float v2 = o_acc[nf][2] * inv1, v3 = o_acc[nf][3] * inv1;
        float h0 = __bfloat162float(__float2bfloat16(v0));
        float h1 = __bfloat162float(__float2bfloat16(v1));
        float h2 = __bfloat162float(__float2bfloat16(v2));
        float h3 = __bfloat162float(__float2bfloat16(v3));
        *(uint32_t*)(oh + (size_t)row0 * D + col) = pack2bf(v0, v1);
        *(uint32_t*)(oh + (size_t)(row0 + 8) * D + col) = pack2bf(v2, v3);
        *(uint32_t*)(ol + (size_t)row0 * D + col) = pack2bf(v0 - h0, v1 - h1);
        *(uint32_t*)(ol + (size_t)(row0 + 8) * D + col) = pack2bf(v2 - h2, v3 - h3);
    }
}

// ---------------------------------------------------------------------------
// flat weight split
// ---------------------------------------------------------------------------
__global__ __launch_bounds__(256) void k_split_flat(const float* __restrict__ W,
                                                    __nv_bfloat16* __restrict__ th,
                                                    __nv_bfloat16* __restrict__ tl) {
    size_t gid = (size_t)blockIdx.x * 256 + threadIdx.x;
    float4 a = ((const float4*)W)[2 * gid];
    float4 b = ((const float4*)W)[2 * gid + 1];
    uint4 uh, ul;
    uh.x = pack2bf(a.x, a.y); uh.y = pack2bf(a.z, a.w);
    uh.z = pack2bf(b.x, b.y); uh.w = pack2bf(b.z, b.w);
    ul.x = pack2bf(a.x - __bfloat162float(__float2bfloat16(a.x)),
                   a.y - __bfloat162float(__float2bfloat16(a.y)));
    ul.y = pack2bf(a.z - __bfloat162float(__float2bfloat16(a.z)),
                   a.w - __bfloat162float(__float2bfloat16(a.w)));
    ul.z = pack2bf(b.x - __bfloat162float(__float2bfloat16(b.x)),
                   b.y - __bfloat162float(__float2bfloat16(b.y)));
    ul.w = pack2bf(b.z - __bfloat162float(__float2bfloat16(b.z)),
                   b.w - __bfloat162float(__float2bfloat16(b.w)));
    ((uint4*)th)[gid] = uh;
    ((uint4*)tl)[gid] = ul;
}

// ---------------------------------------------------------------------------
// embedding + positional encoding
// ---------------------------------------------------------------------------
__global__ __launch_bounds__(256) void k_embed(const int* __restrict__ x,
                                               const float* __restrict__ emb,
                                               float* __restrict__ h) {
    int s = blockIdx.y;
    int d = blockIdx.x * 256 + threadIdx.x;
    int tok = x[s];
    float e = emb[(size_t)tok * D + d];
    int i2 = d & ~1;
    float freq = expf((float)i2 * (-9.210340371976184f / (float)D));
    float ang = (float)s * freq;
    float pe = (d & 1) ? cosf(ang) : sinf(ang);
    h[(size_t)s * D + d] = e + pe;
}

// ---------------------------------------------------------------------------
// layernorm -> bf16 hi/lo
// ---------------------------------------------------------------------------
__global__ __launch_bounds__(256) void k_ln(const float* __restrict__ in,
                                            __nv_bfloat16* __restrict__ oh,
                                            __nv_bfloat16* __restrict__ ol,
                                            const float* __restrict__ w,
                                            const float* __restrict__ b) {
    int row = blockIdx.x;
    const float* xr = in + (size_t)row * D;
    int t = threadIdx.x;
    __shared__ float sh1[256];
    __shared__ float sh2[256];
    float s1 = 0.f, s2 = 0.f;
    for (int d = t; d < D; d += 256) {
        float v = xr[d];
        s1 += v; s2 += v * v;
    }
    sh1[t] = s1; sh2[t] = s2;
    __syncthreads();
    for (int o = 128; o > 0; o >>= 1) {
        if (t < o) { sh1[t] += sh1[t + o]; sh2[t] += sh2[t + o]; }
        __syncthreads();
    }
    float mean = sh1[0] * (1.0f / D);
    float var = sh2[0] * (1.0f / D) - mean * mean;
    float rstd = rsqrtf(var + EPSF);
    for (int d = t; d < D; d += 256) {
        float v = (xr[d] - mean) * rstd * w[d] + b[d];
        __nv_bfloat16 hv = __float2bfloat16(v);
        oh[(size_t)row * D + d] = hv;
        ol[(size_t)row * D + d] = __float2bfloat16(v - __bfloat162float(hv));
    }
}

// ---------------------------------------------------------------------------
// launch orchestration
// ---------------------------------------------------------------------------
extern "C" void kernel_launch(void* const* d_in, const int* in_sizes, int n_in,
                              void* d_out, int out_size) {
    (void)in_sizes; (void)n_in; (void)out_size;
    const int*   x      = (const int*)d_in[0];
    const float* emb    = (const float*)d_in[1];
    const float* Wq     = (const float*)d_in[2];
    const float* Wk     = (const float*)d_in[3];
    const float* Wv     = (const float*)d_in[4];
    const float* Wo     = (const float*)d_in[5];
    const float* bo     = (const float*)d_in[6];
    const float* ln1_w  = (const float*)d_in[7];
    const float* ln1_b  = (const float*)d_in[8];
    const float* W1     = (const float*)d_in[9];
    const float* b1     = (const float*)d_in[10];
    const float* W2     = (const float*)d_in[11];
    const float* b2     = (const float*)d_in[12];
    const float* ln2_w  = (const float*)d_in[13];
    const float* ln2_b  = (const float*)d_in[14];
    const float* fn_w   = (const float*)d_in[15];
    const float* fn_b   = (const float*)d_in[16];
    const float* lmhead = (const float*)d_in[17];
    float* out = (float*)d_out;

    static float* ph = nullptr;
    static __nv_bfloat16 *acth, *actl, *ffh, *ffl, *qh, *ql, *kh, *kl, *vth, *vtl,
                         *qkvh, *qkvl, *woh, *wol, *w1h, *w1l, *w2h, *w2l, *lmh, *lml;
    static cudaStream_t s1, s2;
    static cudaEvent_t evFork, evW[L], evLM, evDone;
    if (!ph) {
        cudaGetSymbolAddress((void**)&ph,   g_h);
        cudaGetSymbolAddress((void**)&acth, g_act_h);
        cudaGetSymbolAddress((void**)&actl, g_act_l);
        cudaGetSymbolAddress((void**)&ffh,  g_ff_h);
        cudaGetSymbolAddress((void**)&ffl,  g_ff_l);
        cudaGetSymbolAddress((void**)&qh,   g_qh);
        cudaGetSymbolAddress((void**)&ql,   g_ql);
        cudaGetSymbolAddress((void**)&kh,   g_kh);
        cudaGetSymbolAddress((void**)&kl,   g_kl);
        cudaGetSymbolAddress((void**)&vth,  g_vth);
        cudaGetSymbolAddress((void**)&vtl,  g_vtl);
        cudaGetSymbolAddress((void**)&qkvh, g_qkv_h);
        cudaGetSymbolAddress((void**)&qkvl, g_qkv_l);
        cudaGetSymbolAddress((void**)&woh,  g_wo_h);
        cudaGetSymbolAddress((void**)&wol,  g_wo_l);
        cudaGetSymbolAddress((void**)&w1h,  g_w1_h);
        cudaGetSymbolAddress((void**)&w1l,  g_w1_l);
        cudaGetSymbolAddress((void**)&w2h,  g_w2_h);
        cudaGetSymbolAddress((void**)&w2l,  g_w2_l);
        cudaGetSymbolAddress((void**)&lmh,  g_lm_h);
        cudaGetSymbolAddress((void**)&lml,  g_lm_l);
        cudaFuncSetAttribute(k_gemm_f32,     cudaFuncAttributeMaxDynamicSharedMemorySize, MG_SMEM);
        cudaFuncSetAttribute(k_gemm_f32_t64, cudaFuncAttributeMaxDynamicSharedMemorySize, T64_SMEM);
        cudaFuncSetAttribute(k_gemm_bf16,    cudaFuncAttributeMaxDynamicSharedMemorySize, MG_SMEM);
        cudaFuncSetAttribute(k_qkv_gemm,     cudaFuncAttributeMaxDynamicSharedMemorySize, MG_SMEM);
        cudaFuncSetAttribute(k_flash,        cudaFuncAttributeMaxDynamicSharedMemorySize, FA_SMEM);
        cudaStreamCreateWithFlags(&s1, cudaStreamNonBlocking);
        cudaStreamCreateWithFlags(&s2, cudaStreamNonBlocking);
        cudaEventCreateWithFlags(&evFork, cudaEventDisableTiming);
        for (int l = 0; l < L; l++) cudaEventCreateWithFlags(&evW[l], cudaEventDisableTiming);
        cudaEventCreateWithFlags(&evLM, cudaEventDisableTiming);
        cudaEventCreateWithFlags(&evDone, cudaEventDisableTiming);
    }

    // fork
    cudaEventRecord(evFork, 0);
    cudaStreamWaitEvent(s1, evFork, 0);
    cudaStreamWaitEvent(s2, evFork, 0);

    // s2: weight prep
    const int gDD = D * D / 2048;
    const int gDF = D * FF / 2048;
    for (int l = 0; l < L; l++) {
        size_t wo = (size_t)l * D * D;
        size_t qo = (size_t)l * 3 * D * D;
        k_split_flat<<<gDD, 256, 0, s2>>>(Wq + wo, qkvh + qo,             qkvl + qo);
        k_split_flat<<<gDD, 256, 0, s2>>>(Wk + wo, qkvh + qo + D * D,     qkvl + qo + D * D);
        k_split_flat<<<gDD, 256, 0, s2>>>(Wv + wo, qkvh + qo + 2 * D * D, qkvl + qo + 2 * D * D);
        k_split_flat<<<gDD, 256, 0, s2>>>(Wo + wo, woh + wo, wol + wo);
        k_split_flat<<<gDF, 256, 0, s2>>>(W1 + (size_t)l * D * FF,
                                          w1h + (size_t)l * D * FF, w1l + (size_t)l * D * FF);
        k_split_flat<<<gDF, 256, 0, s2>>>(W2 + (size_t)l * FF * D,
                                          w2h + (size_t)l * FF * D, w2l + (size_t)l * FF * D);
        cudaEventRecord(evW[l], s2);
    }
    k_split_flat<<<(int)((size_t)D * V / 2048), 256, 0, s2>>>(lmhead, lmh, lml);
    cudaEventRecord(evLM, s2);

    // s1: compute
    k_embed<<<dim3(D / 256, S), 256, 0, s1>>>(x, emb, ph);

    for (int l = 0; l < L; l++) {
        size_t wo = (size_t)l * D * D;
        size_t qo = (size_t)l * 3 * D * D;
        cudaStreamWaitEvent(s1, evW[l], 0);
        // --- attention ---
        k_ln<<<S, 256, 0, s1>>>(ph, acth, actl, ln1_w + (size_t)l * D, ln1_b + (size_t)l * D);
        k_qkv_gemm<<<dim3(3 * D / 128, S / 128), 256, MG_SMEM, s1>>>(
            acth, actl, qkvh + qo, qkvl + qo, qh, ql, kh, kl, vth, vtl);
        k_flash<<<dim3(S / 64, H), 128, FA_SMEM, s1>>>(qh, ql, kh, kl, vth, vtl, acth, actl);
        k_gemm_f32_t64<<<dim3(D / 64, S / 64), 256, T64_SMEM, s1>>>(
            acth, actl, woh + wo, wol + wo, bo + (size_t)l * D, ph, ph, D, D, D);
        // --- FFN ---
        k_ln<<<S, 256, 0, s1>>>(ph, acth, actl, ln2_w + (size_t)l * D, ln2_b + (size_t)l * D);
        k_gemm_bf16<<<dim3(FF / 128, S / 128), 256, MG_SMEM, s1>>>(
            acth, actl, w1h + (size_t)l * D * FF, w1l + (size_t)l * D * FF,
            b1 + (size_t)l * FF, ffh, ffl, D, FF, FF, 1);
        k_gemm_f32_t64<<<dim3(D / 64, S / 64), 256, T64_SMEM, s1>>>(
            ffh, ffl, w2h + (size_t)l * FF * D, w2l + (size_t)l * FF * D,
            b2 + (size_t)l * D, ph, ph, FF, D, D);
    }

    // final LN + LM head
    cudaStreamWaitEvent(s1, evLM, 0);
    k_ln<<<S, 256, 0, s1>>>(ph, acth, actl, fn_w, fn_b);
    k_gemm_f32<<<dim3(V / 128, S / 128), 256, MG_SMEM, s1>>>(
        acth, actl, lmh, lml, nullptr, nullptr, out, D, V, V);

    // join
    cudaEventRecord(evDone, s1);
    cudaStreamWaitEvent(0, evDone, 0);
}